// round 6
// baseline (speedup 1.0000x reference)
#include <cuda_runtime.h>
#include <cuda_bf16.h>
#include <math.h>
#include <stdint.h>

// ===========================================================================
// mma.sync m16n8k16 row.col bf16*bf16 -> f32  (compute_80+, OK on sm_103)
// ===========================================================================
__device__ __forceinline__ void mma_bf16(float* c, const uint32_t* a, const uint32_t* b)
{
    asm volatile(
        "mma.sync.aligned.m16n8k16.row.col.f32.bf16.bf16.f32 "
        "{%0,%1,%2,%3}, {%4,%5,%6,%7}, {%8,%9}, {%0,%1,%2,%3};"
        : "+f"(c[0]), "+f"(c[1]), "+f"(c[2]), "+f"(c[3])
        : "r"(a[0]), "r"(a[1]), "r"(a[2]), "r"(a[3]), "r"(b[0]), "r"(b[1]));
}
// ldmatrix x4: 32 row addresses (one per lane), 4 regs out (compute_75+)
__device__ __forceinline__ void ldsm_x4(uint32_t* r, uint32_t addr)
{
    asm volatile(
        "ldmatrix.sync.aligned.m8n8.x4.shared.b16 {%0,%1,%2,%3}, [%4];"
        : "=r"(r[0]), "=r"(r[1]), "=r"(r[2]), "=r"(r[3]) : "r"(addr));
}

// ===========================================================================
// Scratch buffers
// ===========================================================================
__device__ float g_bwt [(size_t)4*512*128*128];
__device__ float g_r1  [(size_t)4*64*128*128];
__device__ float g_r2  [(size_t)4*512*128*128];
__device__ float g_pool[(size_t)4*2*128*128];
__device__ float g_sal [(size_t)4*128*128];
__device__ float g_m   [4*512];
__device__ float g_cal [4*512];
__device__ float g_wave[(size_t)4*64*256*256];

// ===========================================================================
// K1: BWT  x(4,64,256,256) -> (4,512,128,128)
// ===========================================================================
__global__ void bwt_kernel(const float* __restrict__ x, float* __restrict__ o)
{
    int idx = blockIdx.x * 256 + threadIdx.x;
    int j = idx & 127;
    int i = (idx >> 7) & 127;
    int c = (idx >> 14) & 63;
    int b = idx >> 20;
    const float* xp = x + ((size_t)(b*64 + c)*256 + 2*i)*256 + 2*j;
    float2 r0 = *(const float2*)xp;
    float2 r1 = *(const float2*)(xp + 256);
    float x1 = r0.x*0.5f, x3 = r0.y*0.5f, x2 = r1.x*0.5f, x4 = r1.y*0.5f;
    size_t ob = ((size_t)(b*512 + c) << 14) + (i << 7) + j;
    const size_t gs = (size_t)64 << 14;
    o[ob + 0*gs] =  x1 + x2 + x3 + x4;
    o[ob + 1*gs] = -x1 - x2 + x3 + x4;
    o[ob + 2*gs] = -x1 + x2 - x3 + x4;
    o[ob + 3*gs] =  x1 - x2 - x3 + x4;
    o[ob + 4*gs] =  x1 + x2 - x3 - x4;
    o[ob + 5*gs] = -x1 + x2 + x3 - x4;
    o[ob + 6*gs] =  x1 - x2 + x3 - x4;
    o[ob + 7*gs] = -x1 - x2 - x3 - x4;
}

// ===========================================================================
// Implicit-GEMM conv via mma.sync + ldmatrix. bf16 3-term split.
// CTA: 256 threads (8 warps), tile 16x16 pixels x 64 couts.
// Warp tile m32 x n64 (2 m-frags x 8 n-frags). K: 16 ci/chunk x KS*KS taps.
// Smem rows = 32B (16 ci bf16), XOR-swizzled 16B units for conflict-free LDSM.
//   D = Ahi*Bhi + Ahi*Blo + Alo*Bhi  (f32 accumulate)
// ===========================================================================
template<int CIN, int COUT, int H, int KS, bool RELU, bool ADD_OUT, bool SALCAL>
__global__ __launch_bounds__(256)
void mmaconv_kernel(const float* __restrict__ in, const float* __restrict__ w,
                    const float* __restrict__ sal, const float* __restrict__ cal,
                    float* out)
{
    constexpr int KS2 = KS*KS;
    constexpr int PAD = KS/2;
    constexpr int HC  = 16 + KS - 1;
    constexpr int HEL = HC*HC;
    constexpr int ASZ = HEL*32;       // bytes per A (hi or lo) buffer
    constexpr int WSZ = KS2*64*32;    // bytes per W (hi or lo) buffer

    extern __shared__ __align__(16) char smem[];
    unsigned short* Ahi = (unsigned short*)(smem);
    unsigned short* Alo = (unsigned short*)(smem + ASZ);
    unsigned short* Whi = (unsigned short*)(smem + 2*ASZ);
    unsigned short* Wlo = (unsigned short*)(smem + 2*ASZ + WSZ);

    const uint32_t aHiBase = (uint32_t)__cvta_generic_to_shared(Ahi);
    const uint32_t wHiBase = aHiBase + 2*ASZ;

    const int t    = threadIdx.x;
    const int lane = t & 31, wid = t >> 5;
    const int g    = lane >> 2;          // fragment row group (0..7)
    const int c0   = (lane & 3) * 2;     // fragment col pair base
    const int bx0  = blockIdx.x * 16;
    const int by0  = blockIdx.y * 16;
    const int z    = blockIdx.z;
    const int coT  = z % (COUT/64);
    const int b    = z / (COUT/64);

    // LDSM lane geometry: tile = lane>>3 (0..3), row-in-tile = lane&7
    const int ltile = lane >> 3, lrow = lane & 7;
    const int lt_lo = ltile & 1;         // 0: rows 0-7, 1: rows 8-15
    const int lt_h  = ltile >> 1;        // k-half (ci 0-7 vs 8-15)

    // precompute B smem offsets (per nf-pair), tap-independent part
    uint32_t boff[4];
    #pragma unroll
    for (int nfp = 0; nfp < 4; ++nfp) {
        int co_row = nfp*16 + lt_lo*8 + lrow;
        boff[nfp] = (uint32_t)(co_row*32 + ((lt_h ^ ((co_row>>2)&1)) << 4));
    }

    float acc[2][8][4];
    #pragma unroll
    for (int mf = 0; mf < 2; ++mf)
        #pragma unroll
        for (int nf = 0; nf < 8; ++nf)
            #pragma unroll
            for (int q = 0; q < 4; ++q) acc[mf][nf][q] = 0.f;

    #pragma unroll 1
    for (int cc = 0; cc < CIN/16; ++cc) {
        const int cb = cc * 16;

        // ---- stage input halo (hi/lo split), coalesced over pixels ----
        for (int idx = t; idx < 16*HEL; idx += 256) {
            int ci  = idx / HEL;
            int pix = idx - ci*HEL;
            int py  = pix / HC;
            int px  = pix - py*HC;
            int gy  = by0 + py - PAD;
            int gx  = bx0 + px - PAD;
            float v = 0.f;
            if (gy >= 0 && gy < H && gx >= 0 && gx < H)
                v = in[((size_t)(b*CIN + cb + ci)*H + gy)*H + gx];
            __nv_bfloat16 h = __float2bfloat16_rn(v);
            __nv_bfloat16 l = __float2bfloat16_rn(v - __bfloat162float(h));
            int u = pix*16 + (((ci>>3) ^ ((pix>>2)&1)) << 3) + (ci & 7);
            Ahi[u] = __bfloat16_as_ushort(h);
            Alo[u] = __bfloat16_as_ushort(l);
        }
        // ---- stage weights (hi/lo, optional cal fold) ----
        for (int idx = t; idx < 64*16*KS2; idx += 256) {
            int co  = idx / (16*KS2);
            int r   = idx - co*(16*KS2);
            int ci  = r / KS2;
            int tap = r - ci*KS2;
            float v = w[((size_t)(coT*64 + co)*CIN + cb + ci)*KS2 + tap];
            if (SALCAL) v *= __ldg(&cal[b*CIN + cb + ci]);
            __nv_bfloat16 h = __float2bfloat16_rn(v);
            __nv_bfloat16 l = __float2bfloat16_rn(v - __bfloat162float(h));
            int u = tap*1024 + co*16 + (((ci>>3) ^ ((co>>2)&1)) << 3) + (ci & 7);
            Whi[u] = __bfloat16_as_ushort(h);
            Wlo[u] = __bfloat16_as_ushort(l);
        }
        __syncthreads();

        #pragma unroll
        for (int tap = 0; tap < KS2; ++tap) {
            const int dy = tap / KS, dx = tap - dy*KS;

            // ---- B fragments: 4 LDSM.x4 hi + 4 lo -> 8 nf ----
            uint32_t bh[8][2], bl[8][2];
            #pragma unroll
            for (int nfp = 0; nfp < 4; ++nfp) {
                uint32_t ad = wHiBase + (uint32_t)(tap*2048) + boff[nfp];
                uint32_t tmp[4];
                ldsm_x4(tmp, ad);
                bh[2*nfp][0] = tmp[0]; bh[2*nfp+1][0] = tmp[1];
                bh[2*nfp][1] = tmp[2]; bh[2*nfp+1][1] = tmp[3];
                ldsm_x4(tmp, ad + WSZ);
                bl[2*nfp][0] = tmp[0]; bl[2*nfp+1][0] = tmp[1];
                bl[2*nfp][1] = tmp[2]; bl[2*nfp+1][1] = tmp[3];
            }
            #pragma unroll
            for (int mf = 0; mf < 2; ++mf) {
                // A fragment addresses: rows = 16 consecutive pixels in x
                const int pyb = (wid<<1) + mf + dy;
                const int pix = pyb*HC + dx + lt_lo*8 + lrow;
                uint32_t aoff = (uint32_t)(pix*32 + ((lt_h ^ ((pix>>2)&1)) << 4));
                uint32_t ah[4], al[4];
                ldsm_x4(ah, aHiBase + aoff);
                ldsm_x4(al, aHiBase + aoff + ASZ);
                #pragma unroll
                for (int nf = 0; nf < 8; ++nf) {
                    mma_bf16(acc[mf][nf], ah, bh[nf]);
                    mma_bf16(acc[mf][nf], ah, bl[nf]);
                    mma_bf16(acc[mf][nf], al, bh[nf]);
                }
            }
        }
        __syncthreads();
    }

    // ---- epilogue: thread owns pixels (gy, gx0) & (gy, gx0+8), co pairs ----
    #pragma unroll
    for (int mf = 0; mf < 2; ++mf) {
        const int gy  = by0 + (wid<<1) + mf;
        const int gx0 = bx0 + g;
        const int gx8 = gx0 + 8;
        float s0 = 1.f, s8 = 1.f;
        if (SALCAL) {
            s0 = sal[((size_t)b*H + gy)*H + gx0];
            s8 = sal[((size_t)b*H + gy)*H + gx8];
        }
        #pragma unroll
        for (int nf = 0; nf < 8; ++nf) {
            const int co = coT*64 + nf*8 + c0;
            size_t o0 = ((size_t)(b*COUT + co)*H + gy)*H + gx0;
            size_t o1 = o0 + (size_t)H*H;
            size_t o2 = ((size_t)(b*COUT + co)*H + gy)*H + gx8;
            size_t o3 = o2 + (size_t)H*H;
            float v0 = acc[mf][nf][0]*s0, v1 = acc[mf][nf][1]*s0;
            float v2 = acc[mf][nf][2]*s8, v3 = acc[mf][nf][3]*s8;
            if (RELU) {
                v0 = fmaxf(v0, 0.f); v1 = fmaxf(v1, 0.f);
                v2 = fmaxf(v2, 0.f); v3 = fmaxf(v3, 0.f);
            }
            if (ADD_OUT) { v0 += out[o0]; v1 += out[o1]; v2 += out[o2]; v3 += out[o3]; }
            out[o0] = v0; out[o1] = v1; out[o2] = v2; out[o3] = v3;
        }
    }
}

// ===========================================================================
// Scalar 1x1 conv GEMM — small residual 64x64 conv
// ===========================================================================
template<int COUT, int CIN, int HW>
__global__ __launch_bounds__(256)
void conv1x1_kernel(const float* __restrict__ in, const float* __restrict__ w,
                    float* out)
{
    __shared__ __align__(16) float sIn[16][128];
    __shared__ __align__(16) float sW [16][64];
    const int t  = threadIdx.x;
    const int tp = t & 31, tc = t >> 5;
    const int p0 = tp * 4, co0 = tc * 8;
    const int pBase  = blockIdx.x * 128;
    const int b      = blockIdx.y;
    const int coBase = blockIdx.z * 64;

    float acc[8][4];
    #pragma unroll
    for (int i = 0; i < 8; ++i) { acc[i][0]=acc[i][1]=acc[i][2]=acc[i][3]=0.f; }

    for (int kc = 0; kc < CIN / 16; ++kc) {
        const int kBase = kc * 16;
        #pragma unroll
        for (int i = t; i < 512; i += 256) {
            int k = i >> 5, x4 = i & 31;
            float4 v = *(const float4*)(in + (size_t)(b*CIN + kBase + k)*HW + pBase + x4*4);
            *(float4*)&sIn[k][x4*4] = v;
        }
        #pragma unroll
        for (int i = t; i < 1024; i += 256) {
            int co = i >> 4, k = i & 15;
            sW[k][co] = w[(size_t)(coBase + co)*CIN + kBase + k];
        }
        __syncthreads();
        #pragma unroll
        for (int k = 0; k < 16; ++k) {
            float4 v  = *(const float4*)&sIn[k][p0];
            float4 wl = *(const float4*)&sW[k][co0];
            float4 wh = *(const float4*)&sW[k][co0 + 4];
            float va[4] = {v.x, v.y, v.z, v.w};
            float wa[8] = {wl.x, wl.y, wl.z, wl.w, wh.x, wh.y, wh.z, wh.w};
            #pragma unroll
            for (int co = 0; co < 8; ++co)
                #pragma unroll
                for (int j = 0; j < 4; ++j)
                    acc[co][j] += wa[co] * va[j];
        }
        __syncthreads();
    }

    const int pg = pBase + p0;
    #pragma unroll
    for (int co = 0; co < 8; ++co) {
        size_t oi = (size_t)(b*COUT + coBase + co0 + co)*HW + pg;
        *(float4*)(out + oi) = make_float4(acc[co][0], acc[co][1], acc[co][2], acc[co][3]);
    }
}

// ===========================================================================
// Attention glue kernels
// ===========================================================================
__global__ void chanpool_kernel(const float* __restrict__ r2, float* __restrict__ pool)
{
    int p = blockIdx.x * 256 + threadIdx.x;
    int b = blockIdx.y;
    const float* base = r2 + (((size_t)b*512) << 14) + p;
    float mx = -3.4e38f, s = 0.f;
    #pragma unroll 8
    for (int c = 0; c < 512; ++c) {
        float v = base[(size_t)c << 14];
        mx = fmaxf(mx, v);
        s += v;
    }
    pool[(((size_t)(b*2    )) << 14) + p] = mx;
    pool[(((size_t)(b*2 + 1)) << 14) + p] = s * (1.f/512.f);
}

__global__ void salconv_kernel(const float* __restrict__ pool,
                               const float* __restrict__ wsal,
                               float* __restrict__ sal)
{
    int p = blockIdx.x * 256 + threadIdx.x;
    int b = blockIdx.y;
    int y = p >> 7, x = p & 127;
    float a = 0.f;
    #pragma unroll
    for (int c = 0; c < 2; ++c) {
        const float* pp = pool + (((size_t)(b*2 + c)) << 14);
        #pragma unroll
        for (int ky = 0; ky < 5; ++ky) {
            int iy = y + ky - 2;
            if (iy < 0 || iy >= 128) continue;
            #pragma unroll
            for (int kx = 0; kx < 5; ++kx) {
                int ix = x + kx - 2;
                if (ix < 0 || ix >= 128) continue;
                a += wsal[c*25 + ky*5 + kx] * pp[(iy << 7) + ix];
            }
        }
    }
    sal[(((size_t)b) << 14) + p] = 1.f / (1.f + expf(-a));
}

__global__ void wmean_kernel(const float* __restrict__ r2,
                             const float* __restrict__ sal,
                             float* __restrict__ m)
{
    int c = blockIdx.x, b = blockIdx.y;
    const float* r = r2 + (((size_t)(b*512 + c)) << 14);
    const float* s = sal + (((size_t)b) << 14);
    float sum = 0.f;
    for (int i = threadIdx.x; i < 4096; i += 256) {
        float4 rv = *(const float4*)(r + i*4);
        float4 sv = *(const float4*)(s + i*4);
        sum += rv.x*sv.x + rv.y*sv.y + rv.z*sv.z + rv.w*sv.w;
    }
    #pragma unroll
    for (int o = 16; o > 0; o >>= 1) sum += __shfl_xor_sync(0xffffffffu, sum, o);
    __shared__ float red[8];
    if ((threadIdx.x & 31) == 0) red[threadIdx.x >> 5] = sum;
    __syncthreads();
    if (threadIdx.x == 0) {
        float tot = 0.f;
        #pragma unroll
        for (int i = 0; i < 8; ++i) tot += red[i];
        m[b*512 + c] = tot * (1.f/16384.f);
    }
}

__global__ void calmlp_kernel(const float* __restrict__ m,
                              const float* __restrict__ wca1,
                              const float* __restrict__ wca2,
                              float* __restrict__ cal)
{
    int b = blockIdx.x;
    __shared__ float sm[512];
    __shared__ float sy1[32];
    for (int i = threadIdx.x; i < 512; i += 256) sm[i] = m[b*512 + i];
    __syncthreads();
    if (threadIdx.x < 32) {
        float a = 0.f;
        for (int c = 0; c < 512; ++c) a += wca1[threadIdx.x*512 + c] * sm[c];
        sy1[threadIdx.x] = fmaxf(a, 0.f);
    }
    __syncthreads();
    for (int c = threadIdx.x; c < 512; c += 256) {
        float a = 0.f;
        #pragma unroll
        for (int j = 0; j < 32; ++j) a += wca2[c*32 + j] * sy1[j];
        cal[b*512 + c] = 1.f / (1.f + expf(-a));
    }
}

// ===========================================================================
// K9: IBWT
// ===========================================================================
__global__ void ibwt_kernel(const float* __restrict__ r, float* __restrict__ o)
{
    int idx = blockIdx.x * 256 + threadIdx.x;
    int j = idx & 127;
    int i = (idx >> 7) & 127;
    int c = (idx >> 14) & 63;
    int b = idx >> 20;
    size_t base = ((size_t)(b*512 + c) << 14) + (i << 7) + j;
    const size_t gs = (size_t)64 << 14;
    float x1 = r[base       ]*0.5f, x2 = r[base +   gs]*0.5f;
    float x3 = r[base + 2*gs]*0.5f, x4 = r[base + 3*gs]*0.5f;
    float x5 = r[base + 4*gs]*0.5f, x6 = r[base + 5*gs]*0.5f;
    float x7 = r[base + 6*gs]*0.5f, x8 = r[base + 7*gs]*0.5f;
    float a00 = x1 - x2 - x3 + x4 + x5 - x6 + x7 - x8;
    float a10 = x1 - x2 + x3 - x4 - x5 + x6 - x7 + x8;
    float a01 = x1 + x2 - x3 - x4 - x5 - x6 + x7 + x8;
    float a11 = x1 + x2 + x3 + x4 + x5 + x6 + x7 + x8;
    float* op = o + ((size_t)(b*64 + c)*256 + 2*i)*256 + 2*j;
    *(float2*)op         = make_float2(a00, a01);
    *(float2*)(op + 256) = make_float2(a10, a11);
}

// ===========================================================================
// Launch
// ===========================================================================
extern "C" void kernel_launch(void* const* d_in, const int* in_sizes, int n_in,
                              void* d_out, int out_size)
{
    const float* x       = (const float*)d_in[0];
    const float* w_body1 = (const float*)d_in[1];
    const float* w_body2 = (const float*)d_in[2];
    const float* w_sal   = (const float*)d_in[3];
    const float* w_ca1   = (const float*)d_in[4];
    const float* w_ca2   = (const float*)d_in[5];
    const float* w_1x1   = (const float*)d_in[6];
    const float* w_3x3   = (const float*)d_in[7];
    const float* w_final = (const float*)d_in[8];
    float* out = (float*)d_out;

    float *bwt, *r1, *r2, *pool, *sal, *m, *cal, *wave;
    cudaGetSymbolAddress((void**)&bwt,  g_bwt);
    cudaGetSymbolAddress((void**)&r1,   g_r1);
    cudaGetSymbolAddress((void**)&r2,   g_r2);
    cudaGetSymbolAddress((void**)&pool, g_pool);
    cudaGetSymbolAddress((void**)&sal,  g_sal);
    cudaGetSymbolAddress((void**)&m,    g_m);
    cudaGetSymbolAddress((void**)&cal,  g_cal);
    cudaGetSymbolAddress((void**)&wave, g_wave);

    // dynamic smem sizes: KS=3 -> 2*(18*18*32) + 2*(9*64*32) = 57600 B
    //                     KS=1 -> 2*(16*16*32) + 2*(64*32)   = 20480 B
    constexpr int SM3 = 2*(18*18*32) + 2*(9*64*32);
    constexpr int SM1 = 2*(16*16*32) + 2*(64*32);
    cudaFuncSetAttribute((const void*)mmaconv_kernel<512, 64, 128, 3, true, false, false>,
                         cudaFuncAttributeMaxDynamicSharedMemorySize, SM3);
    cudaFuncSetAttribute((const void*)mmaconv_kernel<64, 512, 128, 3, false, false, false>,
                         cudaFuncAttributeMaxDynamicSharedMemorySize, SM3);
    cudaFuncSetAttribute((const void*)mmaconv_kernel<512, 512, 128, 1, false, true, true>,
                         cudaFuncAttributeMaxDynamicSharedMemorySize, SM1);
    cudaFuncSetAttribute((const void*)mmaconv_kernel<64, 64, 256, 3, true, true, false>,
                         cudaFuncAttributeMaxDynamicSharedMemorySize, SM3);

    // 1) BWT
    bwt_kernel<<<16384, 256>>>(x, bwt);
    // 2) body1 3x3 (512 -> 64) + relu   [tensor]
    mmaconv_kernel<512, 64, 128, 3, true, false, false>
        <<<dim3(8,8,4), 256, SM3>>>(bwt, w_body1, nullptr, nullptr, r1);
    // 3) body2 3x3 (64 -> 512)          [tensor]
    mmaconv_kernel<64, 512, 128, 3, false, false, false>
        <<<dim3(8,8,32), 256, SM3>>>(r1, w_body2, nullptr, nullptr, r2);
    // 4) channel pooling
    chanpool_kernel<<<dim3(64,4), 256>>>(r2, pool);
    // 5) 5x5 conv + sigmoid -> sal
    salconv_kernel<<<dim3(64,4), 256>>>(pool, w_sal, sal);
    // 6) weighted channel means
    wmean_kernel<<<dim3(512,4), 256>>>(r2, sal, m);
    // 7) channel attention MLP
    calmlp_kernel<<<4, 256>>>(m, w_ca1, w_ca2, cal);
    // 8) 1x1 conv (512->512): cal folded, sal epilogue, += x_bwt  [tensor]
    mmaconv_kernel<512, 512, 128, 1, false, true, true>
        <<<dim3(8,8,32), 256, SM1>>>(r2, w_1x1, sal, cal, bwt);
    // 9) IBWT
    ibwt_kernel<<<16384, 256>>>(bwt, wave);
    // 10) residual 1x1 conv -> out (scalar, small)
    conv1x1_kernel<64, 64, 65536><<<dim3(512,4,1), 256>>>(x, w_final, out);
    // 11) final 3x3 conv (64->64) + relu, added onto out  [tensor]
    mmaconv_kernel<64, 64, 256, 3, true, true, false>
        <<<dim3(16,16,4), 256, SM3>>>(wave, w_3x3, nullptr, nullptr, out);
}

// round 7
// speedup vs baseline: 1.3029x; 1.3029x over previous
#include <cuda_runtime.h>
#include <cuda_bf16.h>
#include <math.h>
#include <stdint.h>

// ===========================================================================
// mma.sync m16n8k16 row.col bf16*bf16 -> f32  (compute_80+, OK on sm_103)
// ===========================================================================
__device__ __forceinline__ void mma_bf16(float* c, const uint32_t* a, const uint32_t* b)
{
    asm volatile(
        "mma.sync.aligned.m16n8k16.row.col.f32.bf16.bf16.f32 "
        "{%0,%1,%2,%3}, {%4,%5,%6,%7}, {%8,%9}, {%0,%1,%2,%3};"
        : "+f"(c[0]), "+f"(c[1]), "+f"(c[2]), "+f"(c[3])
        : "r"(a[0]), "r"(a[1]), "r"(a[2]), "r"(a[3]), "r"(b[0]), "r"(b[1]));
}
__device__ __forceinline__ void ldsm_x4(uint32_t* r, uint32_t addr)
{
    asm volatile(
        "ldmatrix.sync.aligned.m8n8.x4.shared.b16 {%0,%1,%2,%3}, [%4];"
        : "=r"(r[0]), "=r"(r[1]), "=r"(r[2]), "=r"(r[3]) : "r"(addr));
}
// split f32 into (hi bf16 | lo bf16 << 16)
__device__ __forceinline__ uint32_t splitpack(float v)
{
    __nv_bfloat16 h = __float2bfloat16_rn(v);
    __nv_bfloat16 l = __float2bfloat16_rn(v - __bfloat162float(h));
    return ((uint32_t)__bfloat16_as_ushort(l) << 16) | __bfloat16_as_ushort(h);
}

// ===========================================================================
// Scratch buffers
// ===========================================================================
__device__ float    g_bwt   [(size_t)4*512*128*128];  // f32 (for += x_bwt)
__device__ uint32_t g_bwt_pk[(size_t)4*512*128*128];  // packed split
__device__ uint32_t g_r1_pk [(size_t)4*64*128*128];
__device__ float    g_r2    [(size_t)4*512*128*128];
__device__ uint32_t g_r2_pk [(size_t)4*512*128*128];
__device__ uint32_t g_wv_pk [(size_t)4*64*256*256];
__device__ float    g_pool  [(size_t)4*2*128*128];
__device__ float    g_sal   [(size_t)4*128*128];
__device__ float    g_m     [4*512];
__device__ float    g_cal   [4*512];
__device__ uint32_t g_wp1   [9*64*512];        // body1 weights packed [tap][co][ci]
__device__ uint32_t g_wp2   [9*512*64];        // body2
__device__ uint32_t g_wp3   [9*64*64];         // final 3x3
__device__ uint32_t g_wpc   [(size_t)4*512*512]; // 1x1 * cal, per batch

// ===========================================================================
// Weight prep: f32 [CO][CI][KS2] -> packed u32 [tap][CO][CI]
// ===========================================================================
__global__ void packw_kernel(const float* __restrict__ w, uint32_t* __restrict__ wp,
                             int CO, int CI, int KS2, int total)
{
    int i = blockIdx.x*256 + threadIdx.x;
    if (i >= total) return;
    int tap = i % KS2;
    int r   = i / KS2;
    int ci  = r % CI;
    int co  = r / CI;
    wp[((size_t)tap*CO + co)*CI + ci] = splitpack(w[i]);
}
// 1x1 weights with cal folded, per batch: wp[b][co][ci]
__global__ void packwcal_kernel(const float* __restrict__ w, const float* __restrict__ cal,
                                uint32_t* __restrict__ wp)
{
    int i  = blockIdx.x*256 + threadIdx.x;   // 4*512*512
    int ci = i & 511;
    int co = (i >> 9) & 511;
    int b  = i >> 18;
    wp[i] = splitpack(w[co*512 + ci] * cal[b*512 + ci]);
}

// ===========================================================================
// K1: BWT  x(4,64,256,256) -> f32 + packed (4,512,128,128)
// ===========================================================================
__global__ void bwt_kernel(const float* __restrict__ x, float* __restrict__ o,
                           uint32_t* __restrict__ opk)
{
    int idx = blockIdx.x * 256 + threadIdx.x;
    int j = idx & 127;
    int i = (idx >> 7) & 127;
    int c = (idx >> 14) & 63;
    int b = idx >> 20;
    const float* xp = x + ((size_t)(b*64 + c)*256 + 2*i)*256 + 2*j;
    float2 r0 = *(const float2*)xp;
    float2 r1 = *(const float2*)(xp + 256);
    float x1 = r0.x*0.5f, x3 = r0.y*0.5f, x2 = r1.x*0.5f, x4 = r1.y*0.5f;
    size_t ob = ((size_t)(b*512 + c) << 14) + (i << 7) + j;
    const size_t gs = (size_t)64 << 14;
    float v;
    v =  x1 + x2 + x3 + x4; o[ob + 0*gs] = v; opk[ob + 0*gs] = splitpack(v);
    v = -x1 - x2 + x3 + x4; o[ob + 1*gs] = v; opk[ob + 1*gs] = splitpack(v);
    v = -x1 + x2 - x3 + x4; o[ob + 2*gs] = v; opk[ob + 2*gs] = splitpack(v);
    v =  x1 - x2 - x3 + x4; o[ob + 3*gs] = v; opk[ob + 3*gs] = splitpack(v);
    v =  x1 + x2 - x3 - x4; o[ob + 4*gs] = v; opk[ob + 4*gs] = splitpack(v);
    v = -x1 + x2 + x3 - x4; o[ob + 5*gs] = v; opk[ob + 5*gs] = splitpack(v);
    v =  x1 - x2 + x3 - x4; o[ob + 6*gs] = v; opk[ob + 6*gs] = splitpack(v);
    v = -x1 - x2 - x3 - x4; o[ob + 7*gs] = v; opk[ob + 7*gs] = splitpack(v);
}

// ===========================================================================
// Implicit-GEMM conv via mma.sync + ldmatrix, packed-split operands.
// CTA: 256 threads (8 warps), tile 16x16 pixels x 64 couts.
// Warp tile m32 x n64. K: 16 ci/chunk x KS*KS taps.
//   D = Ahi*Bhi + Ahi*Blo + Alo*Bhi  (f32 accumulate)
// ===========================================================================
template<int CIN, int COUT, int H, int KS,
         bool RELU, bool ADD_OUT, bool SAL, bool WPERB, bool OUTF32, bool OUTPK>
__global__ __launch_bounds__(256)
void mmaconv_kernel(const uint32_t* __restrict__ in_pk, const uint32_t* __restrict__ wp,
                    const float* __restrict__ sal,
                    float* outf, uint32_t* __restrict__ outpk)
{
    constexpr int KS2 = KS*KS;
    constexpr int PAD = KS/2;
    constexpr int HC  = 16 + KS - 1;
    constexpr int HEL = HC*HC;
    constexpr int ASZ = HEL*32;       // bytes per A (hi or lo) buffer
    constexpr int WSZ = KS2*64*32;    // bytes per W (hi or lo) buffer

    extern __shared__ __align__(16) char smem[];
    uint32_t* Ahi = (uint32_t*)(smem);
    uint32_t* Alo = (uint32_t*)(smem + ASZ);
    uint32_t* Whi = (uint32_t*)(smem + 2*ASZ);
    uint32_t* Wlo = (uint32_t*)(smem + 2*ASZ + WSZ);

    const uint32_t aHiBase = (uint32_t)__cvta_generic_to_shared(Ahi);
    const uint32_t wHiBase = aHiBase + 2*ASZ;

    const int t    = threadIdx.x;
    const int lane = t & 31, wid = t >> 5;
    const int g    = lane >> 2;
    const int c0   = (lane & 3) * 2;
    const int bx0  = blockIdx.x * 16;
    const int by0  = blockIdx.y * 16;
    const int z    = blockIdx.z;
    const int coT  = z % (COUT/64);
    const int b    = z / (COUT/64);

    const int ltile = lane >> 3, lrow = lane & 7;
    const int lt_lo = ltile & 1;
    const int lt_h  = ltile >> 1;

    uint32_t boff[4];
    #pragma unroll
    for (int nfp = 0; nfp < 4; ++nfp) {
        int co_row = nfp*16 + lt_lo*8 + lrow;
        boff[nfp] = (uint32_t)(co_row*32 + ((lt_h ^ ((co_row>>2)&1)) << 4));
    }

    float acc[2][8][4];
    #pragma unroll
    for (int mf = 0; mf < 2; ++mf)
        #pragma unroll
        for (int nf = 0; nf < 8; ++nf)
            #pragma unroll
            for (int q = 0; q < 4; ++q) acc[mf][nf][q] = 0.f;

    #pragma unroll 1
    for (int cc = 0; cc < CIN/16; ++cc) {
        const int cb = cc * 16;

        // ---- stage A: packed u32 loads, PRMT split, coalesced over pixels ----
        for (int idx = t; idx < 8*HEL; idx += 256) {
            int cip = idx / HEL;           // ci pair 0..7
            int pix = idx - cip*HEL;
            int py  = pix / HC;
            int px  = pix - py*HC;
            int gy  = by0 + py - PAD;
            int gx  = bx0 + px - PAD;
            uint32_t va = 0, vb = 0;
            if (gy >= 0 && gy < H && gx >= 0 && gx < H) {
                size_t base = ((size_t)(b*CIN + cb + 2*cip)*H + gy)*H + gx;
                va = in_pk[base];
                vb = in_pk[base + (size_t)H*H];
            }
            int u = pix*8 + (((cip>>2) ^ ((pix>>2)&1)) << 2) + (cip & 3);
            Ahi[u] = __byte_perm(va, vb, 0x5410);
            Alo[u] = __byte_perm(va, vb, 0x7632);
        }
        // ---- stage W: packed, contiguous [tap][co][ci] ----
        for (int idx = t; idx < KS2*64*8; idx += 256) {
            int cip = idx & 7;
            int r   = idx >> 3;            // tap*64 + co
            int co  = r & 63;
            int tap = r >> 6;
            size_t wb = (WPERB ? (size_t)b*COUT*CIN : 0)
                      + ((size_t)(tap*COUT + coT*64 + co)*CIN + cb + 2*cip);
            uint2 wv = *(const uint2*)(wp + wb);
            int u = r*8 + (((cip>>2) ^ ((co>>2)&1)) << 2) + (cip & 3);
            Whi[u] = __byte_perm(wv.x, wv.y, 0x5410);
            Wlo[u] = __byte_perm(wv.x, wv.y, 0x7632);
        }
        __syncthreads();

        #pragma unroll
        for (int tap = 0; tap < KS2; ++tap) {
            const int dy = tap / KS, dx = tap - dy*KS;

            uint32_t bh[8][2], bl[8][2];
            #pragma unroll
            for (int nfp = 0; nfp < 4; ++nfp) {
                uint32_t ad = wHiBase + (uint32_t)(tap*2048) + boff[nfp];
                uint32_t tmp[4];
                ldsm_x4(tmp, ad);
                bh[2*nfp][0] = tmp[0]; bh[2*nfp+1][0] = tmp[1];
                bh[2*nfp][1] = tmp[2]; bh[2*nfp+1][1] = tmp[3];
                ldsm_x4(tmp, ad + WSZ);
                bl[2*nfp][0] = tmp[0]; bl[2*nfp+1][0] = tmp[1];
                bl[2*nfp][1] = tmp[2]; bl[2*nfp+1][1] = tmp[3];
            }
            #pragma unroll
            for (int mf = 0; mf < 2; ++mf) {
                const int pyb = (wid<<1) + mf + dy;
                const int pix = pyb*HC + dx + lt_lo*8 + lrow;
                uint32_t aoff = (uint32_t)(pix*32 + ((lt_h ^ ((pix>>2)&1)) << 4));
                uint32_t ah[4], al[4];
                ldsm_x4(ah, aHiBase + aoff);
                ldsm_x4(al, aHiBase + aoff + ASZ);
                #pragma unroll
                for (int nf = 0; nf < 8; ++nf) {
                    mma_bf16(acc[mf][nf], ah, bh[nf]);
                    mma_bf16(acc[mf][nf], ah, bl[nf]);
                    mma_bf16(acc[mf][nf], al, bh[nf]);
                }
            }
        }
        __syncthreads();
    }

    // ---- epilogue ----
    #pragma unroll
    for (int mf = 0; mf < 2; ++mf) {
        const int gy  = by0 + (wid<<1) + mf;
        const int gx0 = bx0 + g;
        const int gx8 = gx0 + 8;
        float s0 = 1.f, s8 = 1.f;
        if (SAL) {
            s0 = sal[((size_t)b*H + gy)*H + gx0];
            s8 = sal[((size_t)b*H + gy)*H + gx8];
        }
        #pragma unroll
        for (int nf = 0; nf < 8; ++nf) {
            const int co = coT*64 + nf*8 + c0;
            size_t o0 = ((size_t)(b*COUT + co)*H + gy)*H + gx0;
            size_t o1 = o0 + (size_t)H*H;
            size_t o2 = ((size_t)(b*COUT + co)*H + gy)*H + gx8;
            size_t o3 = o2 + (size_t)H*H;
            float v0 = acc[mf][nf][0]*s0, v1 = acc[mf][nf][1]*s0;
            float v2 = acc[mf][nf][2]*s8, v3 = acc[mf][nf][3]*s8;
            if (RELU) {
                v0 = fmaxf(v0, 0.f); v1 = fmaxf(v1, 0.f);
                v2 = fmaxf(v2, 0.f); v3 = fmaxf(v3, 0.f);
            }
            if (ADD_OUT) { v0 += outf[o0]; v1 += outf[o1]; v2 += outf[o2]; v3 += outf[o3]; }
            if (OUTF32) { outf[o0] = v0; outf[o1] = v1; outf[o2] = v2; outf[o3] = v3; }
            if (OUTPK) {
                outpk[o0] = splitpack(v0); outpk[o1] = splitpack(v1);
                outpk[o2] = splitpack(v2); outpk[o3] = splitpack(v3);
            }
        }
    }
}

// ===========================================================================
// Scalar 1x1 conv GEMM — small residual 64x64 conv
// ===========================================================================
template<int COUT, int CIN, int HW>
__global__ __launch_bounds__(256)
void conv1x1_kernel(const float* __restrict__ in, const float* __restrict__ w,
                    float* out)
{
    __shared__ __align__(16) float sIn[16][128];
    __shared__ __align__(16) float sW [16][64];
    const int t  = threadIdx.x;
    const int tp = t & 31, tc = t >> 5;
    const int p0 = tp * 4, co0 = tc * 8;
    const int pBase  = blockIdx.x * 128;
    const int b      = blockIdx.y;
    const int coBase = blockIdx.z * 64;

    float acc[8][4];
    #pragma unroll
    for (int i = 0; i < 8; ++i) { acc[i][0]=acc[i][1]=acc[i][2]=acc[i][3]=0.f; }

    for (int kc = 0; kc < CIN / 16; ++kc) {
        const int kBase = kc * 16;
        #pragma unroll
        for (int i = t; i < 512; i += 256) {
            int k = i >> 5, x4 = i & 31;
            float4 v = *(const float4*)(in + (size_t)(b*CIN + kBase + k)*HW + pBase + x4*4);
            *(float4*)&sIn[k][x4*4] = v;
        }
        #pragma unroll
        for (int i = t; i < 1024; i += 256) {
            int co = i >> 4, k = i & 15;
            sW[k][co] = w[(size_t)(coBase + co)*CIN + kBase + k];
        }
        __syncthreads();
        #pragma unroll
        for (int k = 0; k < 16; ++k) {
            float4 v  = *(const float4*)&sIn[k][p0];
            float4 wl = *(const float4*)&sW[k][co0];
            float4 wh = *(const float4*)&sW[k][co0 + 4];
            float va[4] = {v.x, v.y, v.z, v.w};
            float wa[8] = {wl.x, wl.y, wl.z, wl.w, wh.x, wh.y, wh.z, wh.w};
            #pragma unroll
            for (int co = 0; co < 8; ++co)
                #pragma unroll
                for (int j = 0; j < 4; ++j)
                    acc[co][j] += wa[co] * va[j];
        }
        __syncthreads();
    }

    const int pg = pBase + p0;
    #pragma unroll
    for (int co = 0; co < 8; ++co) {
        size_t oi = (size_t)(b*COUT + coBase + co0 + co)*HW + pg;
        *(float4*)(out + oi) = make_float4(acc[co][0], acc[co][1], acc[co][2], acc[co][3]);
    }
}

// ===========================================================================
// Attention glue kernels
// ===========================================================================
__global__ void chanpool_kernel(const float* __restrict__ r2, float* __restrict__ pool)
{
    int p = blockIdx.x * 256 + threadIdx.x;
    int b = blockIdx.y;
    const float* base = r2 + (((size_t)b*512) << 14) + p;
    float mx = -3.4e38f, s = 0.f;
    #pragma unroll 8
    for (int c = 0; c < 512; ++c) {
        float v = base[(size_t)c << 14];
        mx = fmaxf(mx, v);
        s += v;
    }
    pool[(((size_t)(b*2    )) << 14) + p] = mx;
    pool[(((size_t)(b*2 + 1)) << 14) + p] = s * (1.f/512.f);
}

__global__ void salconv_kernel(const float* __restrict__ pool,
                               const float* __restrict__ wsal,
                               float* __restrict__ sal)
{
    int p = blockIdx.x * 256 + threadIdx.x;
    int b = blockIdx.y;
    int y = p >> 7, x = p & 127;
    float a = 0.f;
    #pragma unroll
    for (int c = 0; c < 2; ++c) {
        const float* pp = pool + (((size_t)(b*2 + c)) << 14);
        #pragma unroll
        for (int ky = 0; ky < 5; ++ky) {
            int iy = y + ky - 2;
            if (iy < 0 || iy >= 128) continue;
            #pragma unroll
            for (int kx = 0; kx < 5; ++kx) {
                int ix = x + kx - 2;
                if (ix < 0 || ix >= 128) continue;
                a += wsal[c*25 + ky*5 + kx] * pp[(iy << 7) + ix];
            }
        }
    }
    sal[(((size_t)b) << 14) + p] = 1.f / (1.f + expf(-a));
}

__global__ void wmean_kernel(const float* __restrict__ r2,
                             const float* __restrict__ sal,
                             float* __restrict__ m)
{
    int c = blockIdx.x, b = blockIdx.y;
    const float* r = r2 + (((size_t)(b*512 + c)) << 14);
    const float* s = sal + (((size_t)b) << 14);
    float sum = 0.f;
    for (int i = threadIdx.x; i < 4096; i += 256) {
        float4 rv = *(const float4*)(r + i*4);
        float4 sv = *(const float4*)(s + i*4);
        sum += rv.x*sv.x + rv.y*sv.y + rv.z*sv.z + rv.w*sv.w;
    }
    #pragma unroll
    for (int o = 16; o > 0; o >>= 1) sum += __shfl_xor_sync(0xffffffffu, sum, o);
    __shared__ float red[8];
    if ((threadIdx.x & 31) == 0) red[threadIdx.x >> 5] = sum;
    __syncthreads();
    if (threadIdx.x == 0) {
        float tot = 0.f;
        #pragma unroll
        for (int i = 0; i < 8; ++i) tot += red[i];
        m[b*512 + c] = tot * (1.f/16384.f);
    }
}

__global__ void calmlp_kernel(const float* __restrict__ m,
                              const float* __restrict__ wca1,
                              const float* __restrict__ wca2,
                              float* __restrict__ cal)
{
    int b = blockIdx.x;
    __shared__ float sm[512];
    __shared__ float sy1[32];
    for (int i = threadIdx.x; i < 512; i += 256) sm[i] = m[b*512 + i];
    __syncthreads();
    if (threadIdx.x < 32) {
        float a = 0.f;
        for (int c = 0; c < 512; ++c) a += wca1[threadIdx.x*512 + c] * sm[c];
        sy1[threadIdx.x] = fmaxf(a, 0.f);
    }
    __syncthreads();
    for (int c = threadIdx.x; c < 512; c += 256) {
        float a = 0.f;
        #pragma unroll
        for (int j = 0; j < 32; ++j) a += wca2[c*32 + j] * sy1[j];
        cal[b*512 + c] = 1.f / (1.f + expf(-a));
    }
}

// ===========================================================================
// K9: IBWT -> packed split output
// ===========================================================================
__global__ void ibwt_kernel(const float* __restrict__ r, uint32_t* __restrict__ opk)
{
    int idx = blockIdx.x * 256 + threadIdx.x;
    int j = idx & 127;
    int i = (idx >> 7) & 127;
    int c = (idx >> 14) & 63;
    int b = idx >> 20;
    size_t base = ((size_t)(b*512 + c) << 14) + (i << 7) + j;
    const size_t gs = (size_t)64 << 14;
    float x1 = r[base       ]*0.5f, x2 = r[base +   gs]*0.5f;
    float x3 = r[base + 2*gs]*0.5f, x4 = r[base + 3*gs]*0.5f;
    float x5 = r[base + 4*gs]*0.5f, x6 = r[base + 5*gs]*0.5f;
    float x7 = r[base + 6*gs]*0.5f, x8 = r[base + 7*gs]*0.5f;
    float a00 = x1 - x2 - x3 + x4 + x5 - x6 + x7 - x8;
    float a10 = x1 - x2 + x3 - x4 - x5 + x6 - x7 + x8;
    float a01 = x1 + x2 - x3 - x4 - x5 - x6 + x7 + x8;
    float a11 = x1 + x2 + x3 + x4 + x5 + x6 + x7 + x8;
    uint32_t* op = opk + ((size_t)(b*64 + c)*256 + 2*i)*256 + 2*j;
    op[0]   = splitpack(a00);  op[1]     = splitpack(a01);
    op[256] = splitpack(a10);  op[257]   = splitpack(a11);
}

// ===========================================================================
// Launch
// ===========================================================================
extern "C" void kernel_launch(void* const* d_in, const int* in_sizes, int n_in,
                              void* d_out, int out_size)
{
    const float* x       = (const float*)d_in[0];
    const float* w_body1 = (const float*)d_in[1];
    const float* w_body2 = (const float*)d_in[2];
    const float* w_sal   = (const float*)d_in[3];
    const float* w_ca1   = (const float*)d_in[4];
    const float* w_ca2   = (const float*)d_in[5];
    const float* w_1x1   = (const float*)d_in[6];
    const float* w_3x3   = (const float*)d_in[7];
    const float* w_final = (const float*)d_in[8];
    float* out = (float*)d_out;

    float *bwt, *r2, *pool, *sal, *m, *cal;
    uint32_t *bwt_pk, *r1_pk, *r2_pk, *wv_pk, *wp1, *wp2, *wp3, *wpc;
    cudaGetSymbolAddress((void**)&bwt,    g_bwt);
    cudaGetSymbolAddress((void**)&bwt_pk, g_bwt_pk);
    cudaGetSymbolAddress((void**)&r1_pk,  g_r1_pk);
    cudaGetSymbolAddress((void**)&r2,     g_r2);
    cudaGetSymbolAddress((void**)&r2_pk,  g_r2_pk);
    cudaGetSymbolAddress((void**)&wv_pk,  g_wv_pk);
    cudaGetSymbolAddress((void**)&pool,   g_pool);
    cudaGetSymbolAddress((void**)&sal,    g_sal);
    cudaGetSymbolAddress((void**)&m,      g_m);
    cudaGetSymbolAddress((void**)&cal,    g_cal);
    cudaGetSymbolAddress((void**)&wp1,    g_wp1);
    cudaGetSymbolAddress((void**)&wp2,    g_wp2);
    cudaGetSymbolAddress((void**)&wp3,    g_wp3);
    cudaGetSymbolAddress((void**)&wpc,    g_wpc);

    constexpr int SM3 = 2*(18*18*32) + 2*(9*64*32);
    constexpr int SM1 = 2*(16*16*32) + 2*(64*32);
    cudaFuncSetAttribute(
        (const void*)mmaconv_kernel<512,64,128,3, true,false,false,false,false,true>,
        cudaFuncAttributeMaxDynamicSharedMemorySize, SM3);
    cudaFuncSetAttribute(
        (const void*)mmaconv_kernel<64,512,128,3, false,false,false,false,true,true>,
        cudaFuncAttributeMaxDynamicSharedMemorySize, SM3);
    cudaFuncSetAttribute(
        (const void*)mmaconv_kernel<512,512,128,1, false,true,true,true,true,false>,
        cudaFuncAttributeMaxDynamicSharedMemorySize, SM1);
    cudaFuncSetAttribute(
        (const void*)mmaconv_kernel<64,64,256,3, true,true,false,false,true,false>,
        cudaFuncAttributeMaxDynamicSharedMemorySize, SM3);

    // 0) weight prep (batch-independent)
    packw_kernel<<<(64*512*9 + 255)/256, 256>>>(w_body1, wp1, 64, 512, 9, 64*512*9);
    packw_kernel<<<(512*64*9 + 255)/256, 256>>>(w_body2, wp2, 512, 64, 9, 512*64*9);
    packw_kernel<<<(64*64*9  + 255)/256, 256>>>(w_3x3,   wp3, 64, 64, 9, 64*64*9);

    // 1) BWT (f32 + packed)
    bwt_kernel<<<16384, 256>>>(x, bwt, bwt_pk);
    // 2) body1 3x3 (512 -> 64) + relu -> r1 packed
    mmaconv_kernel<512,64,128,3, true,false,false,false,false,true>
        <<<dim3(8,8,4), 256, SM3>>>(bwt_pk, wp1, nullptr, nullptr, r1_pk);
    // 3) body2 3x3 (64 -> 512) -> r2 f32 + packed
    mmaconv_kernel<64,512,128,3, false,false,false,false,true,true>
        <<<dim3(8,8,32), 256, SM3>>>(r1_pk, wp2, nullptr, r2, r2_pk);
    // 4) channel pooling
    chanpool_kernel<<<dim3(64,4), 256>>>(r2, pool);
    // 5) 5x5 conv + sigmoid -> sal
    salconv_kernel<<<dim3(64,4), 256>>>(pool, w_sal, sal);
    // 6) weighted channel means
    wmean_kernel<<<dim3(512,4), 256>>>(r2, sal, m);
    // 7) channel attention MLP
    calmlp_kernel<<<4, 256>>>(m, w_ca1, w_ca2, cal);
    // 7b) 1x1 weights with cal folded (per batch)
    packwcal_kernel<<<(4*512*512)/256, 256>>>(w_1x1, cal, wpc);
    // 8) 1x1 conv (512->512): sal epilogue, += x_bwt (f32, in place)
    mmaconv_kernel<512,512,128,1, false,true,true,true,true,false>
        <<<dim3(8,8,32), 256, SM1>>>(r2_pk, wpc, sal, bwt, nullptr);
    // 9) IBWT -> packed wave
    ibwt_kernel<<<16384, 256>>>(bwt, wv_pk);
    // 10) residual 1x1 conv -> out (scalar f32)
    conv1x1_kernel<64, 64, 65536><<<dim3(512,4,1), 256>>>(x, w_final, out);
    // 11) final 3x3 conv (64->64) + relu, added onto out
    mmaconv_kernel<64,64,256,3, true,true,false,false,true,false>
        <<<dim3(16,16,4), 256, SM3>>>(wv_pk, wp3, nullptr, out, nullptr);
}

// round 8
// speedup vs baseline: 1.4673x; 1.1262x over previous
#include <cuda_runtime.h>
#include <cuda_fp16.h>
#include <math.h>
#include <stdint.h>

// ===========================================================================
// mma.sync m16n8k16 row.col fp16*fp16 -> f32  (compute_80+, OK on sm_103)
// ===========================================================================
__device__ __forceinline__ void mma_f16(float* c, const uint32_t* a, const uint32_t* b)
{
    asm volatile(
        "mma.sync.aligned.m16n8k16.row.col.f32.f16.f16.f32 "
        "{%0,%1,%2,%3}, {%4,%5,%6,%7}, {%8,%9}, {%0,%1,%2,%3};"
        : "+f"(c[0]), "+f"(c[1]), "+f"(c[2]), "+f"(c[3])
        : "r"(a[0]), "r"(a[1]), "r"(a[2]), "r"(a[3]), "r"(b[0]), "r"(b[1]));
}
__device__ __forceinline__ void ldsm_x4(uint32_t* r, uint32_t addr)
{
    asm volatile(
        "ldmatrix.sync.aligned.m8n8.x4.shared.b16 {%0,%1,%2,%3}, [%4];"
        : "=r"(r[0]), "=r"(r[1]), "=r"(r[2]), "=r"(r[3]) : "r"(addr));
}
// split f32 into (hi fp16 | lo fp16 << 16)
__device__ __forceinline__ uint32_t splitpack(float v)
{
    __half h = __float2half_rn(v);
    __half l = __float2half_rn(v - __half2float(h));
    return ((uint32_t)__half_as_ushort(l) << 16) | __half_as_ushort(h);
}

// ===========================================================================
// Scratch buffers
// ===========================================================================
__device__ float    g_bwt   [(size_t)4*512*128*128];  // f32 (for += x_bwt)
__device__ uint32_t g_bwt_pk[(size_t)4*512*128*128];  // packed fp16 hi/lo
__device__ uint32_t g_r1_pk [(size_t)4*64*128*128];
__device__ float    g_r2    [(size_t)4*512*128*128];
__device__ uint32_t g_r2_pk [(size_t)4*512*128*128];
__device__ uint32_t g_wv_pk [(size_t)4*64*256*256];
__device__ float    g_pool  [(size_t)4*2*128*128];
__device__ float    g_sal   [(size_t)4*128*128];
__device__ float    g_m     [4*512];
__device__ float    g_cal   [4*512];
__device__ unsigned short g_wp1 [9*64*512];          // body1 fp16 [tap][co][ci]
__device__ unsigned short g_wp2 [9*512*64];          // body2
__device__ unsigned short g_wp3 [9*64*64];           // final 3x3
__device__ unsigned short g_wpc [(size_t)4*512*512]; // 1x1 * cal, per batch

// ===========================================================================
// Weight prep: f32 [CO][CI][KS2] -> fp16 [tap][CO][CI]
// ===========================================================================
__global__ void packw_kernel(const float* __restrict__ w, unsigned short* __restrict__ wp,
                             int CO, int CI, int KS2, int total)
{
    int i = blockIdx.x*256 + threadIdx.x;
    if (i >= total) return;
    int tap = i % KS2;
    int r   = i / KS2;
    int ci  = r % CI;
    int co  = r / CI;
    wp[((size_t)tap*CO + co)*CI + ci] = __half_as_ushort(__float2half_rn(w[i]));
}
// 1x1 weights with cal folded, per batch: wp[b][co][ci]
__global__ void packwcal_kernel(const float* __restrict__ w, const float* __restrict__ cal,
                                unsigned short* __restrict__ wp)
{
    int i  = blockIdx.x*256 + threadIdx.x;   // 4*512*512
    int ci = i & 511;
    int co = (i >> 9) & 511;
    int b  = i >> 18;
    wp[i] = __half_as_ushort(__float2half_rn(w[co*512 + ci] * cal[b*512 + ci]));
}

// ===========================================================================
// K1: BWT  x(4,64,256,256) -> f32 + packed (4,512,128,128)
// ===========================================================================
__global__ void bwt_kernel(const float* __restrict__ x, float* __restrict__ o,
                           uint32_t* __restrict__ opk)
{
    int idx = blockIdx.x * 256 + threadIdx.x;
    int j = idx & 127;
    int i = (idx >> 7) & 127;
    int c = (idx >> 14) & 63;
    int b = idx >> 20;
    const float* xp = x + ((size_t)(b*64 + c)*256 + 2*i)*256 + 2*j;
    float2 r0 = *(const float2*)xp;
    float2 r1 = *(const float2*)(xp + 256);
    float x1 = r0.x*0.5f, x3 = r0.y*0.5f, x2 = r1.x*0.5f, x4 = r1.y*0.5f;
    size_t ob = ((size_t)(b*512 + c) << 14) + (i << 7) + j;
    const size_t gs = (size_t)64 << 14;
    float v;
    v =  x1 + x2 + x3 + x4; o[ob + 0*gs] = v; opk[ob + 0*gs] = splitpack(v);
    v = -x1 - x2 + x3 + x4; o[ob + 1*gs] = v; opk[ob + 1*gs] = splitpack(v);
    v = -x1 + x2 - x3 + x4; o[ob + 2*gs] = v; opk[ob + 2*gs] = splitpack(v);
    v =  x1 - x2 - x3 + x4; o[ob + 3*gs] = v; opk[ob + 3*gs] = splitpack(v);
    v =  x1 + x2 - x3 - x4; o[ob + 4*gs] = v; opk[ob + 4*gs] = splitpack(v);
    v = -x1 + x2 + x3 - x4; o[ob + 5*gs] = v; opk[ob + 5*gs] = splitpack(v);
    v =  x1 - x2 + x3 - x4; o[ob + 6*gs] = v; opk[ob + 6*gs] = splitpack(v);
    v = -x1 - x2 - x3 - x4; o[ob + 7*gs] = v; opk[ob + 7*gs] = splitpack(v);
}

// ===========================================================================
// Implicit-GEMM conv via mma.sync + ldmatrix, fp16 2-term split.
// CTA: 256 threads (8 warps), tile 16x16 pixels x 64 couts.
// Warp tile m32 x n64. K: 16 ci/chunk x KS*KS taps.
//   D = Ahi*B + Alo*B   (f32 accumulate; B single fp16)
// ===========================================================================
template<int CIN, int COUT, int H, int KS,
         bool RELU, bool ADD_OUT, bool SAL, bool WPERB, bool OUTF32, bool OUTPK>
__global__ __launch_bounds__(256)
void mmaconv_kernel(const uint32_t* __restrict__ in_pk,
                    const unsigned short* __restrict__ wp,
                    const float* __restrict__ sal,
                    float* outf, uint32_t* __restrict__ outpk)
{
    constexpr int KS2 = KS*KS;
    constexpr int PAD = KS/2;
    constexpr int HC  = 16 + KS - 1;
    constexpr int HEL = HC*HC;
    constexpr int ASZ = HEL*32;       // bytes per A (hi or lo) buffer
    constexpr int WSZ = KS2*64*32;    // bytes for W (single fp16 plane)

    extern __shared__ __align__(16) char smem[];
    uint32_t* Ahi = (uint32_t*)(smem);
    uint32_t* Alo = (uint32_t*)(smem + ASZ);
    uint32_t* Wsh = (uint32_t*)(smem + 2*ASZ);

    const uint32_t aHiBase = (uint32_t)__cvta_generic_to_shared(Ahi);
    const uint32_t wBase   = aHiBase + 2*ASZ;

    const int t    = threadIdx.x;
    const int lane = t & 31, wid = t >> 5;
    const int g    = lane >> 2;
    const int c0   = (lane & 3) * 2;
    const int bx0  = blockIdx.x * 16;
    const int by0  = blockIdx.y * 16;
    const int z    = blockIdx.z;
    const int coT  = z % (COUT/64);
    const int b    = z / (COUT/64);

    const int ltile = lane >> 3, lrow = lane & 7;
    const int lt_lo = ltile & 1;
    const int lt_h  = ltile >> 1;

    uint32_t boff[4];
    #pragma unroll
    for (int nfp = 0; nfp < 4; ++nfp) {
        int co_row = nfp*16 + lt_lo*8 + lrow;
        boff[nfp] = (uint32_t)(co_row*32 + ((lt_h ^ ((co_row>>2)&1)) << 4));
    }

    float acc[2][8][4];
    #pragma unroll
    for (int mf = 0; mf < 2; ++mf)
        #pragma unroll
        for (int nf = 0; nf < 8; ++nf)
            #pragma unroll
            for (int q = 0; q < 4; ++q) acc[mf][nf][q] = 0.f;

    #pragma unroll 1
    for (int cc = 0; cc < CIN/16; ++cc) {
        const int cb = cc * 16;

        // ---- stage A: packed u32 loads, PRMT hi/lo split ----
        for (int idx = t; idx < 8*HEL; idx += 256) {
            int cip = idx / HEL;           // ci pair 0..7
            int pix = idx - cip*HEL;
            int py  = pix / HC;
            int px  = pix - py*HC;
            int gy  = by0 + py - PAD;
            int gx  = bx0 + px - PAD;
            uint32_t va = 0, vb = 0;
            if (gy >= 0 && gy < H && gx >= 0 && gx < H) {
                size_t base = ((size_t)(b*CIN + cb + 2*cip)*H + gy)*H + gx;
                va = in_pk[base];
                vb = in_pk[base + (size_t)H*H];
            }
            int u = pix*8 + (((cip>>2) ^ ((pix>>2)&1)) << 2) + (cip & 3);
            Ahi[u] = __byte_perm(va, vb, 0x5410);
            Alo[u] = __byte_perm(va, vb, 0x7632);
        }
        // ---- stage W: single fp16 plane, contiguous [tap][co][ci] ----
        for (int idx = t; idx < KS2*64*8; idx += 256) {
            int cip = idx & 7;
            int r   = idx >> 3;            // tap*64 + co
            int co  = r & 63;
            int tap = r >> 6;
            size_t wb = (WPERB ? (size_t)b*COUT*CIN : 0)
                      + ((size_t)(tap*COUT + coT*64 + co)*CIN + cb + 2*cip);
            uint32_t wv = *(const uint32_t*)(wp + wb);   // 2 fp16 = 2 ci
            int u = r*8 + (((cip>>2) ^ ((co>>2)&1)) << 2) + (cip & 3);
            Wsh[u] = wv;
        }
        __syncthreads();

        #pragma unroll
        for (int tap = 0; tap < KS2; ++tap) {
            const int dy = tap / KS, dx = tap - dy*KS;

            uint32_t bh[8][2];
            #pragma unroll
            for (int nfp = 0; nfp < 4; ++nfp) {
                uint32_t ad = wBase + (uint32_t)(tap*2048) + boff[nfp];
                uint32_t tmp[4];
                ldsm_x4(tmp, ad);
                bh[2*nfp][0] = tmp[0]; bh[2*nfp+1][0] = tmp[1];
                bh[2*nfp][1] = tmp[2]; bh[2*nfp+1][1] = tmp[3];
            }
            #pragma unroll
            for (int mf = 0; mf < 2; ++mf) {
                const int pyb = (wid<<1) + mf + dy;
                const int pix = pyb*HC + dx + lt_lo*8 + lrow;
                uint32_t aoff = (uint32_t)(pix*32 + ((lt_h ^ ((pix>>2)&1)) << 4));
                uint32_t ah[4], al[4];
                ldsm_x4(ah, aHiBase + aoff);
                ldsm_x4(al, aHiBase + aoff + ASZ);
                #pragma unroll
                for (int nf = 0; nf < 8; ++nf) {
                    mma_f16(acc[mf][nf], ah, bh[nf]);
                    mma_f16(acc[mf][nf], al, bh[nf]);
                }
            }
        }
        __syncthreads();
    }

    // ---- epilogue ----
    #pragma unroll
    for (int mf = 0; mf < 2; ++mf) {
        const int gy  = by0 + (wid<<1) + mf;
        const int gx0 = bx0 + g;
        const int gx8 = gx0 + 8;
        float s0 = 1.f, s8 = 1.f;
        if (SAL) {
            s0 = sal[((size_t)b*H + gy)*H + gx0];
            s8 = sal[((size_t)b*H + gy)*H + gx8];
        }
        #pragma unroll
        for (int nf = 0; nf < 8; ++nf) {
            const int co = coT*64 + nf*8 + c0;
            size_t o0 = ((size_t)(b*COUT + co)*H + gy)*H + gx0;
            size_t o1 = o0 + (size_t)H*H;
            size_t o2 = ((size_t)(b*COUT + co)*H + gy)*H + gx8;
            size_t o3 = o2 + (size_t)H*H;
            float v0 = acc[mf][nf][0]*s0, v1 = acc[mf][nf][1]*s0;
            float v2 = acc[mf][nf][2]*s8, v3 = acc[mf][nf][3]*s8;
            if (RELU) {
                v0 = fmaxf(v0, 0.f); v1 = fmaxf(v1, 0.f);
                v2 = fmaxf(v2, 0.f); v3 = fmaxf(v3, 0.f);
            }
            if (ADD_OUT) { v0 += outf[o0]; v1 += outf[o1]; v2 += outf[o2]; v3 += outf[o3]; }
            if (OUTF32) { outf[o0] = v0; outf[o1] = v1; outf[o2] = v2; outf[o3] = v3; }
            if (OUTPK) {
                outpk[o0] = splitpack(v0); outpk[o1] = splitpack(v1);
                outpk[o2] = splitpack(v2); outpk[o3] = splitpack(v3);
            }
        }
    }
}

// ===========================================================================
// Scalar 1x1 conv GEMM — small residual 64x64 conv
// ===========================================================================
template<int COUT, int CIN, int HW>
__global__ __launch_bounds__(256)
void conv1x1_kernel(const float* __restrict__ in, const float* __restrict__ w,
                    float* out)
{
    __shared__ __align__(16) float sIn[16][128];
    __shared__ __align__(16) float sW [16][64];
    const int t  = threadIdx.x;
    const int tp = t & 31, tc = t >> 5;
    const int p0 = tp * 4, co0 = tc * 8;
    const int pBase  = blockIdx.x * 128;
    const int b      = blockIdx.y;
    const int coBase = blockIdx.z * 64;

    float acc[8][4];
    #pragma unroll
    for (int i = 0; i < 8; ++i) { acc[i][0]=acc[i][1]=acc[i][2]=acc[i][3]=0.f; }

    for (int kc = 0; kc < CIN / 16; ++kc) {
        const int kBase = kc * 16;
        #pragma unroll
        for (int i = t; i < 512; i += 256) {
            int k = i >> 5, x4 = i & 31;
            float4 v = *(const float4*)(in + (size_t)(b*CIN + kBase + k)*HW + pBase + x4*4);
            *(float4*)&sIn[k][x4*4] = v;
        }
        #pragma unroll
        for (int i = t; i < 1024; i += 256) {
            int co = i >> 4, k = i & 15;
            sW[k][co] = w[(size_t)(coBase + co)*CIN + kBase + k];
        }
        __syncthreads();
        #pragma unroll
        for (int k = 0; k < 16; ++k) {
            float4 v  = *(const float4*)&sIn[k][p0];
            float4 wl = *(const float4*)&sW[k][co0];
            float4 wh = *(const float4*)&sW[k][co0 + 4];
            float va[4] = {v.x, v.y, v.z, v.w};
            float wa[8] = {wl.x, wl.y, wl.z, wl.w, wh.x, wh.y, wh.z, wh.w};
            #pragma unroll
            for (int co = 0; co < 8; ++co)
                #pragma unroll
                for (int j = 0; j < 4; ++j)
                    acc[co][j] += wa[co] * va[j];
        }
        __syncthreads();
    }

    const int pg = pBase + p0;
    #pragma unroll
    for (int co = 0; co < 8; ++co) {
        size_t oi = (size_t)(b*COUT + coBase + co0 + co)*HW + pg;
        *(float4*)(out + oi) = make_float4(acc[co][0], acc[co][1], acc[co][2], acc[co][3]);
    }
}

// ===========================================================================
// Attention glue kernels
// ===========================================================================
__global__ void chanpool_kernel(const float* __restrict__ r2, float* __restrict__ pool)
{
    int p = blockIdx.x * 256 + threadIdx.x;
    int b = blockIdx.y;
    const float* base = r2 + (((size_t)b*512) << 14) + p;
    float mx = -3.4e38f, s = 0.f;
    #pragma unroll 8
    for (int c = 0; c < 512; ++c) {
        float v = base[(size_t)c << 14];
        mx = fmaxf(mx, v);
        s += v;
    }
    pool[(((size_t)(b*2    )) << 14) + p] = mx;
    pool[(((size_t)(b*2 + 1)) << 14) + p] = s * (1.f/512.f);
}

__global__ void salconv_kernel(const float* __restrict__ pool,
                               const float* __restrict__ wsal,
                               float* __restrict__ sal)
{
    int p = blockIdx.x * 256 + threadIdx.x;
    int b = blockIdx.y;
    int y = p >> 7, x = p & 127;
    float a = 0.f;
    #pragma unroll
    for (int c = 0; c < 2; ++c) {
        const float* pp = pool + (((size_t)(b*2 + c)) << 14);
        #pragma unroll
        for (int ky = 0; ky < 5; ++ky) {
            int iy = y + ky - 2;
            if (iy < 0 || iy >= 128) continue;
            #pragma unroll
            for (int kx = 0; kx < 5; ++kx) {
                int ix = x + kx - 2;
                if (ix < 0 || ix >= 128) continue;
                a += wsal[c*25 + ky*5 + kx] * pp[(iy << 7) + ix];
            }
        }
    }
    sal[(((size_t)b) << 14) + p] = 1.f / (1.f + expf(-a));
}

__global__ void wmean_kernel(const float* __restrict__ r2,
                             const float* __restrict__ sal,
                             float* __restrict__ m)
{
    int c = blockIdx.x, b = blockIdx.y;
    const float* r = r2 + (((size_t)(b*512 + c)) << 14);
    const float* s = sal + (((size_t)b) << 14);
    float sum = 0.f;
    for (int i = threadIdx.x; i < 4096; i += 256) {
        float4 rv = *(const float4*)(r + i*4);
        float4 sv = *(const float4*)(s + i*4);
        sum += rv.x*sv.x + rv.y*sv.y + rv.z*sv.z + rv.w*sv.w;
    }
    #pragma unroll
    for (int o = 16; o > 0; o >>= 1) sum += __shfl_xor_sync(0xffffffffu, sum, o);
    __shared__ float red[8];
    if ((threadIdx.x & 31) == 0) red[threadIdx.x >> 5] = sum;
    __syncthreads();
    if (threadIdx.x == 0) {
        float tot = 0.f;
        #pragma unroll
        for (int i = 0; i < 8; ++i) tot += red[i];
        m[b*512 + c] = tot * (1.f/16384.f);
    }
}

__global__ void calmlp_kernel(const float* __restrict__ m,
                              const float* __restrict__ wca1,
                              const float* __restrict__ wca2,
                              float* __restrict__ cal)
{
    int b = blockIdx.x;
    __shared__ float sm[512];
    __shared__ float sy1[32];
    for (int i = threadIdx.x; i < 512; i += 256) sm[i] = m[b*512 + i];
    __syncthreads();
    if (threadIdx.x < 32) {
        float a = 0.f;
        for (int c = 0; c < 512; ++c) a += wca1[threadIdx.x*512 + c] * sm[c];
        sy1[threadIdx.x] = fmaxf(a, 0.f);
    }
    __syncthreads();
    for (int c = threadIdx.x; c < 512; c += 256) {
        float a = 0.f;
        #pragma unroll
        for (int j = 0; j < 32; ++j) a += wca2[c*32 + j] * sy1[j];
        cal[b*512 + c] = 1.f / (1.f + expf(-a));
    }
}

// ===========================================================================
// K9: IBWT -> packed split output
// ===========================================================================
__global__ void ibwt_kernel(const float* __restrict__ r, uint32_t* __restrict__ opk)
{
    int idx = blockIdx.x * 256 + threadIdx.x;
    int j = idx & 127;
    int i = (idx >> 7) & 127;
    int c = (idx >> 14) & 63;
    int b = idx >> 20;
    size_t base = ((size_t)(b*512 + c) << 14) + (i << 7) + j;
    const size_t gs = (size_t)64 << 14;
    float x1 = r[base       ]*0.5f, x2 = r[base +   gs]*0.5f;
    float x3 = r[base + 2*gs]*0.5f, x4 = r[base + 3*gs]*0.5f;
    float x5 = r[base + 4*gs]*0.5f, x6 = r[base + 5*gs]*0.5f;
    float x7 = r[base + 6*gs]*0.5f, x8 = r[base + 7*gs]*0.5f;
    float a00 = x1 - x2 - x3 + x4 + x5 - x6 + x7 - x8;
    float a10 = x1 - x2 + x3 - x4 - x5 + x6 - x7 + x8;
    float a01 = x1 + x2 - x3 - x4 - x5 - x6 + x7 + x8;
    float a11 = x1 + x2 + x3 + x4 + x5 + x6 + x7 + x8;
    uint32_t* op = opk + ((size_t)(b*64 + c)*256 + 2*i)*256 + 2*j;
    op[0]   = splitpack(a00);  op[1]   = splitpack(a01);
    op[256] = splitpack(a10);  op[257] = splitpack(a11);
}

// ===========================================================================
// Launch
// ===========================================================================
extern "C" void kernel_launch(void* const* d_in, const int* in_sizes, int n_in,
                              void* d_out, int out_size)
{
    const float* x       = (const float*)d_in[0];
    const float* w_body1 = (const float*)d_in[1];
    const float* w_body2 = (const float*)d_in[2];
    const float* w_sal   = (const float*)d_in[3];
    const float* w_ca1   = (const float*)d_in[4];
    const float* w_ca2   = (const float*)d_in[5];
    const float* w_1x1   = (const float*)d_in[6];
    const float* w_3x3   = (const float*)d_in[7];
    const float* w_final = (const float*)d_in[8];
    float* out = (float*)d_out;

    float *bwt, *r2, *pool, *sal, *m, *cal;
    uint32_t *bwt_pk, *r1_pk, *r2_pk, *wv_pk;
    unsigned short *wp1, *wp2, *wp3, *wpc;
    cudaGetSymbolAddress((void**)&bwt,    g_bwt);
    cudaGetSymbolAddress((void**)&bwt_pk, g_bwt_pk);
    cudaGetSymbolAddress((void**)&r1_pk,  g_r1_pk);
    cudaGetSymbolAddress((void**)&r2,     g_r2);
    cudaGetSymbolAddress((void**)&r2_pk,  g_r2_pk);
    cudaGetSymbolAddress((void**)&wv_pk,  g_wv_pk);
    cudaGetSymbolAddress((void**)&pool,   g_pool);
    cudaGetSymbolAddress((void**)&sal,    g_sal);
    cudaGetSymbolAddress((void**)&m,      g_m);
    cudaGetSymbolAddress((void**)&cal,    g_cal);
    cudaGetSymbolAddress((void**)&wp1,    g_wp1);
    cudaGetSymbolAddress((void**)&wp2,    g_wp2);
    cudaGetSymbolAddress((void**)&wp3,    g_wp3);
    cudaGetSymbolAddress((void**)&wpc,    g_wpc);

    // smem: KS=3 -> 2*(18*18*32) + 9*64*32 = 39168 B ; KS=1 -> 16384+2048 = 18432 B
    constexpr int SM3 = 2*(18*18*32) + 9*64*32;
    constexpr int SM1 = 2*(16*16*32) + 64*32;
    cudaFuncSetAttribute(
        (const void*)mmaconv_kernel<512,64,128,3, true,false,false,false,false,true>,
        cudaFuncAttributeMaxDynamicSharedMemorySize, SM3);
    cudaFuncSetAttribute(
        (const void*)mmaconv_kernel<64,512,128,3, false,false,false,false,true,true>,
        cudaFuncAttributeMaxDynamicSharedMemorySize, SM3);
    cudaFuncSetAttribute(
        (const void*)mmaconv_kernel<512,512,128,1, false,true,true,true,true,false>,
        cudaFuncAttributeMaxDynamicSharedMemorySize, SM1);
    cudaFuncSetAttribute(
        (const void*)mmaconv_kernel<64,64,256,3, true,true,false,false,true,false>,
        cudaFuncAttributeMaxDynamicSharedMemorySize, SM3);

    // 0) weight prep (batch-independent)
    packw_kernel<<<(64*512*9 + 255)/256, 256>>>(w_body1, wp1, 64, 512, 9, 64*512*9);
    packw_kernel<<<(512*64*9 + 255)/256, 256>>>(w_body2, wp2, 512, 64, 9, 512*64*9);
    packw_kernel<<<(64*64*9  + 255)/256, 256>>>(w_3x3,   wp3, 64, 64, 9, 64*64*9);

    // 1) BWT (f32 + packed)
    bwt_kernel<<<16384, 256>>>(x, bwt, bwt_pk);
    // 2) body1 3x3 (512 -> 64) + relu -> r1 packed
    mmaconv_kernel<512,64,128,3, true,false,false,false,false,true>
        <<<dim3(8,8,4), 256, SM3>>>(bwt_pk, wp1, nullptr, nullptr, r1_pk);
    // 3) body2 3x3 (64 -> 512) -> r2 f32 + packed
    mmaconv_kernel<64,512,128,3, false,false,false,false,true,true>
        <<<dim3(8,8,32), 256, SM3>>>(r1_pk, wp2, nullptr, r2, r2_pk);
    // 4) channel pooling
    chanpool_kernel<<<dim3(64,4), 256>>>(r2, pool);
    // 5) 5x5 conv + sigmoid -> sal
    salconv_kernel<<<dim3(64,4), 256>>>(pool, w_sal, sal);
    // 6) weighted channel means
    wmean_kernel<<<dim3(512,4), 256>>>(r2, sal, m);
    // 7) channel attention MLP
    calmlp_kernel<<<4, 256>>>(m, w_ca1, w_ca2, cal);
    // 7b) 1x1 weights with cal folded (per batch)
    packwcal_kernel<<<(4*512*512)/256, 256>>>(w_1x1, cal, wpc);
    // 8) 1x1 conv (512->512): sal epilogue, += x_bwt (f32, in place)
    mmaconv_kernel<512,512,128,1, false,true,true,true,true,false>
        <<<dim3(8,8,32), 256, SM1>>>(r2_pk, wpc, sal, bwt, nullptr);
    // 9) IBWT -> packed wave
    ibwt_kernel<<<16384, 256>>>(bwt, wv_pk);
    // 10) residual 1x1 conv -> out (scalar f32)
    conv1x1_kernel<64, 64, 65536><<<dim3(512,4,1), 256>>>(x, w_final, out);
    // 11) final 3x3 conv (64->64) + relu, added onto out
    mmaconv_kernel<64,64,256,3, true,true,false,false,true,false>
        <<<dim3(16,16,4), 256, SM3>>>(wv_pk, wp3, nullptr, out, nullptr);
}

// round 9
// speedup vs baseline: 2.2891x; 1.5601x over previous
#include <cuda_runtime.h>
#include <cuda_fp16.h>
#include <math.h>
#include <stdint.h>

// ===========================================================================
// mma.sync m16n8k16 row.col fp16*fp16 -> f32 + ldmatrix + cp.async helpers
// ===========================================================================
__device__ __forceinline__ void mma_f16(float* c, const uint32_t* a, const uint32_t* b)
{
    asm volatile(
        "mma.sync.aligned.m16n8k16.row.col.f32.f16.f16.f32 "
        "{%0,%1,%2,%3}, {%4,%5,%6,%7}, {%8,%9}, {%0,%1,%2,%3};"
        : "+f"(c[0]), "+f"(c[1]), "+f"(c[2]), "+f"(c[3])
        : "r"(a[0]), "r"(a[1]), "r"(a[2]), "r"(a[3]), "r"(b[0]), "r"(b[1]));
}
__device__ __forceinline__ void ldsm_x4(uint32_t* r, uint32_t addr)
{
    asm volatile(
        "ldmatrix.sync.aligned.m8n8.x4.shared.b16 {%0,%1,%2,%3}, [%4];"
        : "=r"(r[0]), "=r"(r[1]), "=r"(r[2]), "=r"(r[3]) : "r"(addr));
}
__device__ __forceinline__ void cp16(uint32_t dst, const void* src)
{
    asm volatile("cp.async.cg.shared.global [%0], [%1], 16;" :: "r"(dst), "l"(src));
}
#define CP_COMMIT asm volatile("cp.async.commit_group;" ::: "memory")
#define CP_WAIT1  asm volatile("cp.async.wait_group 1;" ::: "memory")
#define CP_WAIT0  asm volatile("cp.async.wait_group 0;" ::: "memory")

// split f32 into (hi fp16 | lo fp16 << 16)
__device__ __forceinline__ uint32_t splitpack(float v)
{
    __half h = __float2half_rn(v);
    __half l = __float2half_rn(v - __half2float(h));
    return ((uint32_t)__half_as_ushort(l) << 16) | __half_as_ushort(h);
}
__device__ __forceinline__ uint32_t packhalf2(float lo, float hi)
{
    return ((uint32_t)__half_as_ushort(__float2half_rn(hi)) << 16)
         | __half_as_ushort(__float2half_rn(lo));
}

// ===========================================================================
// Scratch buffers
// ===========================================================================
__device__ float g_bwt [(size_t)4*512*128*128];   // f32 NCHW (for += x_bwt, ibwt)
__device__ uint2 g_bwt_pk[(size_t)4*256*128*128]; // [b][ci/2][px] packed fp16 hi/lo pairs
__device__ uint2 g_r1_pk [(size_t)4*32*128*128];
__device__ float g_r2  [(size_t)4*512*128*128];
__device__ uint2 g_r2_pk [(size_t)4*256*128*128];
__device__ uint2 g_wv_pk [(size_t)4*32*256*256];
__device__ float g_pool[(size_t)4*2*128*128];
__device__ float g_sal [(size_t)4*128*128];
__device__ float g_m   [4*512];
__device__ float g_cal [4*512];
// weight images: exact smem layout, [coT][cc][tap*512 + co*8 + swz(pos)]
__device__ uint32_t g_wi1[32*9*512];               // body1 (coT=1, cc=32)
__device__ uint32_t g_wi2[8*4*9*512];              // body2 (coT=8, cc=4)
__device__ uint32_t g_wi3[4*9*512];                // final 3x3 (coT=1, cc=4)
__device__ uint32_t g_wic[(size_t)4*8*32*512];     // 1x1 * cal, per batch

// ===========================================================================
// Weight prep: f32 [CO][CI][KS2] -> swizzled smem-image u32
// ===========================================================================
__global__ void packw_img(const float* __restrict__ w, uint32_t* __restrict__ wp,
                          int CO, int CI, int KS2, int total)
{
    int i = blockIdx.x*256 + threadIdx.x;
    if (i >= total) return;
    int chunkU = KS2*512;
    int perCoT = (CI/16)*chunkU;
    int coT = i / perCoT;
    int rem = i - coT*perCoT;
    int cc  = rem / chunkU;
    int u   = rem - cc*chunkU;
    int tap = u >> 9;
    int r   = u & 511;
    int co  = r >> 3, pos = r & 7;
    int xb  = (co>>2)&1;
    int cip = ((((pos>>2)^xb)<<2) | (pos&3));
    int ci  = cc*16 + 2*cip;
    int cog = coT*64 + co;
    wp[i] = packhalf2(w[((size_t)cog*CI + ci)*KS2 + tap],
                      w[((size_t)cog*CI + ci+1)*KS2 + tap]);
}
// 1x1 weights with cal folded, per batch
__global__ void packwcal_img(const float* __restrict__ w, const float* __restrict__ cal,
                             uint32_t* __restrict__ wp)
{
    int i = blockIdx.x*256 + threadIdx.x;   // 4*131072
    int b = i >> 17;
    int rem = i & 131071;
    int coT = rem >> 14;
    int rem2 = rem & 16383;
    int cc  = rem2 >> 9;
    int u   = rem2 & 511;
    int co  = u >> 3, pos = u & 7;
    int xb  = (co>>2)&1;
    int cip = ((((pos>>2)^xb)<<2) | (pos&3));
    int ci  = cc*16 + 2*cip;
    int cog = coT*64 + co;
    wp[i] = packhalf2(w[cog*512 + ci]   * cal[b*512 + ci],
                      w[cog*512 + ci+1] * cal[b*512 + ci+1]);
}

// ===========================================================================
// K1: BWT  x(4,64,256,256) -> f32 NCHW + uint2 channel-pair packed
// thread = (b, cp 0..31, i, j): channels 2cp, 2cp+1
// ===========================================================================
__global__ void bwt_kernel(const float* __restrict__ x, float* __restrict__ o,
                           uint2* __restrict__ opk)
{
    int idx = blockIdx.x * 256 + threadIdx.x;   // 4*32*128*128 / 256 = 8192 blocks
    int j  = idx & 127;
    int i  = (idx >> 7) & 127;
    int cp = (idx >> 14) & 31;
    int b  = idx >> 19;
    const float* xp0 = x + ((size_t)(b*64 + 2*cp)*256 + 2*i)*256 + 2*j;
    const float* xp1 = xp0 + 65536;
    float2 r0 = *(const float2*)xp0, r1 = *(const float2*)(xp0 + 256);
    float2 s0 = *(const float2*)xp1, s1 = *(const float2*)(xp1 + 256);
    float a1 = r0.x*0.5f, a3 = r0.y*0.5f, a2 = r1.x*0.5f, a4 = r1.y*0.5f;
    float b1 = s0.x*0.5f, b3 = s0.y*0.5f, b2 = s1.x*0.5f, b4 = s1.y*0.5f;
    int p = (i << 7) + j;
    size_t obF = ((size_t)(b*512 + 2*cp) << 14) + p;
    size_t obP = ((size_t)(b*256 + cp)  << 14) + p;
    const size_t gsF = (size_t)64 << 14;
    const size_t gsP = (size_t)32 << 14;
    float va, vb;
#define BWT_EMIT(k, s1_, s2_, s3_, s4_) \
    va = s1_ a1 s2_ a2 s3_ a3 s4_ a4; \
    vb = s1_ b1 s2_ b2 s3_ b3 s4_ b4; \
    o[obF + k*gsF] = va; o[obF + k*gsF + 16384] = vb; \
    opk[obP + k*gsP] = make_uint2(splitpack(va), splitpack(vb));
    BWT_EMIT(0, +, +, +, +)
    BWT_EMIT(1, -, -, +, +)
    BWT_EMIT(2, -, +, -, +)
    BWT_EMIT(3, +, -, -, +)
    BWT_EMIT(4, +, +, -, -)
    BWT_EMIT(5, -, +, +, -)
    BWT_EMIT(6, +, -, +, -)
    BWT_EMIT(7, -, -, -, -)
#undef BWT_EMIT
}

// ===========================================================================
// Implicit-GEMM conv, fp16 2-term split, fully pipelined:
//   W: pre-swizzled gmem image staged via cp.async (double-buffered)
//   A: uint2 LDG.64 -> register prefetch -> PRMT split -> STS (double-buffered)
// CTA: 256 thr / 8 warps, 16x16 px x 64 co; warp m32 x n64.
// ===========================================================================
template<int CIN, int COUT, int H, int KS,
         bool RELU, bool ADD_OUT, bool SAL, bool WPERB, bool OUTF32, bool OUTPK>
__global__ __launch_bounds__(256)
void mmaconv_kernel(const uint2* __restrict__ in_pk,
                    const uint32_t* __restrict__ wimg,
                    const float* __restrict__ sal,
                    float* outf, uint2* __restrict__ outpk)
{
    constexpr int KS2  = KS*KS;
    constexpr int PAD  = KS/2;
    constexpr int HC   = 16 + KS - 1;
    constexpr int HEL  = HC*HC;
    constexpr int ASTG = HEL*32;          // bytes per A plane (hi or lo)
    constexpr int WCH  = KS2*2048;        // bytes per W chunk
    constexpr int NC   = CIN/16;
    constexpr int NA   = (8*HEL + 255)/256;
    constexpr int NG   = KS2*128;         // 16B granules per W chunk
    constexpr int HW   = H*H;

    extern __shared__ __align__(16) char smem[];
    const uint32_t smemBase = (uint32_t)__cvta_generic_to_shared(smem);
    const uint32_t wSmem    = smemBase + 4*ASTG;

    const int t    = threadIdx.x;
    const int lane = t & 31, wid = t >> 5;
    const int g    = lane >> 2;
    const int c0   = (lane & 3) * 2;
    const int bx0  = blockIdx.x * 16;
    const int by0  = blockIdx.y * 16;
    const int z    = blockIdx.z;
    const int coT  = z % (COUT/64);
    const int b    = z / (COUT/64);

    const int ltile = lane >> 3, lrow = lane & 7;
    const int lt_lo = ltile & 1;
    const int lt_h  = ltile >> 1;

    uint32_t boff[4];
    #pragma unroll
    for (int nfp = 0; nfp < 4; ++nfp) {
        int cr = nfp*16 + lt_lo*8 + lrow;
        boff[nfp] = (uint32_t)(cr*32 + ((lt_h ^ ((cr>>2)&1)) << 4));
    }

    const size_t bciHW = (size_t)(b*(CIN/2))*HW;
    const uint32_t* wChunk0 = wimg
        + (WPERB ? (size_t)b*(COUT/64)*NC*KS2*512 : 0)
        + (size_t)coT*NC*KS2*512;

    float acc[2][8][4];
    #pragma unroll
    for (int mf = 0; mf < 2; ++mf)
        #pragma unroll
        for (int nf = 0; nf < 8; ++nf)
            #pragma unroll
            for (int q = 0; q < 4; ++q) acc[mf][nf][q] = 0.f;

    uint2 av[NA];

    auto loadA = [&](int cc) {
        #pragma unroll
        for (int k = 0; k < NA; ++k) {
            int idx = t + k*256;
            uint2 v = make_uint2(0u, 0u);
            if ((8*HEL) % 256 == 0 || idx < 8*HEL) {
                int cip = idx / HEL;
                int pix = idx - cip*HEL;
                int py  = pix / HC, px = pix - py*HC;
                int gy  = by0 + py - PAD, gx = bx0 + px - PAD;
                if (gy >= 0 && gy < H && gx >= 0 && gx < H)
                    v = in_pk[bciHW + (size_t)(cc*8 + cip)*HW + gy*H + gx];
            }
            av[k] = v;
        }
    };
    auto stsA = [&](int s) {
        uint32_t* AH = (uint32_t*)(smem + s*2*ASTG);
        uint32_t* AL = (uint32_t*)(smem + s*2*ASTG + ASTG);
        #pragma unroll
        for (int k = 0; k < NA; ++k) {
            int idx = t + k*256;
            if ((8*HEL) % 256 == 0 || idx < 8*HEL) {
                int cip = idx / HEL;
                int pix = idx - cip*HEL;
                int u = pix*8 + ((((cip>>2) ^ ((pix>>2)&1)) << 2) | (cip & 3));
                AH[u] = __byte_perm(av[k].x, av[k].y, 0x5410);
                AL[u] = __byte_perm(av[k].x, av[k].y, 0x7632);
            }
        }
    };
    auto cpW = [&](int cc) {
        const uint32_t* src = wChunk0 + (size_t)cc*KS2*512;
        uint32_t dst = wSmem + (cc & 1)*WCH;
        #pragma unroll
        for (int k = t; k < NG; k += 256)
            cp16(dst + k*16, src + k*4);
        CP_COMMIT;
    };
    auto compute = [&](int s) {
        const uint32_t aHi = smemBase + s*(2*ASTG);
        const uint32_t wB  = wSmem + s*WCH;
        #pragma unroll
        for (int tap = 0; tap < KS2; ++tap) {
            const int dy = tap / KS, dx = tap - dy*KS;
            uint32_t bh[8][2];
            #pragma unroll
            for (int nfp = 0; nfp < 4; ++nfp) {
                uint32_t tmp[4];
                ldsm_x4(tmp, wB + (uint32_t)(tap*2048) + boff[nfp]);
                bh[2*nfp][0] = tmp[0]; bh[2*nfp+1][0] = tmp[1];
                bh[2*nfp][1] = tmp[2]; bh[2*nfp+1][1] = tmp[3];
            }
            #pragma unroll
            for (int mf = 0; mf < 2; ++mf) {
                const int pyb = (wid << 1) + mf + dy;
                const int pix = pyb*HC + dx + lt_lo*8 + lrow;
                uint32_t aoff = (uint32_t)(pix*32 + ((lt_h ^ ((pix>>2)&1)) << 4));
                uint32_t ah[4], al[4];
                ldsm_x4(ah, aHi + aoff);
                ldsm_x4(al, aHi + ASTG + aoff);
                #pragma unroll
                for (int nf = 0; nf < 8; ++nf) {
                    mma_f16(acc[mf][nf], ah, bh[nf]);
                    mma_f16(acc[mf][nf], al, bh[nf]);
                }
            }
        }
    };

    // ---- pipelined chunk loop ----
    loadA(0); cpW(0);
    stsA(0);
    loadA(1); cpW(1);
    CP_WAIT1;
    __syncthreads();
    #pragma unroll 1
    for (int cc = 0; cc < NC; ++cc) {
        compute(cc & 1);
        if (cc + 1 < NC) {
            __syncthreads();
            stsA((cc + 1) & 1);
            if (cc + 2 < NC) { loadA(cc + 2); cpW(cc + 2); CP_WAIT1; }
            else             { CP_WAIT0; }
            __syncthreads();
        }
    }

    // ---- epilogue ----
    #pragma unroll
    for (int mf = 0; mf < 2; ++mf) {
        const int gy  = by0 + (wid << 1) + mf;
        const int gx0 = bx0 + g;
        const int gx8 = gx0 + 8;
        float s0 = 1.f, s8 = 1.f;
        if (SAL) {
            s0 = sal[((size_t)b*H + gy)*H + gx0];
            s8 = sal[((size_t)b*H + gy)*H + gx8];
        }
        #pragma unroll
        for (int nf = 0; nf < 8; ++nf) {
            const int co = coT*64 + nf*8 + c0;
            size_t o0 = ((size_t)(b*COUT + co)*H + gy)*H + gx0;
            size_t o1 = o0 + (size_t)H*H;
            size_t o2 = ((size_t)(b*COUT + co)*H + gy)*H + gx8;
            size_t o3 = o2 + (size_t)H*H;
            float v0 = acc[mf][nf][0]*s0, v1 = acc[mf][nf][1]*s0;
            float v2 = acc[mf][nf][2]*s8, v3 = acc[mf][nf][3]*s8;
            if (RELU) {
                v0 = fmaxf(v0, 0.f); v1 = fmaxf(v1, 0.f);
                v2 = fmaxf(v2, 0.f); v3 = fmaxf(v3, 0.f);
            }
            if (ADD_OUT) { v0 += outf[o0]; v1 += outf[o1]; v2 += outf[o2]; v3 += outf[o3]; }
            if (OUTF32) { outf[o0] = v0; outf[o1] = v1; outf[o2] = v2; outf[o3] = v3; }
            if (OUTPK) {
                const int cip = co >> 1;
                size_t pbase = ((size_t)(b*(COUT/2) + cip))*H*H + (size_t)gy*H;
                outpk[pbase + gx0] = make_uint2(splitpack(v0), splitpack(v1));
                outpk[pbase + gx8] = make_uint2(splitpack(v2), splitpack(v3));
            }
        }
    }
}

// ===========================================================================
// Scalar 1x1 conv GEMM — small residual 64x64 conv
// ===========================================================================
template<int COUT, int CIN, int HW>
__global__ __launch_bounds__(256)
void conv1x1_kernel(const float* __restrict__ in, const float* __restrict__ w,
                    float* out)
{
    __shared__ __align__(16) float sIn[16][128];
    __shared__ __align__(16) float sW [16][64];
    const int t  = threadIdx.x;
    const int tp = t & 31, tc = t >> 5;
    const int p0 = tp * 4, co0 = tc * 8;
    const int pBase  = blockIdx.x * 128;
    const int b      = blockIdx.y;
    const int coBase = blockIdx.z * 64;

    float acc[8][4];
    #pragma unroll
    for (int i = 0; i < 8; ++i) { acc[i][0]=acc[i][1]=acc[i][2]=acc[i][3]=0.f; }

    for (int kc = 0; kc < CIN / 16; ++kc) {
        const int kBase = kc * 16;
        #pragma unroll
        for (int i = t; i < 512; i += 256) {
            int k = i >> 5, x4 = i & 31;
            float4 v = *(const float4*)(in + (size_t)(b*CIN + kBase + k)*HW + pBase + x4*4);
            *(float4*)&sIn[k][x4*4] = v;
        }
        #pragma unroll
        for (int i = t; i < 1024; i += 256) {
            int co = i >> 4, k = i & 15;
            sW[k][co] = w[(size_t)(coBase + co)*CIN + kBase + k];
        }
        __syncthreads();
        #pragma unroll
        for (int k = 0; k < 16; ++k) {
            float4 v  = *(const float4*)&sIn[k][p0];
            float4 wl = *(const float4*)&sW[k][co0];
            float4 wh = *(const float4*)&sW[k][co0 + 4];
            float va[4] = {v.x, v.y, v.z, v.w};
            float wa[8] = {wl.x, wl.y, wl.z, wl.w, wh.x, wh.y, wh.z, wh.w};
            #pragma unroll
            for (int co = 0; co < 8; ++co)
                #pragma unroll
                for (int j = 0; j < 4; ++j)
                    acc[co][j] += wa[co] * va[j];
        }
        __syncthreads();
    }

    const int pg = pBase + p0;
    #pragma unroll
    for (int co = 0; co < 8; ++co) {
        size_t oi = (size_t)(b*COUT + coBase + co0 + co)*HW + pg;
        *(float4*)(out + oi) = make_float4(acc[co][0], acc[co][1], acc[co][2], acc[co][3]);
    }
}

// ===========================================================================
// Attention glue kernels
// ===========================================================================
__global__ void chanpool_kernel(const float* __restrict__ r2, float* __restrict__ pool)
{
    int p = blockIdx.x * 256 + threadIdx.x;
    int b = blockIdx.y;
    const float* base = r2 + (((size_t)b*512) << 14) + p;
    float mx = -3.4e38f, s = 0.f;
    #pragma unroll 8
    for (int c = 0; c < 512; ++c) {
        float v = base[(size_t)c << 14];
        mx = fmaxf(mx, v);
        s += v;
    }
    pool[(((size_t)(b*2    )) << 14) + p] = mx;
    pool[(((size_t)(b*2 + 1)) << 14) + p] = s * (1.f/512.f);
}

__global__ void salconv_kernel(const float* __restrict__ pool,
                               const float* __restrict__ wsal,
                               float* __restrict__ sal)
{
    int p = blockIdx.x * 256 + threadIdx.x;
    int b = blockIdx.y;
    int y = p >> 7, x = p & 127;
    float a = 0.f;
    #pragma unroll
    for (int c = 0; c < 2; ++c) {
        const float* pp = pool + (((size_t)(b*2 + c)) << 14);
        #pragma unroll
        for (int ky = 0; ky < 5; ++ky) {
            int iy = y + ky - 2;
            if (iy < 0 || iy >= 128) continue;
            #pragma unroll
            for (int kx = 0; kx < 5; ++kx) {
                int ix = x + kx - 2;
                if (ix < 0 || ix >= 128) continue;
                a += wsal[c*25 + ky*5 + kx] * pp[(iy << 7) + ix];
            }
        }
    }
    sal[(((size_t)b) << 14) + p] = 1.f / (1.f + expf(-a));
}

__global__ void wmean_kernel(const float* __restrict__ r2,
                             const float* __restrict__ sal,
                             float* __restrict__ m)
{
    int c = blockIdx.x, b = blockIdx.y;
    const float* r = r2 + (((size_t)(b*512 + c)) << 14);
    const float* s = sal + (((size_t)b) << 14);
    float sum = 0.f;
    for (int i = threadIdx.x; i < 4096; i += 256) {
        float4 rv = *(const float4*)(r + i*4);
        float4 sv = *(const float4*)(s + i*4);
        sum += rv.x*sv.x + rv.y*sv.y + rv.z*sv.z + rv.w*sv.w;
    }
    #pragma unroll
    for (int o = 16; o > 0; o >>= 1) sum += __shfl_xor_sync(0xffffffffu, sum, o);
    __shared__ float red[8];
    if ((threadIdx.x & 31) == 0) red[threadIdx.x >> 5] = sum;
    __syncthreads();
    if (threadIdx.x == 0) {
        float tot = 0.f;
        #pragma unroll
        for (int i = 0; i < 8; ++i) tot += red[i];
        m[b*512 + c] = tot * (1.f/16384.f);
    }
}

__global__ void calmlp_kernel(const float* __restrict__ m,
                              const float* __restrict__ wca1,
                              const float* __restrict__ wca2,
                              float* __restrict__ cal)
{
    int b = blockIdx.x;
    __shared__ float sm[512];
    __shared__ float sy1[32];
    for (int i = threadIdx.x; i < 512; i += 256) sm[i] = m[b*512 + i];
    __syncthreads();
    if (threadIdx.x < 32) {
        float a = 0.f;
        for (int c = 0; c < 512; ++c) a += wca1[threadIdx.x*512 + c] * sm[c];
        sy1[threadIdx.x] = fmaxf(a, 0.f);
    }
    __syncthreads();
    for (int c = threadIdx.x; c < 512; c += 256) {
        float a = 0.f;
        #pragma unroll
        for (int j = 0; j < 32; ++j) a += wca2[c*32 + j] * sy1[j];
        cal[b*512 + c] = 1.f / (1.f + expf(-a));
    }
}

// ===========================================================================
// K9: IBWT -> uint2 channel-pair packed output (2 channels per thread)
// ===========================================================================
__global__ void ibwt_kernel(const float* __restrict__ r, uint2* __restrict__ opk)
{
    int idx = blockIdx.x * 256 + threadIdx.x;   // 4*32*128*128 / 256 = 8192 blocks
    int j  = idx & 127;
    int i  = (idx >> 7) & 127;
    int cp = (idx >> 14) & 31;
    int b  = idx >> 19;
    size_t base = ((size_t)(b*512 + 2*cp) << 14) + (i << 7) + j;
    const size_t gs = (size_t)64 << 14;
    float p1 = r[base       ]*0.5f, p2 = r[base +   gs]*0.5f;
    float p3 = r[base + 2*gs]*0.5f, p4 = r[base + 3*gs]*0.5f;
    float p5 = r[base + 4*gs]*0.5f, p6 = r[base + 5*gs]*0.5f;
    float p7 = r[base + 6*gs]*0.5f, p8 = r[base + 7*gs]*0.5f;
    float q1 = r[base + 16384       ]*0.5f, q2 = r[base + 16384 +   gs]*0.5f;
    float q3 = r[base + 16384 + 2*gs]*0.5f, q4 = r[base + 16384 + 3*gs]*0.5f;
    float q5 = r[base + 16384 + 4*gs]*0.5f, q6 = r[base + 16384 + 5*gs]*0.5f;
    float q7 = r[base + 16384 + 6*gs]*0.5f, q8 = r[base + 16384 + 7*gs]*0.5f;
    float a00p = p1 - p2 - p3 + p4 + p5 - p6 + p7 - p8;
    float a10p = p1 - p2 + p3 - p4 - p5 + p6 - p7 + p8;
    float a01p = p1 + p2 - p3 - p4 - p5 - p6 + p7 + p8;
    float a11p = p1 + p2 + p3 + p4 + p5 + p6 + p7 + p8;
    float a00q = q1 - q2 - q3 + q4 + q5 - q6 + q7 - q8;
    float a10q = q1 - q2 + q3 - q4 - q5 + q6 - q7 + q8;
    float a01q = q1 + q2 - q3 - q4 - q5 - q6 + q7 + q8;
    float a11q = q1 + q2 + q3 + q4 + q5 + q6 + q7 + q8;
    size_t off = ((size_t)(b*32 + cp) << 16) + ((size_t)(2*i))*256 + 2*j;
    opk[off      ] = make_uint2(splitpack(a00p), splitpack(a00q));
    opk[off + 1  ] = make_uint2(splitpack(a01p), splitpack(a01q));
    opk[off + 256] = make_uint2(splitpack(a10p), splitpack(a10q));
    opk[off + 257] = make_uint2(splitpack(a11p), splitpack(a11q));
}

// ===========================================================================
// Launch
// ===========================================================================
extern "C" void kernel_launch(void* const* d_in, const int* in_sizes, int n_in,
                              void* d_out, int out_size)
{
    const float* x       = (const float*)d_in[0];
    const float* w_body1 = (const float*)d_in[1];
    const float* w_body2 = (const float*)d_in[2];
    const float* w_sal   = (const float*)d_in[3];
    const float* w_ca1   = (const float*)d_in[4];
    const float* w_ca2   = (const float*)d_in[5];
    const float* w_1x1   = (const float*)d_in[6];
    const float* w_3x3   = (const float*)d_in[7];
    const float* w_final = (const float*)d_in[8];
    float* out = (float*)d_out;

    float *bwt, *r2, *pool, *sal, *m, *cal;
    uint2 *bwt_pk, *r1_pk, *r2_pk, *wv_pk;
    uint32_t *wi1, *wi2, *wi3, *wic;
    cudaGetSymbolAddress((void**)&bwt,    g_bwt);
    cudaGetSymbolAddress((void**)&bwt_pk, g_bwt_pk);
    cudaGetSymbolAddress((void**)&r1_pk,  g_r1_pk);
    cudaGetSymbolAddress((void**)&r2,     g_r2);
    cudaGetSymbolAddress((void**)&r2_pk,  g_r2_pk);
    cudaGetSymbolAddress((void**)&wv_pk,  g_wv_pk);
    cudaGetSymbolAddress((void**)&pool,   g_pool);
    cudaGetSymbolAddress((void**)&sal,    g_sal);
    cudaGetSymbolAddress((void**)&m,      g_m);
    cudaGetSymbolAddress((void**)&cal,    g_cal);
    cudaGetSymbolAddress((void**)&wi1,    g_wi1);
    cudaGetSymbolAddress((void**)&wi2,    g_wi2);
    cudaGetSymbolAddress((void**)&wi3,    g_wi3);
    cudaGetSymbolAddress((void**)&wic,    g_wic);

    // smem: KS=3 -> 4*(18*18*32) + 2*9*2048 = 41472 + 36864 = 78336
    //       KS=1 -> 4*(16*16*32) + 2*2048   = 32768 + 4096  = 36864
    constexpr int SM3 = 4*(18*18*32) + 2*9*2048;
    constexpr int SM1 = 4*(16*16*32) + 2*2048;
    cudaFuncSetAttribute(
        (const void*)mmaconv_kernel<512,64,128,3, true,false,false,false,false,true>,
        cudaFuncAttributeMaxDynamicSharedMemorySize, SM3);
    cudaFuncSetAttribute(
        (const void*)mmaconv_kernel<64,512,128,3, false,false,false,false,true,true>,
        cudaFuncAttributeMaxDynamicSharedMemorySize, SM3);
    cudaFuncSetAttribute(
        (const void*)mmaconv_kernel<512,512,128,1, false,true,true,true,true,false>,
        cudaFuncAttributeMaxDynamicSharedMemorySize, SM1);
    cudaFuncSetAttribute(
        (const void*)mmaconv_kernel<64,64,256,3, true,true,false,false,true,false>,
        cudaFuncAttributeMaxDynamicSharedMemorySize, SM3);

    // 0) weight prep (batch-independent)
    packw_img<<<(32*9*512 + 255)/256, 256>>>(w_body1, wi1, 64, 512, 9, 32*9*512);
    packw_img<<<(8*4*9*512 + 255)/256, 256>>>(w_body2, wi2, 512, 64, 9, 8*4*9*512);
    packw_img<<<(4*9*512 + 255)/256, 256>>>(w_3x3, wi3, 64, 64, 9, 4*9*512);

    // 1) BWT (f32 + packed pairs)
    bwt_kernel<<<8192, 256>>>(x, bwt, bwt_pk);
    // 2) body1 3x3 (512 -> 64) + relu -> r1 packed
    mmaconv_kernel<512,64,128,3, true,false,false,false,false,true>
        <<<dim3(8,8,4), 256, SM3>>>(bwt_pk, wi1, nullptr, nullptr, r1_pk);
    // 3) body2 3x3 (64 -> 512) -> r2 f32 + packed
    mmaconv_kernel<64,512,128,3, false,false,false,false,true,true>
        <<<dim3(8,8,32), 256, SM3>>>(r1_pk, wi2, nullptr, r2, r2_pk);
    // 4) channel pooling
    chanpool_kernel<<<dim3(64,4), 256>>>(r2, pool);
    // 5) 5x5 conv + sigmoid -> sal
    salconv_kernel<<<dim3(64,4), 256>>>(pool, w_sal, sal);
    // 6) weighted channel means
    wmean_kernel<<<dim3(512,4), 256>>>(r2, sal, m);
    // 7) channel attention MLP
    calmlp_kernel<<<4, 256>>>(m, w_ca1, w_ca2, cal);
    // 7b) 1x1 weights with cal folded (per batch), swizzled image
    packwcal_img<<<(4*8*32*512)/256, 256>>>(w_1x1, cal, wic);
    // 8) 1x1 conv (512->512): sal epilogue, += x_bwt (f32, in place)
    mmaconv_kernel<512,512,128,1, false,true,true,true,true,false>
        <<<dim3(8,8,32), 256, SM1>>>(r2_pk, wic, sal, bwt, nullptr);
    // 9) IBWT -> packed wave
    ibwt_kernel<<<8192, 256>>>(bwt, wv_pk);
    // 10) residual 1x1 conv -> out (scalar f32)
    conv1x1_kernel<64, 64, 65536><<<dim3(512,4,1), 256>>>(x, w_final, out);
    // 11) final 3x3 conv (64->64) + relu, added onto out
    mmaconv_kernel<64,64,256,3, true,true,false,false,true,false>
        <<<dim3(16,16,4), 256, SM3>>>(wv_pk, wi3, nullptr, out, nullptr);
}

// round 10
// speedup vs baseline: 3.2221x; 1.4076x over previous
#include <cuda_runtime.h>
#include <cuda_fp16.h>
#include <math.h>
#include <stdint.h>

// ===========================================================================
// mma.sync m16n8k16 row.col fp16*fp16 -> f32 + ldmatrix + cp.async helpers
// ===========================================================================
__device__ __forceinline__ void mma_f16(float* c, const uint32_t* a, const uint32_t* b)
{
    asm volatile(
        "mma.sync.aligned.m16n8k16.row.col.f32.f16.f16.f32 "
        "{%0,%1,%2,%3}, {%4,%5,%6,%7}, {%8,%9}, {%0,%1,%2,%3};"
        : "+f"(c[0]), "+f"(c[1]), "+f"(c[2]), "+f"(c[3])
        : "r"(a[0]), "r"(a[1]), "r"(a[2]), "r"(a[3]), "r"(b[0]), "r"(b[1]));
}
__device__ __forceinline__ void ldsm_x4(uint32_t* r, uint32_t addr)
{
    asm volatile(
        "ldmatrix.sync.aligned.m8n8.x4.shared.b16 {%0,%1,%2,%3}, [%4];"
        : "=r"(r[0]), "=r"(r[1]), "=r"(r[2]), "=r"(r[3]) : "r"(addr));
}
__device__ __forceinline__ void cp16(uint32_t dst, const void* src)
{
    asm volatile("cp.async.cg.shared.global [%0], [%1], 16;" :: "r"(dst), "l"(src));
}
#define CP_COMMIT asm volatile("cp.async.commit_group;" ::: "memory")
#define CP_WAIT1  asm volatile("cp.async.wait_group 1;" ::: "memory")

// pack two channels' fp16 into one u32: half(c0) | half(c1)<<16
__device__ __forceinline__ uint32_t packhalf2(float c0, float c1)
{
    return ((uint32_t)__half_as_ushort(__float2half_rn(c1)) << 16)
         | __half_as_ushort(__float2half_rn(c0));
}

// ===========================================================================
// Scratch buffers
// ===========================================================================
__device__ float    g_bwt   [(size_t)4*512*128*128]; // f32 NCHW (conv8 +=, ibwt in)
__device__ uint32_t g_bwt_hp[(size_t)4*256*128*128]; // hi-pair fp16 [b][ch/2][px]
__device__ uint32_t g_r1_hp [(size_t)4*32*128*128];
__device__ float    g_r2    [(size_t)4*512*128*128];
__device__ uint32_t g_r2_hp [(size_t)4*256*128*128];
__device__ uint32_t g_wv_hp [(size_t)4*32*256*256];
__device__ float    g_pool  [(size_t)4*2*128*128];
__device__ float    g_sal   [(size_t)4*128*128];
__device__ float    g_m     [4*512];
__device__ float    g_cal   [4*512];
// weight images: exact smem layout, [coT][cc][tap*512 + co*8 + swz(pos)]
__device__ uint32_t g_wi1[32*9*512];
__device__ uint32_t g_wi2[8*4*9*512];
__device__ uint32_t g_wi3[4*9*512];
__device__ uint32_t g_wic[(size_t)4*8*32*512];

// ===========================================================================
// Weight prep: f32 [CO][CI][KS2] -> swizzled smem-image u32 (fp16 ci-pairs)
// ===========================================================================
__global__ void packw_img(const float* __restrict__ w, uint32_t* __restrict__ wp,
                          int CO, int CI, int KS2, int total)
{
    int i = blockIdx.x*256 + threadIdx.x;
    if (i >= total) return;
    int chunkU = KS2*512;
    int perCoT = (CI/16)*chunkU;
    int coT = i / perCoT;
    int rem = i - coT*perCoT;
    int cc  = rem / chunkU;
    int u   = rem - cc*chunkU;
    int tap = u >> 9;
    int r   = u & 511;
    int co  = r >> 3, pos = r & 7;
    int xb  = (co>>2)&1;
    int cip = ((((pos>>2)^xb)<<2) | (pos&3));
    int ci  = cc*16 + 2*cip;
    int cog = coT*64 + co;
    wp[i] = packhalf2(w[((size_t)cog*CI + ci)*KS2 + tap],
                      w[((size_t)cog*CI + ci+1)*KS2 + tap]);
}
__global__ void packwcal_img(const float* __restrict__ w, const float* __restrict__ cal,
                             uint32_t* __restrict__ wp)
{
    int i = blockIdx.x*256 + threadIdx.x;   // 4*131072
    int b = i >> 17;
    int rem = i & 131071;
    int coT = rem >> 14;
    int rem2 = rem & 16383;
    int cc  = rem2 >> 9;
    int u   = rem2 & 511;
    int co  = u >> 3, pos = u & 7;
    int xb  = (co>>2)&1;
    int cip = ((((pos>>2)^xb)<<2) | (pos&3));
    int ci  = cc*16 + 2*cip;
    int cog = coT*64 + co;
    wp[i] = packhalf2(w[cog*512 + ci]   * cal[b*512 + ci],
                      w[cog*512 + ci+1] * cal[b*512 + ci+1]);
}

// ===========================================================================
// K1: BWT  x -> f32 NCHW + hi-pair packed
// ===========================================================================
__global__ void bwt_kernel(const float* __restrict__ x, float* __restrict__ o,
                           uint32_t* __restrict__ ohp)
{
    int idx = blockIdx.x * 256 + threadIdx.x;   // 4*32*128*128
    int j  = idx & 127;
    int i  = (idx >> 7) & 127;
    int cp = (idx >> 14) & 31;
    int b  = idx >> 19;
    const float* xp0 = x + ((size_t)(b*64 + 2*cp)*256 + 2*i)*256 + 2*j;
    const float* xp1 = xp0 + 65536;
    float2 r0 = *(const float2*)xp0, r1 = *(const float2*)(xp0 + 256);
    float2 s0 = *(const float2*)xp1, s1 = *(const float2*)(xp1 + 256);
    float a1 = r0.x*0.5f, a3 = r0.y*0.5f, a2 = r1.x*0.5f, a4 = r1.y*0.5f;
    float b1 = s0.x*0.5f, b3 = s0.y*0.5f, b2 = s1.x*0.5f, b4 = s1.y*0.5f;
    int p = (i << 7) + j;
    size_t obF = ((size_t)(b*512 + 2*cp) << 14) + p;
    size_t obP = ((size_t)(b*256 + cp)  << 14) + p;
    const size_t gsF = (size_t)64 << 14;
    const size_t gsP = (size_t)32 << 14;
    float va, vb;
#define BWT_EMIT(k, s1_, s2_, s3_, s4_) \
    va = s1_ a1 s2_ a2 s3_ a3 s4_ a4; \
    vb = s1_ b1 s2_ b2 s3_ b3 s4_ b4; \
    o[obF + k*gsF] = va; o[obF + k*gsF + 16384] = vb; \
    ohp[obP + k*gsP] = packhalf2(va, vb);
    BWT_EMIT(0, +, +, +, +)
    BWT_EMIT(1, -, -, +, +)
    BWT_EMIT(2, -, +, -, +)
    BWT_EMIT(3, +, -, -, +)
    BWT_EMIT(4, +, +, -, -)
    BWT_EMIT(5, -, +, +, -)
    BWT_EMIT(6, +, -, +, -)
    BWT_EMIT(7, -, -, -, -)
#undef BWT_EMIT
}

// ===========================================================================
// Implicit-GEMM conv, single-term fp16 mma.sync, 1 sync per chunk:
//   W: pre-swizzled gmem image, 3-stage cp.async (prefetch depth 2)
//   A: hi-pair u32 LDG -> register prefetch -> STS (2-stage, no PRMT)
// CTA: 256 thr / 8 warps, 16x16 px x 64 co; warp m32 x n64.
// ===========================================================================
template<int CIN, int COUT, int H, int KS,
         bool RELU, bool ADD_OUT, bool SAL, bool WPERB, bool OUTF32, bool OUTPK>
__global__ __launch_bounds__(256)
void mmaconv_kernel(const uint32_t* __restrict__ in_hp,
                    const uint32_t* __restrict__ wimg,
                    const float* __restrict__ sal,
                    float* outf, uint32_t* __restrict__ outhp)
{
    constexpr int KS2  = KS*KS;
    constexpr int PAD  = KS/2;
    constexpr int HC   = 16 + KS - 1;
    constexpr int HEL  = HC*HC;
    constexpr int ASTG = HEL*32;          // bytes per A stage
    constexpr int WCH  = KS2*2048;        // bytes per W chunk
    constexpr int NC   = CIN/16;
    constexpr int NA   = (8*HEL + 255)/256;
    constexpr int NG   = KS2*128;         // 16B granules per W chunk
    constexpr int HW   = H*H;

    extern __shared__ __align__(16) char smem[];
    const uint32_t smemBase = (uint32_t)__cvta_generic_to_shared(smem);
    const uint32_t wSmem    = smemBase + 2*ASTG;

    const int t    = threadIdx.x;
    const int lane = t & 31, wid = t >> 5;
    const int g    = lane >> 2;
    const int c0   = (lane & 3) * 2;
    const int bx0  = blockIdx.x * 16;
    const int by0  = blockIdx.y * 16;
    const int z    = blockIdx.z;
    const int coT  = z % (COUT/64);
    const int b    = z / (COUT/64);

    const int ltile = lane >> 3, lrow = lane & 7;
    const int lt_lo = ltile & 1;
    const int lt_h  = ltile >> 1;

    uint32_t boff[4];
    #pragma unroll
    for (int nfp = 0; nfp < 4; ++nfp) {
        int cr = nfp*16 + lt_lo*8 + lrow;
        boff[nfp] = (uint32_t)(cr*32 + ((lt_h ^ ((cr>>2)&1)) << 4));
    }

    const size_t bciHW = (size_t)(b*(CIN/2))*HW;
    const uint32_t* wChunk0 = wimg
        + (WPERB ? (size_t)b*(COUT/64)*NC*KS2*512 : 0)
        + (size_t)coT*NC*KS2*512;

    float acc[2][8][4];
    #pragma unroll
    for (int mf = 0; mf < 2; ++mf)
        #pragma unroll
        for (int nf = 0; nf < 8; ++nf)
            #pragma unroll
            for (int q = 0; q < 4; ++q) acc[mf][nf][q] = 0.f;

    uint32_t av[NA];

    auto loadA = [&](int cc) {
        #pragma unroll
        for (int k = 0; k < NA; ++k) {
            int idx = t + k*256;
            uint32_t v = 0u;
            if ((8*HEL) % 256 == 0 || idx < 8*HEL) {
                int cip = idx / HEL;
                int pix = idx - cip*HEL;
                int py  = pix / HC, px = pix - py*HC;
                int gy  = by0 + py - PAD, gx = bx0 + px - PAD;
                if (gy >= 0 && gy < H && gx >= 0 && gx < H)
                    v = in_hp[bciHW + (size_t)(cc*8 + cip)*HW + gy*H + gx];
            }
            av[k] = v;
        }
    };
    auto stsA = [&](int s) {
        uint32_t* AH = (uint32_t*)(smem + s*ASTG);
        #pragma unroll
        for (int k = 0; k < NA; ++k) {
            int idx = t + k*256;
            if ((8*HEL) % 256 == 0 || idx < 8*HEL) {
                int cip = idx / HEL;
                int pix = idx - cip*HEL;
                int u = pix*8 + ((((cip>>2) ^ ((pix>>2)&1)) << 2) | (cip & 3));
                AH[u] = av[k];
            }
        }
    };
    auto cpW = [&](int cc) {
        const uint32_t* src = wChunk0 + (size_t)cc*KS2*512;
        uint32_t dst = wSmem + (cc % 3)*WCH;
        #pragma unroll
        for (int k = t; k < NG; k += 256)
            cp16(dst + k*16, src + k*4);
    };
    auto compute = [&](int sa, int sw) {
        const uint32_t aHi = smemBase + sa*ASTG;
        const uint32_t wB  = wSmem + sw*WCH;
        #pragma unroll
        for (int tap = 0; tap < KS2; ++tap) {
            const int dy = tap / KS, dx = tap - dy*KS;
            uint32_t bh[8][2];
            #pragma unroll
            for (int nfp = 0; nfp < 4; ++nfp) {
                uint32_t tmp[4];
                ldsm_x4(tmp, wB + (uint32_t)(tap*2048) + boff[nfp]);
                bh[2*nfp][0] = tmp[0]; bh[2*nfp+1][0] = tmp[1];
                bh[2*nfp][1] = tmp[2]; bh[2*nfp+1][1] = tmp[3];
            }
            #pragma unroll
            for (int mf = 0; mf < 2; ++mf) {
                const int pyb = (wid << 1) + mf + dy;
                const int pix = pyb*HC + dx + lt_lo*8 + lrow;
                uint32_t aoff = (uint32_t)(pix*32 + ((lt_h ^ ((pix>>2)&1)) << 4));
                uint32_t ah[4];
                ldsm_x4(ah, aHi + aoff);
                #pragma unroll
                for (int nf = 0; nf < 8; ++nf)
                    mma_f16(acc[mf][nf], ah, bh[nf]);
            }
        }
    };

    // ---- pipelined chunk loop: ONE sync per chunk ----
    loadA(0);
    cpW(0); CP_COMMIT;
    cpW(1); CP_COMMIT;
    stsA(0);
    loadA(1);
    CP_WAIT1;                 // chunk 0 W ready
    __syncthreads();
    #pragma unroll 1
    for (int cc = 0; cc < NC; ++cc) {
        compute(cc & 1, cc % 3);
        if (cc + 1 < NC) {
            stsA((cc + 1) & 1);              // buf (cc-1)&1: all readers done
            if (cc + 2 < NC) { loadA(cc + 2); cpW(cc + 2); }
            CP_COMMIT;                        // group == chunk cc+2 (maybe empty)
            CP_WAIT1;                         // chunk cc+1 W complete
            __syncthreads();
        }
    }

    // ---- epilogue ----
    #pragma unroll
    for (int mf = 0; mf < 2; ++mf) {
        const int gy  = by0 + (wid << 1) + mf;
        const int gx0 = bx0 + g;
        const int gx8 = gx0 + 8;
        float s0 = 1.f, s8 = 1.f;
        if (SAL) {
            s0 = sal[((size_t)b*H + gy)*H + gx0];
            s8 = sal[((size_t)b*H + gy)*H + gx8];
        }
        #pragma unroll
        for (int nf = 0; nf < 8; ++nf) {
            const int co = coT*64 + nf*8 + c0;
            size_t o0 = ((size_t)(b*COUT + co)*H + gy)*H + gx0;
            size_t o1 = o0 + (size_t)H*H;
            size_t o2 = ((size_t)(b*COUT + co)*H + gy)*H + gx8;
            size_t o3 = o2 + (size_t)H*H;
            float v0 = acc[mf][nf][0]*s0, v1 = acc[mf][nf][1]*s0;
            float v2 = acc[mf][nf][2]*s8, v3 = acc[mf][nf][3]*s8;
            if (RELU) {
                v0 = fmaxf(v0, 0.f); v1 = fmaxf(v1, 0.f);
                v2 = fmaxf(v2, 0.f); v3 = fmaxf(v3, 0.f);
            }
            if (ADD_OUT) { v0 += outf[o0]; v1 += outf[o1]; v2 += outf[o2]; v3 += outf[o3]; }
            if (OUTF32) { outf[o0] = v0; outf[o1] = v1; outf[o2] = v2; outf[o3] = v3; }
            if (OUTPK) {
                size_t pb = ((size_t)(b*(COUT/2) + (co >> 1)))*HW + (size_t)gy*H;
                outhp[pb + gx0] = packhalf2(v0, v1);
                outhp[pb + gx8] = packhalf2(v2, v3);
            }
        }
    }
}

// ===========================================================================
// Scalar 1x1 conv GEMM — small residual 64x64 conv (exact f32 path)
// ===========================================================================
template<int COUT, int CIN, int HW>
__global__ __launch_bounds__(256)
void conv1x1_kernel(const float* __restrict__ in, const float* __restrict__ w,
                    float* out)
{
    __shared__ __align__(16) float sIn[16][128];
    __shared__ __align__(16) float sW [16][64];
    const int t  = threadIdx.x;
    const int tp = t & 31, tc = t >> 5;
    const int p0 = tp * 4, co0 = tc * 8;
    const int pBase  = blockIdx.x * 128;
    const int b      = blockIdx.y;
    const int coBase = blockIdx.z * 64;

    float acc[8][4];
    #pragma unroll
    for (int i = 0; i < 8; ++i) { acc[i][0]=acc[i][1]=acc[i][2]=acc[i][3]=0.f; }

    for (int kc = 0; kc < CIN / 16; ++kc) {
        const int kBase = kc * 16;
        #pragma unroll
        for (int i = t; i < 512; i += 256) {
            int k = i >> 5, x4 = i & 31;
            float4 v = *(const float4*)(in + (size_t)(b*CIN + kBase + k)*HW + pBase + x4*4);
            *(float4*)&sIn[k][x4*4] = v;
        }
        #pragma unroll
        for (int i = t; i < 1024; i += 256) {
            int co = i >> 4, k = i & 15;
            sW[k][co] = w[(size_t)(coBase + co)*CIN + kBase + k];
        }
        __syncthreads();
        #pragma unroll
        for (int k = 0; k < 16; ++k) {
            float4 v  = *(const float4*)&sIn[k][p0];
            float4 wl = *(const float4*)&sW[k][co0];
            float4 wh = *(const float4*)&sW[k][co0 + 4];
            float va[4] = {v.x, v.y, v.z, v.w};
            float wa[8] = {wl.x, wl.y, wl.z, wl.w, wh.x, wh.y, wh.z, wh.w};
            #pragma unroll
            for (int co = 0; co < 8; ++co)
                #pragma unroll
                for (int j = 0; j < 4; ++j)
                    acc[co][j] += wa[co] * va[j];
        }
        __syncthreads();
    }

    const int pg = pBase + p0;
    #pragma unroll
    for (int co = 0; co < 8; ++co) {
        size_t oi = (size_t)(b*COUT + coBase + co0 + co)*HW + pg;
        *(float4*)(out + oi) = make_float4(acc[co][0], acc[co][1], acc[co][2], acc[co][3]);
    }
}

// ===========================================================================
// Attention glue kernels
// ===========================================================================
__global__ void chanpool_kernel(const float* __restrict__ r2, float* __restrict__ pool)
{
    int p = blockIdx.x * 256 + threadIdx.x;
    int b = blockIdx.y;
    const float* base = r2 + (((size_t)b*512) << 14) + p;
    float mx = -3.4e38f, s = 0.f;
    #pragma unroll 8
    for (int c = 0; c < 512; ++c) {
        float v = base[(size_t)c << 14];
        mx = fmaxf(mx, v);
        s += v;
    }
    pool[(((size_t)(b*2    )) << 14) + p] = mx;
    pool[(((size_t)(b*2 + 1)) << 14) + p] = s * (1.f/512.f);
}

__global__ void salconv_kernel(const float* __restrict__ pool,
                               const float* __restrict__ wsal,
                               float* __restrict__ sal)
{
    int p = blockIdx.x * 256 + threadIdx.x;
    int b = blockIdx.y;
    int y = p >> 7, x = p & 127;
    float a = 0.f;
    #pragma unroll
    for (int c = 0; c < 2; ++c) {
        const float* pp = pool + (((size_t)(b*2 + c)) << 14);
        #pragma unroll
        for (int ky = 0; ky < 5; ++ky) {
            int iy = y + ky - 2;
            if (iy < 0 || iy >= 128) continue;
            #pragma unroll
            for (int kx = 0; kx < 5; ++kx) {
                int ix = x + kx - 2;
                if (ix < 0 || ix >= 128) continue;
                a += wsal[c*25 + ky*5 + kx] * pp[(iy << 7) + ix];
            }
        }
    }
    sal[(((size_t)b) << 14) + p] = 1.f / (1.f + expf(-a));
}

__global__ void wmean_kernel(const float* __restrict__ r2,
                             const float* __restrict__ sal,
                             float* __restrict__ m)
{
    int c = blockIdx.x, b = blockIdx.y;
    const float* r = r2 + (((size_t)(b*512 + c)) << 14);
    const float* s = sal + (((size_t)b) << 14);
    float sum = 0.f;
    for (int i = threadIdx.x; i < 4096; i += 256) {
        float4 rv = *(const float4*)(r + i*4);
        float4 sv = *(const float4*)(s + i*4);
        sum += rv.x*sv.x + rv.y*sv.y + rv.z*sv.z + rv.w*sv.w;
    }
    #pragma unroll
    for (int o = 16; o > 0; o >>= 1) sum += __shfl_xor_sync(0xffffffffu, sum, o);
    __shared__ float red[8];
    if ((threadIdx.x & 31) == 0) red[threadIdx.x >> 5] = sum;
    __syncthreads();
    if (threadIdx.x == 0) {
        float tot = 0.f;
        #pragma unroll
        for (int i = 0; i < 8; ++i) tot += red[i];
        m[b*512 + c] = tot * (1.f/16384.f);
    }
}

__global__ void calmlp_kernel(const float* __restrict__ m,
                              const float* __restrict__ wca1,
                              const float* __restrict__ wca2,
                              float* __restrict__ cal)
{
    int b = blockIdx.x;
    __shared__ float sm[512];
    __shared__ float sy1[32];
    for (int i = threadIdx.x; i < 512; i += 256) sm[i] = m[b*512 + i];
    __syncthreads();
    if (threadIdx.x < 32) {
        float a = 0.f;
        for (int c = 0; c < 512; ++c) a += wca1[threadIdx.x*512 + c] * sm[c];
        sy1[threadIdx.x] = fmaxf(a, 0.f);
    }
    __syncthreads();
    for (int c = threadIdx.x; c < 512; c += 256) {
        float a = 0.f;
        #pragma unroll
        for (int j = 0; j < 32; ++j) a += wca2[c*32 + j] * sy1[j];
        cal[b*512 + c] = 1.f / (1.f + expf(-a));
    }
}

// ===========================================================================
// K9: IBWT -> hi-pair packed output (2 channels per thread)
// ===========================================================================
__global__ void ibwt_kernel(const float* __restrict__ r, uint32_t* __restrict__ ohp)
{
    int idx = blockIdx.x * 256 + threadIdx.x;
    int j  = idx & 127;
    int i  = (idx >> 7) & 127;
    int cp = (idx >> 14) & 31;
    int b  = idx >> 19;
    size_t base = ((size_t)(b*512 + 2*cp) << 14) + (i << 7) + j;
    const size_t gs = (size_t)64 << 14;
    float p1 = r[base       ]*0.5f, p2 = r[base +   gs]*0.5f;
    float p3 = r[base + 2*gs]*0.5f, p4 = r[base + 3*gs]*0.5f;
    float p5 = r[base + 4*gs]*0.5f, p6 = r[base + 5*gs]*0.5f;
    float p7 = r[base + 6*gs]*0.5f, p8 = r[base + 7*gs]*0.5f;
    float q1 = r[base + 16384       ]*0.5f, q2 = r[base + 16384 +   gs]*0.5f;
    float q3 = r[base + 16384 + 2*gs]*0.5f, q4 = r[base + 16384 + 3*gs]*0.5f;
    float q5 = r[base + 16384 + 4*gs]*0.5f, q6 = r[base + 16384 + 5*gs]*0.5f;
    float q7 = r[base + 16384 + 6*gs]*0.5f, q8 = r[base + 16384 + 7*gs]*0.5f;
    float a00p = p1 - p2 - p3 + p4 + p5 - p6 + p7 - p8;
    float a10p = p1 - p2 + p3 - p4 - p5 + p6 - p7 + p8;
    float a01p = p1 + p2 - p3 - p4 - p5 - p6 + p7 + p8;
    float a11p = p1 + p2 + p3 + p4 + p5 + p6 + p7 + p8;
    float a00q = q1 - q2 - q3 + q4 + q5 - q6 + q7 - q8;
    float a10q = q1 - q2 + q3 - q4 - q5 + q6 - q7 + q8;
    float a01q = q1 + q2 - q3 - q4 - q5 - q6 + q7 + q8;
    float a11q = q1 + q2 + q3 + q4 + q5 + q6 + q7 + q8;
    size_t off = ((size_t)(b*32 + cp) << 16) + ((size_t)(2*i))*256 + 2*j;
    ohp[off      ] = packhalf2(a00p, a00q);
    ohp[off + 1  ] = packhalf2(a01p, a01q);
    ohp[off + 256] = packhalf2(a10p, a10q);
    ohp[off + 257] = packhalf2(a11p, a11q);
}

// ===========================================================================
// Launch
// ===========================================================================
extern "C" void kernel_launch(void* const* d_in, const int* in_sizes, int n_in,
                              void* d_out, int out_size)
{
    const float* x       = (const float*)d_in[0];
    const float* w_body1 = (const float*)d_in[1];
    const float* w_body2 = (const float*)d_in[2];
    const float* w_sal   = (const float*)d_in[3];
    const float* w_ca1   = (const float*)d_in[4];
    const float* w_ca2   = (const float*)d_in[5];
    const float* w_1x1   = (const float*)d_in[6];
    const float* w_3x3   = (const float*)d_in[7];
    const float* w_final = (const float*)d_in[8];
    float* out = (float*)d_out;

    float *bwt, *r2, *pool, *sal, *m, *cal;
    uint32_t *bwt_hp, *r1_hp, *r2_hp, *wv_hp, *wi1, *wi2, *wi3, *wic;
    cudaGetSymbolAddress((void**)&bwt,    g_bwt);
    cudaGetSymbolAddress((void**)&bwt_hp, g_bwt_hp);
    cudaGetSymbolAddress((void**)&r1_hp,  g_r1_hp);
    cudaGetSymbolAddress((void**)&r2,     g_r2);
    cudaGetSymbolAddress((void**)&r2_hp,  g_r2_hp);
    cudaGetSymbolAddress((void**)&wv_hp,  g_wv_hp);
    cudaGetSymbolAddress((void**)&pool,   g_pool);
    cudaGetSymbolAddress((void**)&sal,    g_sal);
    cudaGetSymbolAddress((void**)&m,      g_m);
    cudaGetSymbolAddress((void**)&cal,    g_cal);
    cudaGetSymbolAddress((void**)&wi1,    g_wi1);
    cudaGetSymbolAddress((void**)&wi2,    g_wi2);
    cudaGetSymbolAddress((void**)&wi3,    g_wi3);
    cudaGetSymbolAddress((void**)&wic,    g_wic);

    // smem: KS=3 -> 2*10368 + 3*18432 = 76032 ; KS=1 -> 2*8192 + 3*2048 = 22528
    constexpr int SM3 = 2*(18*18*32) + 3*(9*2048);
    constexpr int SM1 = 2*(16*16*32) + 3*2048;
    cudaFuncSetAttribute(
        (const void*)mmaconv_kernel<512,64,128,3, true,false,false,false,false,true>,
        cudaFuncAttributeMaxDynamicSharedMemorySize, SM3);
    cudaFuncSetAttribute(
        (const void*)mmaconv_kernel<64,512,128,3, false,false,false,false,true,true>,
        cudaFuncAttributeMaxDynamicSharedMemorySize, SM3);
    cudaFuncSetAttribute(
        (const void*)mmaconv_kernel<512,512,128,1, false,true,true,true,true,false>,
        cudaFuncAttributeMaxDynamicSharedMemorySize, SM1);
    cudaFuncSetAttribute(
        (const void*)mmaconv_kernel<64,64,256,3, true,true,false,false,true,false>,
        cudaFuncAttributeMaxDynamicSharedMemorySize, SM3);

    // 0) weight prep (batch-independent)
    packw_img<<<(32*9*512 + 255)/256, 256>>>(w_body1, wi1, 64, 512, 9, 32*9*512);
    packw_img<<<(8*4*9*512 + 255)/256, 256>>>(w_body2, wi2, 512, 64, 9, 8*4*9*512);
    packw_img<<<(4*9*512 + 255)/256, 256>>>(w_3x3, wi3, 64, 64, 9, 4*9*512);

    // 1) BWT (f32 + hi-pair)
    bwt_kernel<<<8192, 256>>>(x, bwt, bwt_hp);
    // 2) body1 3x3 (512 -> 64) + relu -> r1 hi-pair
    mmaconv_kernel<512,64,128,3, true,false,false,false,false,true>
        <<<dim3(8,8,4), 256, SM3>>>(bwt_hp, wi1, nullptr, nullptr, r1_hp);
    // 3) body2 3x3 (64 -> 512) -> r2 f32 + hi-pair
    mmaconv_kernel<64,512,128,3, false,false,false,false,true,true>
        <<<dim3(8,8,32), 256, SM3>>>(r1_hp, wi2, nullptr, r2, r2_hp);
    // 4) channel pooling
    chanpool_kernel<<<dim3(64,4), 256>>>(r2, pool);
    // 5) 5x5 conv + sigmoid -> sal
    salconv_kernel<<<dim3(64,4), 256>>>(pool, w_sal, sal);
    // 6) weighted channel means
    wmean_kernel<<<dim3(512,4), 256>>>(r2, sal, m);
    // 7) channel attention MLP
    calmlp_kernel<<<4, 256>>>(m, w_ca1, w_ca2, cal);
    // 7b) 1x1 weights with cal folded (per batch), swizzled image
    packwcal_img<<<(4*8*32*512)/256, 256>>>(w_1x1, cal, wic);
    // 8) 1x1 conv (512->512): sal epilogue, += x_bwt (f32, in place)
    mmaconv_kernel<512,512,128,1, false,true,true,true,true,false>
        <<<dim3(8,8,32), 256, SM1>>>(r2_hp, wic, sal, bwt, nullptr);
    // 9) IBWT -> hi-pair wave
    ibwt_kernel<<<8192, 256>>>(bwt, wv_hp);
    // 10) residual 1x1 conv -> out (scalar f32, exact)
    conv1x1_kernel<64, 64, 65536><<<dim3(512,4,1), 256>>>(x, w_final, out);
    // 11) final 3x3 conv (64->64) + relu, added onto out
    mmaconv_kernel<64,64,256,3, true,true,false,false,true,false>
        <<<dim3(16,16,4), 256, SM3>>>(wv_hp, wi3, nullptr, out, nullptr);
}

// round 11
// speedup vs baseline: 3.9516x; 1.2264x over previous
#include <cuda_runtime.h>
#include <cuda_fp16.h>
#include <math.h>
#include <stdint.h>

// ===========================================================================
// mma.sync m16n8k16 row.col fp16*fp16 -> f32 + ldmatrix + cp.async helpers
// ===========================================================================
__device__ __forceinline__ void mma_f16(float* c, const uint32_t* a, const uint32_t* b)
{
    asm volatile(
        "mma.sync.aligned.m16n8k16.row.col.f32.f16.f16.f32 "
        "{%0,%1,%2,%3}, {%4,%5,%6,%7}, {%8,%9}, {%0,%1,%2,%3};"
        : "+f"(c[0]), "+f"(c[1]), "+f"(c[2]), "+f"(c[3])
        : "r"(a[0]), "r"(a[1]), "r"(a[2]), "r"(a[3]), "r"(b[0]), "r"(b[1]));
}
__device__ __forceinline__ void ldsm_x4(uint32_t* r, uint32_t addr)
{
    asm volatile(
        "ldmatrix.sync.aligned.m8n8.x4.shared.b16 {%0,%1,%2,%3}, [%4];"
        : "=r"(r[0]), "=r"(r[1]), "=r"(r[2]), "=r"(r[3]) : "r"(addr));
}
__device__ __forceinline__ void cp16(uint32_t dst, const void* src)
{
    asm volatile("cp.async.cg.shared.global [%0], [%1], 16;" :: "r"(dst), "l"(src));
}
#define CP_COMMIT asm volatile("cp.async.commit_group;" ::: "memory")
#define CP_WAIT1  asm volatile("cp.async.wait_group 1;" ::: "memory")

// pack two channels' fp16 into one u32: half(c0) | half(c1)<<16
__device__ __forceinline__ uint32_t packhalf2(float c0, float c1)
{
    return ((uint32_t)__half_as_ushort(__float2half_rn(c1)) << 16)
         | __half_as_ushort(__float2half_rn(c0));
}
__device__ __forceinline__ float2 unpackhalf2(uint32_t v)
{
    __half2 h = *(__half2*)&v;
    return __half22float2(h);
}

// ===========================================================================
// Scratch buffers (all activations in fp16 hi-pair format [b][ch/2][px])
// ===========================================================================
__device__ float    g_w8    [(size_t)4*512*128*128]; // conv8 output f32 (ibwt in)
__device__ uint32_t g_bwt_hp[(size_t)4*256*128*128];
__device__ uint32_t g_x_hp  [(size_t)4*32*256*256];
__device__ uint32_t g_r1_hp [(size_t)4*32*128*128];
__device__ uint32_t g_r2_hp [(size_t)4*256*128*128];
__device__ uint32_t g_wv_hp [(size_t)4*32*256*256];
__device__ float    g_pool  [(size_t)4*2*128*128];
__device__ float    g_sal   [(size_t)4*128*128];
__device__ float    g_m     [4*512];
__device__ float    g_cal   [4*512];
// weight images: exact smem layout, [coT][cc][tap*512 + co*8 + swz(pos)]
__device__ uint32_t g_wi1[32*9*512];
__device__ uint32_t g_wi2[8*4*9*512];
__device__ uint32_t g_wi3[4*9*512];
__device__ uint32_t g_wif[4*512];
__device__ uint32_t g_wic[(size_t)4*8*32*512];

// ===========================================================================
// Weight prep: f32 [CO][CI][KS2] -> swizzled smem-image u32 (fp16 ci-pairs)
// ===========================================================================
__global__ void packw_img(const float* __restrict__ w, uint32_t* __restrict__ wp,
                          int CO, int CI, int KS2, int total)
{
    int i = blockIdx.x*256 + threadIdx.x;
    if (i >= total) return;
    int chunkU = KS2*512;
    int perCoT = (CI/16)*chunkU;
    int coT = i / perCoT;
    int rem = i - coT*perCoT;
    int cc  = rem / chunkU;
    int u   = rem - cc*chunkU;
    int tap = u >> 9;
    int r   = u & 511;
    int co  = r >> 3, pos = r & 7;
    int xb  = (co>>2)&1;
    int cip = ((((pos>>2)^xb)<<2) | (pos&3));
    int ci  = cc*16 + 2*cip;
    int cog = coT*64 + co;
    wp[i] = packhalf2(w[((size_t)cog*CI + ci)*KS2 + tap],
                      w[((size_t)cog*CI + ci+1)*KS2 + tap]);
}
__global__ void packwcal_img(const float* __restrict__ w, const float* __restrict__ cal,
                             uint32_t* __restrict__ wp)
{
    int i = blockIdx.x*256 + threadIdx.x;   // 4*131072
    int b = i >> 17;
    int rem = i & 131071;
    int coT = rem >> 14;
    int rem2 = rem & 16383;
    int cc  = rem2 >> 9;
    int u   = rem2 & 511;
    int co  = u >> 3, pos = u & 7;
    int xb  = (co>>2)&1;
    int cip = ((((pos>>2)^xb)<<2) | (pos&3));
    int ci  = cc*16 + 2*cip;
    int cog = coT*64 + co;
    wp[i] = packhalf2(w[cog*512 + ci]   * cal[b*512 + ci],
                      w[cog*512 + ci+1] * cal[b*512 + ci+1]);
}

// ===========================================================================
// K1: BWT  x -> bwt hi-pair, plus x itself repacked to hi-pair (for residual)
// ===========================================================================
__global__ void bwt_kernel(const float* __restrict__ x,
                           uint32_t* __restrict__ ohp, uint32_t* __restrict__ xhp)
{
    int idx = blockIdx.x * 256 + threadIdx.x;   // 4*32*128*128
    int j  = idx & 127;
    int i  = (idx >> 7) & 127;
    int cp = (idx >> 14) & 31;
    int b  = idx >> 19;
    const float* xp0 = x + ((size_t)(b*64 + 2*cp)*256 + 2*i)*256 + 2*j;
    const float* xp1 = xp0 + 65536;
    float2 r0 = *(const float2*)xp0, r1 = *(const float2*)(xp0 + 256);
    float2 s0 = *(const float2*)xp1, s1 = *(const float2*)(xp1 + 256);
    // repack x for the residual conv: [b][cp][py][px]
    size_t xb = ((size_t)(b*32 + cp) << 16) + (size_t)(2*i)*256 + 2*j;
    xhp[xb      ] = packhalf2(r0.x, s0.x);
    xhp[xb + 1  ] = packhalf2(r0.y, s0.y);
    xhp[xb + 256] = packhalf2(r1.x, s1.x);
    xhp[xb + 257] = packhalf2(r1.y, s1.y);
    float a1 = r0.x*0.5f, a3 = r0.y*0.5f, a2 = r1.x*0.5f, a4 = r1.y*0.5f;
    float b1 = s0.x*0.5f, b3 = s0.y*0.5f, b2 = s1.x*0.5f, b4 = s1.y*0.5f;
    int p = (i << 7) + j;
    size_t obP = ((size_t)(b*256 + cp) << 14) + p;
    const size_t gsP = (size_t)32 << 14;
#define BWT_EMIT(k, s1_, s2_, s3_, s4_) \
    ohp[obP + k*gsP] = packhalf2(s1_ a1 s2_ a2 s3_ a3 s4_ a4, \
                                 s1_ b1 s2_ b2 s3_ b3 s4_ b4);
    BWT_EMIT(0, +, +, +, +)
    BWT_EMIT(1, -, -, +, +)
    BWT_EMIT(2, -, +, -, +)
    BWT_EMIT(3, +, -, -, +)
    BWT_EMIT(4, +, +, -, -)
    BWT_EMIT(5, -, +, +, -)
    BWT_EMIT(6, +, -, +, -)
    BWT_EMIT(7, -, -, -, -)
#undef BWT_EMIT
}

// ===========================================================================
// Implicit-GEMM conv, single-term fp16 mma.sync, pipelined, 1 sync/chunk.
//   ADD_OUT: += outf (f32)    ADD_HP: += hi-pair buffer (co-pair word)
// ===========================================================================
template<int CIN, int COUT, int H, int KS,
         bool RELU, bool ADD_OUT, bool ADD_HP, bool SAL, bool WPERB,
         bool OUTF32, bool OUTPK>
__global__ __launch_bounds__(256)
void mmaconv_kernel(const uint32_t* __restrict__ in_hp,
                    const uint32_t* __restrict__ wimg,
                    const float* __restrict__ sal,
                    const uint32_t* __restrict__ addhp,
                    float* outf, uint32_t* __restrict__ outhp)
{
    constexpr int KS2  = KS*KS;
    constexpr int PAD  = KS/2;
    constexpr int HC   = 16 + KS - 1;
    constexpr int HEL  = HC*HC;
    constexpr int ASTG = HEL*32;
    constexpr int WCH  = KS2*2048;
    constexpr int NC   = CIN/16;
    constexpr int NA   = (8*HEL + 255)/256;
    constexpr int NG   = KS2*128;
    constexpr int HW   = H*H;

    extern __shared__ __align__(16) char smem[];
    const uint32_t smemBase = (uint32_t)__cvta_generic_to_shared(smem);
    const uint32_t wSmem    = smemBase + 2*ASTG;

    const int t    = threadIdx.x;
    const int lane = t & 31, wid = t >> 5;
    const int g    = lane >> 2;
    const int c0   = (lane & 3) * 2;
    const int bx0  = blockIdx.x * 16;
    const int by0  = blockIdx.y * 16;
    const int z    = blockIdx.z;
    const int coT  = z % (COUT/64);
    const int b    = z / (COUT/64);

    const int ltile = lane >> 3, lrow = lane & 7;
    const int lt_lo = ltile & 1;
    const int lt_h  = ltile >> 1;

    uint32_t boff[4];
    #pragma unroll
    for (int nfp = 0; nfp < 4; ++nfp) {
        int cr = nfp*16 + lt_lo*8 + lrow;
        boff[nfp] = (uint32_t)(cr*32 + ((lt_h ^ ((cr>>2)&1)) << 4));
    }

    const size_t bciHW = (size_t)(b*(CIN/2))*HW;
    const uint32_t* wChunk0 = wimg
        + (WPERB ? (size_t)b*(COUT/64)*NC*KS2*512 : 0)
        + (size_t)coT*NC*KS2*512;

    float acc[2][8][4];
    #pragma unroll
    for (int mf = 0; mf < 2; ++mf)
        #pragma unroll
        for (int nf = 0; nf < 8; ++nf)
            #pragma unroll
            for (int q = 0; q < 4; ++q) acc[mf][nf][q] = 0.f;

    uint32_t av[NA];

    auto loadA = [&](int cc) {
        #pragma unroll
        for (int k = 0; k < NA; ++k) {
            int idx = t + k*256;
            uint32_t v = 0u;
            if ((8*HEL) % 256 == 0 || idx < 8*HEL) {
                int cip = idx / HEL;
                int pix = idx - cip*HEL;
                int py  = pix / HC, px = pix - py*HC;
                int gy  = by0 + py - PAD, gx = bx0 + px - PAD;
                if (gy >= 0 && gy < H && gx >= 0 && gx < H)
                    v = in_hp[bciHW + (size_t)(cc*8 + cip)*HW + gy*H + gx];
            }
            av[k] = v;
        }
    };
    auto stsA = [&](int s) {
        uint32_t* AH = (uint32_t*)(smem + s*ASTG);
        #pragma unroll
        for (int k = 0; k < NA; ++k) {
            int idx = t + k*256;
            if ((8*HEL) % 256 == 0 || idx < 8*HEL) {
                int cip = idx / HEL;
                int pix = idx - cip*HEL;
                int u = pix*8 + ((((cip>>2) ^ ((pix>>2)&1)) << 2) | (cip & 3));
                AH[u] = av[k];
            }
        }
    };
    auto cpW = [&](int cc) {
        const uint32_t* src = wChunk0 + (size_t)cc*KS2*512;
        uint32_t dst = wSmem + (cc % 3)*WCH;
        #pragma unroll
        for (int k = t; k < NG; k += 256)
            cp16(dst + k*16, src + k*4);
    };
    auto compute = [&](int sa, int sw) {
        const uint32_t aHi = smemBase + sa*ASTG;
        const uint32_t wB  = wSmem + sw*WCH;
        #pragma unroll
        for (int tap = 0; tap < KS2; ++tap) {
            const int dy = tap / KS, dx = tap - dy*KS;
            uint32_t bh[8][2];
            #pragma unroll
            for (int nfp = 0; nfp < 4; ++nfp) {
                uint32_t tmp[4];
                ldsm_x4(tmp, wB + (uint32_t)(tap*2048) + boff[nfp]);
                bh[2*nfp][0] = tmp[0]; bh[2*nfp+1][0] = tmp[1];
                bh[2*nfp][1] = tmp[2]; bh[2*nfp+1][1] = tmp[3];
            }
            #pragma unroll
            for (int mf = 0; mf < 2; ++mf) {
                const int pyb = (wid << 1) + mf + dy;
                const int pix = pyb*HC + dx + lt_lo*8 + lrow;
                uint32_t aoff = (uint32_t)(pix*32 + ((lt_h ^ ((pix>>2)&1)) << 4));
                uint32_t ah[4];
                ldsm_x4(ah, aHi + aoff);
                #pragma unroll
                for (int nf = 0; nf < 8; ++nf)
                    mma_f16(acc[mf][nf], ah, bh[nf]);
            }
        }
    };

    // ---- pipelined chunk loop: ONE sync per chunk ----
    loadA(0);
    cpW(0); CP_COMMIT;
    cpW(1); CP_COMMIT;
    stsA(0);
    loadA(1);
    CP_WAIT1;
    __syncthreads();
    #pragma unroll 1
    for (int cc = 0; cc < NC; ++cc) {
        compute(cc & 1, cc % 3);
        if (cc + 1 < NC) {
            stsA((cc + 1) & 1);
            if (cc + 2 < NC) { loadA(cc + 2); cpW(cc + 2); }
            CP_COMMIT;
            CP_WAIT1;
            __syncthreads();
        }
    }

    // ---- epilogue ----
    #pragma unroll
    for (int mf = 0; mf < 2; ++mf) {
        const int gy  = by0 + (wid << 1) + mf;
        const int gx0 = bx0 + g;
        const int gx8 = gx0 + 8;
        float s0 = 1.f, s8 = 1.f;
        if (SAL) {
            s0 = sal[((size_t)b*H + gy)*H + gx0];
            s8 = sal[((size_t)b*H + gy)*H + gx8];
        }
        #pragma unroll
        for (int nf = 0; nf < 8; ++nf) {
            const int co = coT*64 + nf*8 + c0;
            size_t o0 = ((size_t)(b*COUT + co)*H + gy)*H + gx0;
            size_t o1 = o0 + (size_t)H*H;
            size_t o2 = ((size_t)(b*COUT + co)*H + gy)*H + gx8;
            size_t o3 = o2 + (size_t)H*H;
            float v0 = acc[mf][nf][0]*s0, v1 = acc[mf][nf][1]*s0;
            float v2 = acc[mf][nf][2]*s8, v3 = acc[mf][nf][3]*s8;
            if (RELU) {
                v0 = fmaxf(v0, 0.f); v1 = fmaxf(v1, 0.f);
                v2 = fmaxf(v2, 0.f); v3 = fmaxf(v3, 0.f);
            }
            if (ADD_OUT) { v0 += outf[o0]; v1 += outf[o1]; v2 += outf[o2]; v3 += outf[o3]; }
            size_t pb = ((size_t)(b*(COUT/2) + (co >> 1)))*HW + (size_t)gy*H;
            if (ADD_HP) {
                float2 h0 = unpackhalf2(addhp[pb + gx0]);
                float2 h8 = unpackhalf2(addhp[pb + gx8]);
                v0 += h0.x; v1 += h0.y; v2 += h8.x; v3 += h8.y;
            }
            if (OUTF32) { outf[o0] = v0; outf[o1] = v1; outf[o2] = v2; outf[o3] = v3; }
            if (OUTPK) {
                outhp[pb + gx0] = packhalf2(v0, v1);
                outhp[pb + gx8] = packhalf2(v2, v3);
            }
        }
    }
}

// ===========================================================================
// Attention glue kernels (hp inputs)
// ===========================================================================
__global__ void chanpool_kernel(const uint32_t* __restrict__ r2hp, float* __restrict__ pool)
{
    int p = blockIdx.x * 256 + threadIdx.x;
    int b = blockIdx.y;
    const uint32_t* base = r2hp + (((size_t)b*256) << 14) + p;
    float mx = -3.4e38f, s = 0.f;
    #pragma unroll 8
    for (int c = 0; c < 256; ++c) {
        float2 f = unpackhalf2(base[(size_t)c << 14]);
        mx = fmaxf(mx, fmaxf(f.x, f.y));
        s += f.x + f.y;
    }
    pool[(((size_t)(b*2    )) << 14) + p] = mx;
    pool[(((size_t)(b*2 + 1)) << 14) + p] = s * (1.f/512.f);
}

__global__ void salconv_kernel(const float* __restrict__ pool,
                               const float* __restrict__ wsal,
                               float* __restrict__ sal)
{
    int p = blockIdx.x * 256 + threadIdx.x;
    int b = blockIdx.y;
    int y = p >> 7, x = p & 127;
    float a = 0.f;
    #pragma unroll
    for (int c = 0; c < 2; ++c) {
        const float* pp = pool + (((size_t)(b*2 + c)) << 14);
        #pragma unroll
        for (int ky = 0; ky < 5; ++ky) {
            int iy = y + ky - 2;
            if (iy < 0 || iy >= 128) continue;
            #pragma unroll
            for (int kx = 0; kx < 5; ++kx) {
                int ix = x + kx - 2;
                if (ix < 0 || ix >= 128) continue;
                a += wsal[c*25 + ky*5 + kx] * pp[(iy << 7) + ix];
            }
        }
    }
    sal[(((size_t)b) << 14) + p] = 1.f / (1.f + expf(-a));
}

// weighted means for a channel PAIR per block
__global__ void wmean_kernel(const uint32_t* __restrict__ r2hp,
                             const float* __restrict__ sal,
                             float* __restrict__ m)
{
    int cp = blockIdx.x, b = blockIdx.y;
    const uint32_t* r = r2hp + (((size_t)(b*256 + cp)) << 14);
    const float* s = sal + (((size_t)b) << 14);
    float s0 = 0.f, s1 = 0.f;
    for (int i = threadIdx.x; i < 4096; i += 256) {
        uint4 rv = *(const uint4*)(r + i*4);
        float4 sv = *(const float4*)(s + i*4);
        float2 f0 = unpackhalf2(rv.x), f1 = unpackhalf2(rv.y);
        float2 f2 = unpackhalf2(rv.z), f3 = unpackhalf2(rv.w);
        s0 += f0.x*sv.x + f1.x*sv.y + f2.x*sv.z + f3.x*sv.w;
        s1 += f0.y*sv.x + f1.y*sv.y + f2.y*sv.z + f3.y*sv.w;
    }
    #pragma unroll
    for (int o = 16; o > 0; o >>= 1) {
        s0 += __shfl_xor_sync(0xffffffffu, s0, o);
        s1 += __shfl_xor_sync(0xffffffffu, s1, o);
    }
    __shared__ float red[8][2];
    if ((threadIdx.x & 31) == 0) {
        red[threadIdx.x >> 5][0] = s0;
        red[threadIdx.x >> 5][1] = s1;
    }
    __syncthreads();
    if (threadIdx.x == 0) {
        float t0 = 0.f, t1 = 0.f;
        #pragma unroll
        for (int i = 0; i < 8; ++i) { t0 += red[i][0]; t1 += red[i][1]; }
        m[b*512 + 2*cp    ] = t0 * (1.f/16384.f);
        m[b*512 + 2*cp + 1] = t1 * (1.f/16384.f);
    }
}

__global__ void calmlp_kernel(const float* __restrict__ m,
                              const float* __restrict__ wca1,
                              const float* __restrict__ wca2,
                              float* __restrict__ cal)
{
    int b = blockIdx.x;
    __shared__ float sm[512];
    __shared__ float sy1[32];
    for (int i = threadIdx.x; i < 512; i += 256) sm[i] = m[b*512 + i];
    __syncthreads();
    if (threadIdx.x < 32) {
        float a = 0.f;
        for (int c = 0; c < 512; ++c) a += wca1[threadIdx.x*512 + c] * sm[c];
        sy1[threadIdx.x] = fmaxf(a, 0.f);
    }
    __syncthreads();
    for (int c = threadIdx.x; c < 512; c += 256) {
        float a = 0.f;
        #pragma unroll
        for (int j = 0; j < 32; ++j) a += wca2[c*32 + j] * sy1[j];
        cal[b*512 + c] = 1.f / (1.f + expf(-a));
    }
}

// ===========================================================================
// K9: IBWT (f32 in from conv8) -> hi-pair packed output
// ===========================================================================
__global__ void ibwt_kernel(const float* __restrict__ r, uint32_t* __restrict__ ohp)
{
    int idx = blockIdx.x * 256 + threadIdx.x;
    int j  = idx & 127;
    int i  = (idx >> 7) & 127;
    int cp = (idx >> 14) & 31;
    int b  = idx >> 19;
    size_t base = ((size_t)(b*512 + 2*cp) << 14) + (i << 7) + j;
    const size_t gs = (size_t)64 << 14;
    float p1 = r[base       ]*0.5f, p2 = r[base +   gs]*0.5f;
    float p3 = r[base + 2*gs]*0.5f, p4 = r[base + 3*gs]*0.5f;
    float p5 = r[base + 4*gs]*0.5f, p6 = r[base + 5*gs]*0.5f;
    float p7 = r[base + 6*gs]*0.5f, p8 = r[base + 7*gs]*0.5f;
    float q1 = r[base + 16384       ]*0.5f, q2 = r[base + 16384 +   gs]*0.5f;
    float q3 = r[base + 16384 + 2*gs]*0.5f, q4 = r[base + 16384 + 3*gs]*0.5f;
    float q5 = r[base + 16384 + 4*gs]*0.5f, q6 = r[base + 16384 + 5*gs]*0.5f;
    float q7 = r[base + 16384 + 6*gs]*0.5f, q8 = r[base + 16384 + 7*gs]*0.5f;
    float a00p = p1 - p2 - p3 + p4 + p5 - p6 + p7 - p8;
    float a10p = p1 - p2 + p3 - p4 - p5 + p6 - p7 + p8;
    float a01p = p1 + p2 - p3 - p4 - p5 - p6 + p7 + p8;
    float a11p = p1 + p2 + p3 + p4 + p5 + p6 + p7 + p8;
    float a00q = q1 - q2 - q3 + q4 + q5 - q6 + q7 - q8;
    float a10q = q1 - q2 + q3 - q4 - q5 + q6 - q7 + q8;
    float a01q = q1 + q2 - q3 - q4 - q5 - q6 + q7 + q8;
    float a11q = q1 + q2 + q3 + q4 + q5 + q6 + q7 + q8;
    size_t off = ((size_t)(b*32 + cp) << 16) + ((size_t)(2*i))*256 + 2*j;
    ohp[off      ] = packhalf2(a00p, a00q);
    ohp[off + 1  ] = packhalf2(a01p, a01q);
    ohp[off + 256] = packhalf2(a10p, a10q);
    ohp[off + 257] = packhalf2(a11p, a11q);
}

// ===========================================================================
// Launch
// ===========================================================================
extern "C" void kernel_launch(void* const* d_in, const int* in_sizes, int n_in,
                              void* d_out, int out_size)
{
    const float* x       = (const float*)d_in[0];
    const float* w_body1 = (const float*)d_in[1];
    const float* w_body2 = (const float*)d_in[2];
    const float* w_sal   = (const float*)d_in[3];
    const float* w_ca1   = (const float*)d_in[4];
    const float* w_ca2   = (const float*)d_in[5];
    const float* w_1x1   = (const float*)d_in[6];
    const float* w_3x3   = (const float*)d_in[7];
    const float* w_final = (const float*)d_in[8];
    float* out = (float*)d_out;

    float *w8, *pool, *sal, *m, *cal;
    uint32_t *bwt_hp, *x_hp, *r1_hp, *r2_hp, *wv_hp, *wi1, *wi2, *wi3, *wif, *wic;
    cudaGetSymbolAddress((void**)&w8,     g_w8);
    cudaGetSymbolAddress((void**)&bwt_hp, g_bwt_hp);
    cudaGetSymbolAddress((void**)&x_hp,   g_x_hp);
    cudaGetSymbolAddress((void**)&r1_hp,  g_r1_hp);
    cudaGetSymbolAddress((void**)&r2_hp,  g_r2_hp);
    cudaGetSymbolAddress((void**)&wv_hp,  g_wv_hp);
    cudaGetSymbolAddress((void**)&pool,   g_pool);
    cudaGetSymbolAddress((void**)&sal,    g_sal);
    cudaGetSymbolAddress((void**)&m,      g_m);
    cudaGetSymbolAddress((void**)&cal,    g_cal);
    cudaGetSymbolAddress((void**)&wi1,    g_wi1);
    cudaGetSymbolAddress((void**)&wi2,    g_wi2);
    cudaGetSymbolAddress((void**)&wi3,    g_wi3);
    cudaGetSymbolAddress((void**)&wif,    g_wif);
    cudaGetSymbolAddress((void**)&wic,    g_wic);

    constexpr int SM3 = 2*(18*18*32) + 3*(9*2048);   // 76032
    constexpr int SM1 = 2*(16*16*32) + 3*2048;       // 22528
    cudaFuncSetAttribute(
        (const void*)mmaconv_kernel<512,64,128,3, true,false,false,false,false,false,true>,
        cudaFuncAttributeMaxDynamicSharedMemorySize, SM3);
    cudaFuncSetAttribute(
        (const void*)mmaconv_kernel<64,512,128,3, false,false,false,false,false,false,true>,
        cudaFuncAttributeMaxDynamicSharedMemorySize, SM3);
    cudaFuncSetAttribute(
        (const void*)mmaconv_kernel<512,512,128,1, false,false,true,true,true,true,false>,
        cudaFuncAttributeMaxDynamicSharedMemorySize, SM1);
    cudaFuncSetAttribute(
        (const void*)mmaconv_kernel<64,64,256,1, false,false,false,false,false,true,false>,
        cudaFuncAttributeMaxDynamicSharedMemorySize, SM1);
    cudaFuncSetAttribute(
        (const void*)mmaconv_kernel<64,64,256,3, true,true,false,false,false,true,false>,
        cudaFuncAttributeMaxDynamicSharedMemorySize, SM3);

    // 0) weight prep (batch-independent)
    packw_img<<<(32*9*512 + 255)/256, 256>>>(w_body1, wi1, 64, 512, 9, 32*9*512);
    packw_img<<<(8*4*9*512 + 255)/256, 256>>>(w_body2, wi2, 512, 64, 9, 8*4*9*512);
    packw_img<<<(4*9*512 + 255)/256, 256>>>(w_3x3, wi3, 64, 64, 9, 4*9*512);
    packw_img<<<(4*512 + 255)/256, 256>>>(w_final, wif, 64, 64, 1, 4*512);

    // 1) BWT (hi-pair) + x repack
    bwt_kernel<<<8192, 256>>>(x, bwt_hp, x_hp);
    // 2) body1 3x3 (512 -> 64) + relu -> r1 hi-pair
    mmaconv_kernel<512,64,128,3, true,false,false,false,false,false,true>
        <<<dim3(8,8,4), 256, SM3>>>(bwt_hp, wi1, nullptr, nullptr, nullptr, r1_hp);
    // 3) body2 3x3 (64 -> 512) -> r2 hi-pair only
    mmaconv_kernel<64,512,128,3, false,false,false,false,false,false,true>
        <<<dim3(8,8,32), 256, SM3>>>(r1_hp, wi2, nullptr, nullptr, nullptr, r2_hp);
    // 4) channel pooling (hp)
    chanpool_kernel<<<dim3(64,4), 256>>>(r2_hp, pool);
    // 5) 5x5 conv + sigmoid -> sal
    salconv_kernel<<<dim3(64,4), 256>>>(pool, w_sal, sal);
    // 6) weighted channel means (hp, pairs)
    wmean_kernel<<<dim3(256,4), 256>>>(r2_hp, sal, m);
    // 7) channel attention MLP
    calmlp_kernel<<<4, 256>>>(m, w_ca1, w_ca2, cal);
    // 7b) 1x1 weights with cal folded (per batch), swizzled image
    packwcal_img<<<(4*8*32*512)/256, 256>>>(w_1x1, cal, wic);
    // 8) 1x1 conv (512->512): sal epilogue, += x_bwt from hp -> f32 for ibwt
    mmaconv_kernel<512,512,128,1, false,false,true,true,true,true,false>
        <<<dim3(8,8,32), 256, SM1>>>(r2_hp, wic, sal, bwt_hp, w8, nullptr);
    // 9) IBWT -> hi-pair wave
    ibwt_kernel<<<8192, 256>>>(w8, wv_hp);
    // 10) residual 1x1 conv (tensor) -> out f32
    mmaconv_kernel<64,64,256,1, false,false,false,false,false,true,false>
        <<<dim3(16,16,4), 256, SM1>>>(x_hp, wif, nullptr, nullptr, out, nullptr);
    // 11) final 3x3 conv (64->64) + relu, added onto out
    mmaconv_kernel<64,64,256,3, true,true,false,false,false,true,false>
        <<<dim3(16,16,4), 256, SM3>>>(wv_hp, wi3, nullptr, nullptr, out, nullptr);
}

// round 12
// speedup vs baseline: 4.1915x; 1.0607x over previous
#include <cuda_runtime.h>
#include <cuda_fp16.h>
#include <math.h>
#include <stdint.h>

// ===========================================================================
// mma.sync m16n8k16 row.col fp16*fp16 -> f32 + ldmatrix + cp.async helpers
// ===========================================================================
__device__ __forceinline__ void mma_f16(float* c, const uint32_t* a, const uint32_t* b)
{
    asm volatile(
        "mma.sync.aligned.m16n8k16.row.col.f32.f16.f16.f32 "
        "{%0,%1,%2,%3}, {%4,%5,%6,%7}, {%8,%9}, {%0,%1,%2,%3};"
        : "+f"(c[0]), "+f"(c[1]), "+f"(c[2]), "+f"(c[3])
        : "r"(a[0]), "r"(a[1]), "r"(a[2]), "r"(a[3]), "r"(b[0]), "r"(b[1]));
}
__device__ __forceinline__ void ldsm_x4(uint32_t* r, uint32_t addr)
{
    asm volatile(
        "ldmatrix.sync.aligned.m8n8.x4.shared.b16 {%0,%1,%2,%3}, [%4];"
        : "=r"(r[0]), "=r"(r[1]), "=r"(r[2]), "=r"(r[3]) : "r"(addr));
}
__device__ __forceinline__ void cp16(uint32_t dst, const void* src)
{
    asm volatile("cp.async.cg.shared.global [%0], [%1], 16;" :: "r"(dst), "l"(src));
}
#define CP_COMMIT asm volatile("cp.async.commit_group;" ::: "memory")
#define CP_WAIT1  asm volatile("cp.async.wait_group 1;" ::: "memory")

// pack two channels' fp16 into one u32: half(c0) | half(c1)<<16
__device__ __forceinline__ uint32_t packhalf2(float c0, float c1)
{
    return ((uint32_t)__half_as_ushort(__float2half_rn(c1)) << 16)
         | __half_as_ushort(__float2half_rn(c0));
}
__device__ __forceinline__ float2 unpackhalf2(uint32_t v)
{
    __half2 h = *(__half2*)&v;
    return __half22float2(h);
}

// ===========================================================================
// Scratch buffers (all activations in fp16 hi-pair format [b][ch/2][px])
// ===========================================================================
__device__ uint32_t g_w8_hp [(size_t)4*256*128*128]; // conv8 output hp (ibwt in)
__device__ uint32_t g_bwt_hp[(size_t)4*256*128*128];
__device__ uint32_t g_x_hp  [(size_t)4*32*256*256];
__device__ uint32_t g_r1_hp [(size_t)4*32*128*128];
__device__ uint32_t g_r2_hp [(size_t)4*256*128*128];
__device__ uint32_t g_wv_hp [(size_t)4*32*256*256];
__device__ float    g_pool  [(size_t)4*2*128*128];
__device__ float    g_sal   [(size_t)4*128*128];
__device__ float    g_m     [4*512];
__device__ float    g_cal   [4*512];
// weight images: exact smem layout, [coT][cc16][tap*512 + co*8 + swz(pos)]
__device__ uint32_t g_wi1[32*9*512];
__device__ uint32_t g_wi2[8*4*9*512];
__device__ uint32_t g_wi3[4*9*512];
__device__ uint32_t g_wif[4*512];
__device__ uint32_t g_wic[(size_t)4*8*32*512];

// ===========================================================================
// Weight prep: f32 [CO][CI][KS2] -> swizzled smem-image u32 (fp16 ci-pairs)
// ===========================================================================
__global__ void packw_img(const float* __restrict__ w, uint32_t* __restrict__ wp,
                          int CO, int CI, int KS2, int total)
{
    int i = blockIdx.x*256 + threadIdx.x;
    if (i >= total) return;
    int chunkU = KS2*512;
    int perCoT = (CI/16)*chunkU;
    int coT = i / perCoT;
    int rem = i - coT*perCoT;
    int cc  = rem / chunkU;
    int u   = rem - cc*chunkU;
    int tap = u >> 9;
    int r   = u & 511;
    int co  = r >> 3, pos = r & 7;
    int xb  = (co>>2)&1;
    int cip = ((((pos>>2)^xb)<<2) | (pos&3));
    int ci  = cc*16 + 2*cip;
    int cog = coT*64 + co;
    wp[i] = packhalf2(w[((size_t)cog*CI + ci)*KS2 + tap],
                      w[((size_t)cog*CI + ci+1)*KS2 + tap]);
}
__global__ void packwcal_img(const float* __restrict__ w, const float* __restrict__ cal,
                             uint32_t* __restrict__ wp)
{
    int i = blockIdx.x*256 + threadIdx.x;   // 4*131072
    int b = i >> 17;
    int rem = i & 131071;
    int coT = rem >> 14;
    int rem2 = rem & 16383;
    int cc  = rem2 >> 9;
    int u   = rem2 & 511;
    int co  = u >> 3, pos = u & 7;
    int xb  = (co>>2)&1;
    int cip = ((((pos>>2)^xb)<<2) | (pos&3));
    int ci  = cc*16 + 2*cip;
    int cog = coT*64 + co;
    wp[i] = packhalf2(w[cog*512 + ci]   * cal[b*512 + ci],
                      w[cog*512 + ci+1] * cal[b*512 + ci+1]);
}

// ===========================================================================
// K1: BWT  x -> bwt hi-pair, plus x itself repacked to hi-pair (for residual)
// ===========================================================================
__global__ void bwt_kernel(const float* __restrict__ x,
                           uint32_t* __restrict__ ohp, uint32_t* __restrict__ xhp)
{
    int idx = blockIdx.x * 256 + threadIdx.x;   // 4*32*128*128
    int j  = idx & 127;
    int i  = (idx >> 7) & 127;
    int cp = (idx >> 14) & 31;
    int b  = idx >> 19;
    const float* xp0 = x + ((size_t)(b*64 + 2*cp)*256 + 2*i)*256 + 2*j;
    const float* xp1 = xp0 + 65536;
    float2 r0 = *(const float2*)xp0, r1 = *(const float2*)(xp0 + 256);
    float2 s0 = *(const float2*)xp1, s1 = *(const float2*)(xp1 + 256);
    size_t xb = ((size_t)(b*32 + cp) << 16) + (size_t)(2*i)*256 + 2*j;
    xhp[xb      ] = packhalf2(r0.x, s0.x);
    xhp[xb + 1  ] = packhalf2(r0.y, s0.y);
    xhp[xb + 256] = packhalf2(r1.x, s1.x);
    xhp[xb + 257] = packhalf2(r1.y, s1.y);
    float a1 = r0.x*0.5f, a3 = r0.y*0.5f, a2 = r1.x*0.5f, a4 = r1.y*0.5f;
    float b1 = s0.x*0.5f, b3 = s0.y*0.5f, b2 = s1.x*0.5f, b4 = s1.y*0.5f;
    int p = (i << 7) + j;
    size_t obP = ((size_t)(b*256 + cp) << 14) + p;
    const size_t gsP = (size_t)32 << 14;
#define BWT_EMIT(k, s1_, s2_, s3_, s4_) \
    ohp[obP + k*gsP] = packhalf2(s1_ a1 s2_ a2 s3_ a3 s4_ a4, \
                                 s1_ b1 s2_ b2 s3_ b3 s4_ b4);
    BWT_EMIT(0, +, +, +, +)
    BWT_EMIT(1, -, -, +, +)
    BWT_EMIT(2, -, +, -, +)
    BWT_EMIT(3, +, -, -, +)
    BWT_EMIT(4, +, +, -, -)
    BWT_EMIT(5, -, +, +, -)
    BWT_EMIT(6, +, -, +, -)
    BWT_EMIT(7, -, -, -, -)
#undef BWT_EMIT
}

// ===========================================================================
// Implicit-GEMM conv, single-term fp16 mma.sync, pipelined, 1 sync/chunk.
// KCH = input channels per chunk (16 or 32); NSUB 16-ci sub-chunks inside.
// ===========================================================================
template<int CIN, int COUT, int H, int KS, int KCH,
         bool RELU, bool ADD_OUT, bool ADD_HP, bool SAL, bool WPERB,
         bool OUTF32, bool OUTPK>
__global__ __launch_bounds__(256)
void mmaconv_kernel(const uint32_t* __restrict__ in_hp,
                    const uint32_t* __restrict__ wimg,
                    const float* __restrict__ sal,
                    const uint32_t* __restrict__ addhp,
                    float* outf, uint32_t* __restrict__ outhp)
{
    constexpr int KS2  = KS*KS;
    constexpr int PAD  = KS/2;
    constexpr int HC   = 16 + KS - 1;
    constexpr int HEL  = HC*HC;
    constexpr int NSUB = KCH/16;
    constexpr int APL  = HEL*32;            // bytes per 16-ci sub-plane
    constexpr int ASTG = NSUB*APL;          // bytes per A stage
    constexpr int WCH  = NSUB*KS2*2048;     // bytes per W chunk
    constexpr int NC   = CIN/KCH;
    constexpr int ACNT = (KCH/2)*HEL;       // u32 per A stage
    constexpr int NA   = (ACNT + 255)/256;
    constexpr int NG   = NSUB*KS2*128;      // 16B granules per W chunk
    constexpr int HW   = H*H;

    extern __shared__ __align__(16) char smem[];
    const uint32_t smemBase = (uint32_t)__cvta_generic_to_shared(smem);
    const uint32_t wSmem    = smemBase + 2*ASTG;

    const int t    = threadIdx.x;
    const int lane = t & 31, wid = t >> 5;
    const int g    = lane >> 2;
    const int c0   = (lane & 3) * 2;
    const int bx0  = blockIdx.x * 16;
    const int by0  = blockIdx.y * 16;
    const int z    = blockIdx.z;
    const int coT  = z % (COUT/64);
    const int b    = z / (COUT/64);

    const int ltile = lane >> 3, lrow = lane & 7;
    const int lt_lo = ltile & 1;
    const int lt_h  = ltile >> 1;

    uint32_t boff[4];
    #pragma unroll
    for (int nfp = 0; nfp < 4; ++nfp) {
        int cr = nfp*16 + lt_lo*8 + lrow;
        boff[nfp] = (uint32_t)(cr*32 + ((lt_h ^ ((cr>>2)&1)) << 4));
    }

    const size_t bciHW = (size_t)(b*(CIN/2))*HW;
    constexpr int NC16 = CIN/16;
    const uint32_t* wChunk0 = wimg
        + (WPERB ? (size_t)b*(COUT/64)*NC16*KS2*512 : 0)
        + (size_t)coT*NC16*KS2*512;

    float acc[2][8][4];
    #pragma unroll
    for (int mf = 0; mf < 2; ++mf)
        #pragma unroll
        for (int nf = 0; nf < 8; ++nf)
            #pragma unroll
            for (int q = 0; q < 4; ++q) acc[mf][nf][q] = 0.f;

    uint32_t av[NA];

    auto loadA = [&](int cc) {
        #pragma unroll
        for (int k = 0; k < NA; ++k) {
            int idx = t + k*256;
            uint32_t v = 0u;
            if (ACNT % 256 == 0 || idx < ACNT) {
                int cip = idx / HEL;         // 16-ci pair plane 0..KCH/2-1
                int pix = idx - cip*HEL;
                int py  = pix / HC, px = pix - py*HC;
                int gy  = by0 + py - PAD, gx = bx0 + px - PAD;
                if (gy >= 0 && gy < H && gx >= 0 && gx < H)
                    v = in_hp[bciHW + (size_t)(cc*(KCH/2) + cip)*HW + gy*H + gx];
            }
            av[k] = v;
        }
    };
    auto stsA = [&](int s) {
        uint32_t* AH = (uint32_t*)(smem + s*ASTG);
        #pragma unroll
        for (int k = 0; k < NA; ++k) {
            int idx = t + k*256;
            if (ACNT % 256 == 0 || idx < ACNT) {
                int cip = idx / HEL;
                int pix = idx - cip*HEL;
                int sub = cip >> 3, c8 = cip & 7;
                int u = sub*(HEL*8) + pix*8
                      + ((((c8>>2) ^ ((pix>>2)&1)) << 2) | (c8 & 3));
                AH[u] = av[k];
            }
        }
    };
    auto cpW = [&](int cc) {
        const uint32_t* src = wChunk0 + (size_t)cc*NSUB*KS2*512;
        uint32_t dst = wSmem + (cc % 3)*WCH;
        #pragma unroll
        for (int k = t; k < NG; k += 256)
            cp16(dst + k*16, src + k*4);
    };
    auto compute = [&](int sa, int sw) {
        #pragma unroll
        for (int s = 0; s < NSUB; ++s) {
            const uint32_t aHi = smemBase + sa*ASTG + s*APL;
            const uint32_t wB  = wSmem + sw*WCH + s*KS2*2048;
            #pragma unroll
            for (int tap = 0; tap < KS2; ++tap) {
                const int dy = tap / KS, dx = tap - dy*KS;
                uint32_t bh[8][2];
                #pragma unroll
                for (int nfp = 0; nfp < 4; ++nfp) {
                    uint32_t tmp[4];
                    ldsm_x4(tmp, wB + (uint32_t)(tap*2048) + boff[nfp]);
                    bh[2*nfp][0] = tmp[0]; bh[2*nfp+1][0] = tmp[1];
                    bh[2*nfp][1] = tmp[2]; bh[2*nfp+1][1] = tmp[3];
                }
                #pragma unroll
                for (int mf = 0; mf < 2; ++mf) {
                    const int pyb = (wid << 1) + mf + dy;
                    const int pix = pyb*HC + dx + lt_lo*8 + lrow;
                    uint32_t aoff = (uint32_t)(pix*32 + ((lt_h ^ ((pix>>2)&1)) << 4));
                    uint32_t ah[4];
                    ldsm_x4(ah, aHi + aoff);
                    #pragma unroll
                    for (int nf = 0; nf < 8; ++nf)
                        mma_f16(acc[mf][nf], ah, bh[nf]);
                }
            }
        }
    };

    // ---- pipelined chunk loop: ONE sync per chunk ----
    loadA(0);
    cpW(0); CP_COMMIT;
    cpW(1); CP_COMMIT;
    stsA(0);
    loadA(1);
    CP_WAIT1;
    __syncthreads();
    #pragma unroll 1
    for (int cc = 0; cc < NC; ++cc) {
        compute(cc & 1, cc % 3);
        if (cc + 1 < NC) {
            stsA((cc + 1) & 1);
            if (cc + 2 < NC) { loadA(cc + 2); cpW(cc + 2); }
            CP_COMMIT;
            CP_WAIT1;
            __syncthreads();
        }
    }

    // ---- epilogue ----
    #pragma unroll
    for (int mf = 0; mf < 2; ++mf) {
        const int gy  = by0 + (wid << 1) + mf;
        const int gx0 = bx0 + g;
        const int gx8 = gx0 + 8;
        float s0 = 1.f, s8 = 1.f;
        if (SAL) {
            s0 = sal[((size_t)b*H + gy)*H + gx0];
            s8 = sal[((size_t)b*H + gy)*H + gx8];
        }
        #pragma unroll
        for (int nf = 0; nf < 8; ++nf) {
            const int co = coT*64 + nf*8 + c0;
            size_t o0 = ((size_t)(b*COUT + co)*H + gy)*H + gx0;
            size_t o1 = o0 + (size_t)H*H;
            size_t o2 = ((size_t)(b*COUT + co)*H + gy)*H + gx8;
            size_t o3 = o2 + (size_t)H*H;
            float v0 = acc[mf][nf][0]*s0, v1 = acc[mf][nf][1]*s0;
            float v2 = acc[mf][nf][2]*s8, v3 = acc[mf][nf][3]*s8;
            if (RELU) {
                v0 = fmaxf(v0, 0.f); v1 = fmaxf(v1, 0.f);
                v2 = fmaxf(v2, 0.f); v3 = fmaxf(v3, 0.f);
            }
            if (ADD_OUT) { v0 += outf[o0]; v1 += outf[o1]; v2 += outf[o2]; v3 += outf[o3]; }
            size_t pb = ((size_t)(b*(COUT/2) + (co >> 1)))*HW + (size_t)gy*H;
            if (ADD_HP) {
                float2 h0 = unpackhalf2(addhp[pb + gx0]);
                float2 h8 = unpackhalf2(addhp[pb + gx8]);
                v0 += h0.x; v1 += h0.y; v2 += h8.x; v3 += h8.y;
            }
            if (OUTF32) { outf[o0] = v0; outf[o1] = v1; outf[o2] = v2; outf[o3] = v3; }
            if (OUTPK) {
                outhp[pb + gx0] = packhalf2(v0, v1);
                outhp[pb + gx8] = packhalf2(v2, v3);
            }
        }
    }
}

// ===========================================================================
// Attention glue kernels (hp inputs)
// ===========================================================================
__global__ void chanpool_kernel(const uint32_t* __restrict__ r2hp, float* __restrict__ pool)
{
    int p = blockIdx.x * 256 + threadIdx.x;
    int b = blockIdx.y;
    const uint32_t* base = r2hp + (((size_t)b*256) << 14) + p;
    float mx = -3.4e38f, s = 0.f;
    #pragma unroll 8
    for (int c = 0; c < 256; ++c) {
        float2 f = unpackhalf2(base[(size_t)c << 14]);
        mx = fmaxf(mx, fmaxf(f.x, f.y));
        s += f.x + f.y;
    }
    pool[(((size_t)(b*2    )) << 14) + p] = mx;
    pool[(((size_t)(b*2 + 1)) << 14) + p] = s * (1.f/512.f);
}

__global__ void salconv_kernel(const float* __restrict__ pool,
                               const float* __restrict__ wsal,
                               float* __restrict__ sal)
{
    int p = blockIdx.x * 256 + threadIdx.x;
    int b = blockIdx.y;
    int y = p >> 7, x = p & 127;
    float a = 0.f;
    #pragma unroll
    for (int c = 0; c < 2; ++c) {
        const float* pp = pool + (((size_t)(b*2 + c)) << 14);
        #pragma unroll
        for (int ky = 0; ky < 5; ++ky) {
            int iy = y + ky - 2;
            if (iy < 0 || iy >= 128) continue;
            #pragma unroll
            for (int kx = 0; kx < 5; ++kx) {
                int ix = x + kx - 2;
                if (ix < 0 || ix >= 128) continue;
                a += wsal[c*25 + ky*5 + kx] * pp[(iy << 7) + ix];
            }
        }
    }
    sal[(((size_t)b) << 14) + p] = 1.f / (1.f + expf(-a));
}

__global__ void wmean_kernel(const uint32_t* __restrict__ r2hp,
                             const float* __restrict__ sal,
                             float* __restrict__ m)
{
    int cp = blockIdx.x, b = blockIdx.y;
    const uint32_t* r = r2hp + (((size_t)(b*256 + cp)) << 14);
    const float* s = sal + (((size_t)b) << 14);
    float s0 = 0.f, s1 = 0.f;
    for (int i = threadIdx.x; i < 4096; i += 256) {
        uint4 rv = *(const uint4*)(r + i*4);
        float4 sv = *(const float4*)(s + i*4);
        float2 f0 = unpackhalf2(rv.x), f1 = unpackhalf2(rv.y);
        float2 f2 = unpackhalf2(rv.z), f3 = unpackhalf2(rv.w);
        s0 += f0.x*sv.x + f1.x*sv.y + f2.x*sv.z + f3.x*sv.w;
        s1 += f0.y*sv.x + f1.y*sv.y + f2.y*sv.z + f3.y*sv.w;
    }
    #pragma unroll
    for (int o = 16; o > 0; o >>= 1) {
        s0 += __shfl_xor_sync(0xffffffffu, s0, o);
        s1 += __shfl_xor_sync(0xffffffffu, s1, o);
    }
    __shared__ float red[8][2];
    if ((threadIdx.x & 31) == 0) {
        red[threadIdx.x >> 5][0] = s0;
        red[threadIdx.x >> 5][1] = s1;
    }
    __syncthreads();
    if (threadIdx.x == 0) {
        float t0 = 0.f, t1 = 0.f;
        #pragma unroll
        for (int i = 0; i < 8; ++i) { t0 += red[i][0]; t1 += red[i][1]; }
        m[b*512 + 2*cp    ] = t0 * (1.f/16384.f);
        m[b*512 + 2*cp + 1] = t1 * (1.f/16384.f);
    }
}

__global__ void calmlp_kernel(const float* __restrict__ m,
                              const float* __restrict__ wca1,
                              const float* __restrict__ wca2,
                              float* __restrict__ cal)
{
    int b = blockIdx.x;
    __shared__ float sm[512];
    __shared__ float sy1[32];
    for (int i = threadIdx.x; i < 512; i += 256) sm[i] = m[b*512 + i];
    __syncthreads();
    if (threadIdx.x < 32) {
        float a = 0.f;
        for (int c = 0; c < 512; ++c) a += wca1[threadIdx.x*512 + c] * sm[c];
        sy1[threadIdx.x] = fmaxf(a, 0.f);
    }
    __syncthreads();
    for (int c = threadIdx.x; c < 512; c += 256) {
        float a = 0.f;
        #pragma unroll
        for (int j = 0; j < 32; ++j) a += wca2[c*32 + j] * sy1[j];
        cal[b*512 + c] = 1.f / (1.f + expf(-a));
    }
}

// ===========================================================================
// K9: IBWT (hp in from conv8) -> hi-pair packed output
// ===========================================================================
__global__ void ibwt_kernel(const uint32_t* __restrict__ rhp, uint32_t* __restrict__ ohp)
{
    int idx = blockIdx.x * 256 + threadIdx.x;
    int j  = idx & 127;
    int i  = (idx >> 7) & 127;
    int cp = (idx >> 14) & 31;
    int b  = idx >> 19;
    int p  = (i << 7) + j;
    size_t base = ((size_t)(b*256 + cp) << 14) + p;
    const size_t gsP = (size_t)32 << 14;
    float pe[8], qe[8];
    #pragma unroll
    for (int s = 0; s < 8; ++s) {
        float2 f = unpackhalf2(rhp[base + s*gsP]);
        pe[s] = f.x*0.5f; qe[s] = f.y*0.5f;
    }
    float a00p = pe[0]-pe[1]-pe[2]+pe[3]+pe[4]-pe[5]+pe[6]-pe[7];
    float a10p = pe[0]-pe[1]+pe[2]-pe[3]-pe[4]+pe[5]-pe[6]+pe[7];
    float a01p = pe[0]+pe[1]-pe[2]-pe[3]-pe[4]-pe[5]+pe[6]+pe[7];
    float a11p = pe[0]+pe[1]+pe[2]+pe[3]+pe[4]+pe[5]+pe[6]+pe[7];
    float a00q = qe[0]-qe[1]-qe[2]+qe[3]+qe[4]-qe[5]+qe[6]-qe[7];
    float a10q = qe[0]-qe[1]+qe[2]-qe[3]-qe[4]+qe[5]-qe[6]+qe[7];
    float a01q = qe[0]+qe[1]-qe[2]-qe[3]-qe[4]-qe[5]+qe[6]+qe[7];
    float a11q = qe[0]+qe[1]+qe[2]+qe[3]+qe[4]+qe[5]+qe[6]+qe[7];
    size_t off = ((size_t)(b*32 + cp) << 16) + ((size_t)(2*i))*256 + 2*j;
    ohp[off      ] = packhalf2(a00p, a00q);
    ohp[off + 1  ] = packhalf2(a01p, a01q);
    ohp[off + 256] = packhalf2(a10p, a10q);
    ohp[off + 257] = packhalf2(a11p, a11q);
}

// ===========================================================================
// Launch
// ===========================================================================
extern "C" void kernel_launch(void* const* d_in, const int* in_sizes, int n_in,
                              void* d_out, int out_size)
{
    const float* x       = (const float*)d_in[0];
    const float* w_body1 = (const float*)d_in[1];
    const float* w_body2 = (const float*)d_in[2];
    const float* w_sal   = (const float*)d_in[3];
    const float* w_ca1   = (const float*)d_in[4];
    const float* w_ca2   = (const float*)d_in[5];
    const float* w_1x1   = (const float*)d_in[6];
    const float* w_3x3   = (const float*)d_in[7];
    const float* w_final = (const float*)d_in[8];
    float* out = (float*)d_out;

    float *pool, *sal, *m, *cal;
    uint32_t *w8_hp, *bwt_hp, *x_hp, *r1_hp, *r2_hp, *wv_hp;
    uint32_t *wi1, *wi2, *wi3, *wif, *wic;
    cudaGetSymbolAddress((void**)&w8_hp,  g_w8_hp);
    cudaGetSymbolAddress((void**)&bwt_hp, g_bwt_hp);
    cudaGetSymbolAddress((void**)&x_hp,   g_x_hp);
    cudaGetSymbolAddress((void**)&r1_hp,  g_r1_hp);
    cudaGetSymbolAddress((void**)&r2_hp,  g_r2_hp);
    cudaGetSymbolAddress((void**)&wv_hp,  g_wv_hp);
    cudaGetSymbolAddress((void**)&pool,   g_pool);
    cudaGetSymbolAddress((void**)&sal,    g_sal);
    cudaGetSymbolAddress((void**)&m,      g_m);
    cudaGetSymbolAddress((void**)&cal,    g_cal);
    cudaGetSymbolAddress((void**)&wi1,    g_wi1);
    cudaGetSymbolAddress((void**)&wi2,    g_wi2);
    cudaGetSymbolAddress((void**)&wi3,    g_wi3);
    cudaGetSymbolAddress((void**)&wif,    g_wif);
    cudaGetSymbolAddress((void**)&wic,    g_wic);

    constexpr int SM3    = 2*(18*18*32) + 3*(9*2048);      // 76032
    constexpr int SM1    = 2*(16*16*32) + 3*2048;          // 22528
    constexpr int SM1K32 = 2*(2*16*16*32) + 3*(2*2048);    // 45056
    cudaFuncSetAttribute(
        (const void*)mmaconv_kernel<512,64,128,3,16, true,false,false,false,false,false,true>,
        cudaFuncAttributeMaxDynamicSharedMemorySize, SM3);
    cudaFuncSetAttribute(
        (const void*)mmaconv_kernel<64,512,128,3,16, false,false,false,false,false,false,true>,
        cudaFuncAttributeMaxDynamicSharedMemorySize, SM3);
    cudaFuncSetAttribute(
        (const void*)mmaconv_kernel<512,512,128,1,32, false,false,true,true,true,false,true>,
        cudaFuncAttributeMaxDynamicSharedMemorySize, SM1K32);
    cudaFuncSetAttribute(
        (const void*)mmaconv_kernel<64,64,256,1,16, false,false,false,false,false,true,false>,
        cudaFuncAttributeMaxDynamicSharedMemorySize, SM1);
    cudaFuncSetAttribute(
        (const void*)mmaconv_kernel<64,64,256,3,16, true,true,false,false,false,true,false>,
        cudaFuncAttributeMaxDynamicSharedMemorySize, SM3);

    // 0) weight prep (batch-independent)
    packw_img<<<(32*9*512 + 255)/256, 256>>>(w_body1, wi1, 64, 512, 9, 32*9*512);
    packw_img<<<(8*4*9*512 + 255)/256, 256>>>(w_body2, wi2, 512, 64, 9, 8*4*9*512);
    packw_img<<<(4*9*512 + 255)/256, 256>>>(w_3x3, wi3, 64, 64, 9, 4*9*512);
    packw_img<<<(4*512 + 255)/256, 256>>>(w_final, wif, 64, 64, 1, 4*512);

    // 1) BWT (hi-pair) + x repack
    bwt_kernel<<<8192, 256>>>(x, bwt_hp, x_hp);
    // 2) body1 3x3 (512 -> 64) + relu -> r1 hi-pair
    mmaconv_kernel<512,64,128,3,16, true,false,false,false,false,false,true>
        <<<dim3(8,8,4), 256, SM3>>>(bwt_hp, wi1, nullptr, nullptr, nullptr, r1_hp);
    // 3) body2 3x3 (64 -> 512) -> r2 hi-pair
    mmaconv_kernel<64,512,128,3,16, false,false,false,false,false,false,true>
        <<<dim3(8,8,32), 256, SM3>>>(r1_hp, wi2, nullptr, nullptr, nullptr, r2_hp);
    // 4) channel pooling (hp)
    chanpool_kernel<<<dim3(64,4), 256>>>(r2_hp, pool);
    // 5) 5x5 conv + sigmoid -> sal
    salconv_kernel<<<dim3(64,4), 256>>>(pool, w_sal, sal);
    // 6) weighted channel means (hp, pairs)
    wmean_kernel<<<dim3(256,4), 256>>>(r2_hp, sal, m);
    // 7) channel attention MLP
    calmlp_kernel<<<4, 256>>>(m, w_ca1, w_ca2, cal);
    // 7b) 1x1 weights with cal folded (per batch), swizzled image
    packwcal_img<<<(4*8*32*512)/256, 256>>>(w_1x1, cal, wic);
    // 8) 1x1 conv (512->512), KCH=32: sal epilogue, += x_bwt hp -> w8 hp
    mmaconv_kernel<512,512,128,1,32, false,false,true,true,true,false,true>
        <<<dim3(8,8,32), 256, SM1K32>>>(r2_hp, wic, sal, bwt_hp, nullptr, w8_hp);
    // 9) IBWT (hp in) -> hi-pair wave
    ibwt_kernel<<<8192, 256>>>(w8_hp, wv_hp);
    // 10) residual 1x1 conv (tensor) -> out f32
    mmaconv_kernel<64,64,256,1,16, false,false,false,false,false,true,false>
        <<<dim3(16,16,4), 256, SM1>>>(x_hp, wif, nullptr, nullptr, out, nullptr);
    // 11) final 3x3 conv (64->64) + relu, added onto out
    mmaconv_kernel<64,64,256,3,16, true,true,false,false,false,true,false>
        <<<dim3(16,16,4), 256, SM3>>>(wv_hp, wi3, nullptr, nullptr, out, nullptr);
}

// round 13
// speedup vs baseline: 4.4957x; 1.0726x over previous
#include <cuda_runtime.h>
#include <cuda_fp16.h>
#include <math.h>
#include <stdint.h>

// ===========================================================================
// mma.sync m16n8k16 row.col fp16*fp16 -> f32 + ldmatrix + cp.async helpers
// ===========================================================================
__device__ __forceinline__ void mma_f16(float* c, const uint32_t* a, const uint32_t* b)
{
    asm volatile(
        "mma.sync.aligned.m16n8k16.row.col.f32.f16.f16.f32 "
        "{%0,%1,%2,%3}, {%4,%5,%6,%7}, {%8,%9}, {%0,%1,%2,%3};"
        : "+f"(c[0]), "+f"(c[1]), "+f"(c[2]), "+f"(c[3])
        : "r"(a[0]), "r"(a[1]), "r"(a[2]), "r"(a[3]), "r"(b[0]), "r"(b[1]));
}
__device__ __forceinline__ void ldsm_x4(uint32_t* r, uint32_t addr)
{
    asm volatile(
        "ldmatrix.sync.aligned.m8n8.x4.shared.b16 {%0,%1,%2,%3}, [%4];"
        : "=r"(r[0]), "=r"(r[1]), "=r"(r[2]), "=r"(r[3]) : "r"(addr));
}
__device__ __forceinline__ void cp16(uint32_t dst, const void* src)
{
    asm volatile("cp.async.cg.shared.global [%0], [%1], 16;" :: "r"(dst), "l"(src));
}
#define CP_COMMIT asm volatile("cp.async.commit_group;" ::: "memory")
#define CP_WAIT1  asm volatile("cp.async.wait_group 1;" ::: "memory")

__device__ __forceinline__ uint32_t packhalf2(float c0, float c1)
{
    return ((uint32_t)__half_as_ushort(__float2half_rn(c1)) << 16)
         | __half_as_ushort(__float2half_rn(c0));
}
__device__ __forceinline__ float2 unpackhalf2(uint32_t v)
{
    __half2 h = *(__half2*)&v;
    return __half22float2(h);
}

// ===========================================================================
// Scratch buffers (activations in fp16 hi-pair format [b][ch/2][px])
// ===========================================================================
__device__ uint32_t g_w8_hp [(size_t)4*256*128*128];
__device__ uint32_t g_bwt_hp[(size_t)4*256*128*128];
__device__ uint32_t g_x_hp  [(size_t)4*32*256*256];
__device__ uint32_t g_r1_hp [(size_t)4*32*128*128];
__device__ uint32_t g_r2_hp [(size_t)4*256*128*128];
__device__ uint32_t g_wv_hp [(size_t)4*32*256*256];
__device__ float    g_pool  [(size_t)4*2*128*128];
__device__ float    g_sal   [(size_t)4*128*128];
__device__ float    g_m     [4*512];
__device__ float    g_cal   [4*512];
// weight images: exact smem layout, [coT][cc16][tap*512 + co*8 + swz(pos)]
__device__ uint32_t g_wi1[32*9*512];
__device__ uint32_t g_wi2[8*4*9*512];
__device__ uint32_t g_wi3[4*9*512];
__device__ uint32_t g_wif[4*512];
__device__ uint32_t g_wic[(size_t)4*8*32*512];

// ===========================================================================
// Weight prep: f32 [CO][CI][KS2] -> swizzled smem-image u32 (fp16 ci-pairs)
// ===========================================================================
__device__ __forceinline__ void packone(const float* __restrict__ w,
                                        uint32_t* __restrict__ wp,
                                        int CO, int CI, int KS2, int i)
{
    int chunkU = KS2*512;
    int perCoT = (CI/16)*chunkU;
    int coT = i / perCoT;
    int rem = i - coT*perCoT;
    int cc  = rem / chunkU;
    int u   = rem - cc*chunkU;
    int tap = u >> 9;
    int r   = u & 511;
    int co  = r >> 3, pos = r & 7;
    int xb  = (co>>2)&1;
    int cip = ((((pos>>2)^xb)<<2) | (pos&3));
    int ci  = cc*16 + 2*cip;
    int cog = coT*64 + co;
    wp[i] = packhalf2(w[((size_t)cog*CI + ci)*KS2 + tap],
                      w[((size_t)cog*CI + ci+1)*KS2 + tap]);
}
// all 4 static weight tensors in one launch
__global__ void packall_img(const float* __restrict__ w1, const float* __restrict__ w2,
                            const float* __restrict__ w3, const float* __restrict__ wf,
                            uint32_t* __restrict__ o1, uint32_t* __restrict__ o2,
                            uint32_t* __restrict__ o3, uint32_t* __restrict__ of)
{
    int i = blockIdx.x*256 + threadIdx.x;
    if (i < 147456)            packone(w1, o1, 64, 512, 9, i);
    else if (i < 294912)       packone(w2, o2, 512, 64, 9, i - 147456);
    else if (i < 313344)       packone(w3, o3, 64, 64, 9, i - 294912);
    else if (i < 315392)       packone(wf, of, 64, 64, 1, i - 313344);
}
__global__ void packwcal_img(const float* __restrict__ w, const float* __restrict__ cal,
                             uint32_t* __restrict__ wp)
{
    int i = blockIdx.x*256 + threadIdx.x;   // 4*131072
    int b = i >> 17;
    int rem = i & 131071;
    int coT = rem >> 14;
    int rem2 = rem & 16383;
    int cc  = rem2 >> 9;
    int u   = rem2 & 511;
    int co  = u >> 3, pos = u & 7;
    int xb  = (co>>2)&1;
    int cip = ((((pos>>2)^xb)<<2) | (pos&3));
    int ci  = cc*16 + 2*cip;
    int cog = coT*64 + co;
    wp[i] = packhalf2(w[cog*512 + ci]   * cal[b*512 + ci],
                      w[cog*512 + ci+1] * cal[b*512 + ci+1]);
}

// ===========================================================================
// K1: BWT  x -> bwt hi-pair, plus x repacked to hi-pair (for residual)
// ===========================================================================
__global__ void bwt_kernel(const float* __restrict__ x,
                           uint32_t* __restrict__ ohp, uint32_t* __restrict__ xhp)
{
    int idx = blockIdx.x * 256 + threadIdx.x;   // 4*32*128*128
    int j  = idx & 127;
    int i  = (idx >> 7) & 127;
    int cp = (idx >> 14) & 31;
    int b  = idx >> 19;
    const float* xp0 = x + ((size_t)(b*64 + 2*cp)*256 + 2*i)*256 + 2*j;
    const float* xp1 = xp0 + 65536;
    float2 r0 = *(const float2*)xp0, r1 = *(const float2*)(xp0 + 256);
    float2 s0 = *(const float2*)xp1, s1 = *(const float2*)(xp1 + 256);
    size_t xb = ((size_t)(b*32 + cp) << 16) + (size_t)(2*i)*256 + 2*j;
    xhp[xb      ] = packhalf2(r0.x, s0.x);
    xhp[xb + 1  ] = packhalf2(r0.y, s0.y);
    xhp[xb + 256] = packhalf2(r1.x, s1.x);
    xhp[xb + 257] = packhalf2(r1.y, s1.y);
    float a1 = r0.x*0.5f, a3 = r0.y*0.5f, a2 = r1.x*0.5f, a4 = r1.y*0.5f;
    float b1 = s0.x*0.5f, b3 = s0.y*0.5f, b2 = s1.x*0.5f, b4 = s1.y*0.5f;
    int p = (i << 7) + j;
    size_t obP = ((size_t)(b*256 + cp) << 14) + p;
    const size_t gsP = (size_t)32 << 14;
#define BWT_EMIT(k, s1_, s2_, s3_, s4_) \
    ohp[obP + k*gsP] = packhalf2(s1_ a1 s2_ a2 s3_ a3 s4_ a4, \
                                 s1_ b1 s2_ b2 s3_ b3 s4_ b4);
    BWT_EMIT(0, +, +, +, +)
    BWT_EMIT(1, -, -, +, +)
    BWT_EMIT(2, -, +, -, +)
    BWT_EMIT(3, +, -, -, +)
    BWT_EMIT(4, +, +, -, -)
    BWT_EMIT(5, -, +, +, -)
    BWT_EMIT(6, +, -, +, -)
    BWT_EMIT(7, -, -, -, -)
#undef BWT_EMIT
}

// ===========================================================================
// Implicit-GEMM conv, single-term fp16 mma.sync, pipelined, 1 sync/chunk.
// KCH = input channels per chunk; CIN2>0 enables fused second phase:
//   acc = relu(acc) after main loop, then += 1x1 conv of in2_hp (wimg2).
// ===========================================================================
template<int CIN, int COUT, int H, int KS, int KCH,
         bool RELU, bool ADD_OUT, bool ADD_HP, bool SAL, bool WPERB,
         bool OUTF32, bool OUTPK, int CIN2>
__global__ __launch_bounds__(256)
void mmaconv_kernel(const uint32_t* __restrict__ in_hp,
                    const uint32_t* __restrict__ wimg,
                    const float* __restrict__ sal,
                    const uint32_t* __restrict__ addhp,
                    const uint32_t* __restrict__ in2_hp,
                    const uint32_t* __restrict__ wimg2,
                    float* outf, uint32_t* __restrict__ outhp)
{
    constexpr int KS2  = KS*KS;
    constexpr int PAD  = KS/2;
    constexpr int HC   = 16 + KS - 1;
    constexpr int HEL  = HC*HC;
    constexpr int NSUB = KCH/16;
    constexpr int APL  = HEL*32;
    constexpr int ASTG = NSUB*APL;
    constexpr int WCH  = NSUB*KS2*2048;
    constexpr int NC   = CIN/KCH;
    constexpr int ACNT = (KCH/2)*HEL;
    constexpr int NA   = (ACNT + 255)/256;
    constexpr int NG   = NSUB*KS2*128;
    constexpr int HW   = H*H;

    extern __shared__ __align__(16) char smem[];
    const uint32_t smemBase = (uint32_t)__cvta_generic_to_shared(smem);
    const uint32_t wSmem    = smemBase + 2*ASTG;

    const int t    = threadIdx.x;
    const int lane = t & 31, wid = t >> 5;
    const int g    = lane >> 2;
    const int c0   = (lane & 3) * 2;
    const int bx0  = blockIdx.x * 16;
    const int by0  = blockIdx.y * 16;
    const int z    = blockIdx.z;
    const int coT  = z % (COUT/64);
    const int b    = z / (COUT/64);

    const int ltile = lane >> 3, lrow = lane & 7;
    const int lt_lo = ltile & 1;
    const int lt_h  = ltile >> 1;

    uint32_t boff[4];
    #pragma unroll
    for (int nfp = 0; nfp < 4; ++nfp) {
        int cr = nfp*16 + lt_lo*8 + lrow;
        boff[nfp] = (uint32_t)(cr*32 + ((lt_h ^ ((cr>>2)&1)) << 4));
    }

    const size_t bciHW = (size_t)(b*(CIN/2))*HW;
    constexpr int NC16 = CIN/16;
    const uint32_t* wChunk0 = wimg
        + (WPERB ? (size_t)b*(COUT/64)*NC16*KS2*512 : 0)
        + (size_t)coT*NC16*KS2*512;

    float acc[2][8][4];
    #pragma unroll
    for (int mf = 0; mf < 2; ++mf)
        #pragma unroll
        for (int nf = 0; nf < 8; ++nf)
            #pragma unroll
            for (int q = 0; q < 4; ++q) acc[mf][nf][q] = 0.f;

    uint32_t av[NA];

    auto loadA = [&](const uint32_t* src, size_t bbase, int cc) {
        #pragma unroll
        for (int k = 0; k < NA; ++k) {
            int idx = t + k*256;
            uint32_t v = 0u;
            if (ACNT % 256 == 0 || idx < ACNT) {
                int cip = idx / HEL;
                int pix = idx - cip*HEL;
                int py  = pix / HC, px = pix - py*HC;
                int gy  = by0 + py - PAD, gx = bx0 + px - PAD;
                if (gy >= 0 && gy < H && gx >= 0 && gx < H)
                    v = src[bbase + (size_t)(cc*(KCH/2) + cip)*HW + gy*H + gx];
            }
            av[k] = v;
        }
    };
    auto stsA = [&](int s) {
        uint32_t* AH = (uint32_t*)(smem + s*ASTG);
        #pragma unroll
        for (int k = 0; k < NA; ++k) {
            int idx = t + k*256;
            if (ACNT % 256 == 0 || idx < ACNT) {
                int cip = idx / HEL;
                int pix = idx - cip*HEL;
                int sub = cip >> 3, c8 = cip & 7;
                int u = sub*(HEL*8) + pix*8
                      + ((((c8>>2) ^ ((pix>>2)&1)) << 2) | (c8 & 3));
                AH[u] = av[k];
            }
        }
    };
    auto cpW = [&](int cc) {
        const uint32_t* src = wChunk0 + (size_t)cc*NSUB*KS2*512;
        uint32_t dst = wSmem + (cc % 3)*WCH;
        #pragma unroll
        for (int k = t; k < NG; k += 256)
            cp16(dst + k*16, src + k*4);
    };
    auto computeTap = [&](uint32_t aHi, uint32_t wTap, int dy, int dx) {
        uint32_t bh[8][2];
        #pragma unroll
        for (int nfp = 0; nfp < 4; ++nfp) {
            uint32_t tmp[4];
            ldsm_x4(tmp, wTap + boff[nfp]);
            bh[2*nfp][0] = tmp[0]; bh[2*nfp+1][0] = tmp[1];
            bh[2*nfp][1] = tmp[2]; bh[2*nfp+1][1] = tmp[3];
        }
        #pragma unroll
        for (int mf = 0; mf < 2; ++mf) {
            const int pyb = (wid << 1) + mf + dy;
            const int pix = pyb*HC + dx + lt_lo*8 + lrow;
            uint32_t aoff = (uint32_t)(pix*32 + ((lt_h ^ ((pix>>2)&1)) << 4));
            uint32_t ah[4];
            ldsm_x4(ah, aHi + aoff);
            #pragma unroll
            for (int nf = 0; nf < 8; ++nf)
                mma_f16(acc[mf][nf], ah, bh[nf]);
        }
    };
    auto compute = [&](int sa, int sw) {
        #pragma unroll
        for (int s = 0; s < NSUB; ++s) {
            const uint32_t aHi = smemBase + sa*ASTG + s*APL;
            const uint32_t wB  = wSmem + sw*WCH + s*KS2*2048;
            #pragma unroll
            for (int tap = 0; tap < KS2; ++tap)
                computeTap(aHi, wB + (uint32_t)(tap*2048), tap/KS, tap - (tap/KS)*KS);
        }
    };

    // ---- pipelined chunk loop: ONE sync per chunk ----
    loadA(in_hp, bciHW, 0);
    cpW(0); CP_COMMIT;
    cpW(1); CP_COMMIT;
    stsA(0);
    loadA(in_hp, bciHW, 1);
    CP_WAIT1;
    __syncthreads();
    #pragma unroll 1
    for (int cc = 0; cc < NC; ++cc) {
        compute(cc & 1, cc % 3);
        if (cc + 1 < NC) {
            stsA((cc + 1) & 1);
            if (cc + 2 < NC) { loadA(in_hp, bciHW, cc + 2); cpW(cc + 2); }
            CP_COMMIT;
            CP_WAIT1;
            __syncthreads();
        }
    }

    // ---- fused phase 2: relu + 1x1 conv of in2 accumulated on top ----
    if constexpr (CIN2 > 0) {
        #pragma unroll
        for (int mf = 0; mf < 2; ++mf)
            #pragma unroll
            for (int nf = 0; nf < 8; ++nf)
                #pragma unroll
                for (int q = 0; q < 4; ++q)
                    acc[mf][nf][q] = fmaxf(acc[mf][nf][q], 0.f);
        const size_t bci2 = (size_t)(b*(CIN2/2))*HW;
        #pragma unroll 1
        for (int cc = 0; cc < CIN2/16; ++cc) {
            loadA(in2_hp, bci2, cc);
            __syncthreads();            // all warps done with smem stage 0
            stsA(0);
            for (int k = t; k < 512; k += 256)
                ((uint32_t*)(smem + 2*ASTG))[k] = wimg2[cc*512 + k];
            __syncthreads();
            computeTap(smemBase, wSmem, PAD, PAD);   // center tap == 1x1
        }
    }

    // ---- epilogue ----
    #pragma unroll
    for (int mf = 0; mf < 2; ++mf) {
        const int gy  = by0 + (wid << 1) + mf;
        const int gx0 = bx0 + g;
        const int gx8 = gx0 + 8;
        float s0 = 1.f, s8 = 1.f;
        if (SAL) {
            s0 = sal[((size_t)b*H + gy)*H + gx0];
            s8 = sal[((size_t)b*H + gy)*H + gx8];
        }
        #pragma unroll
        for (int nf = 0; nf < 8; ++nf) {
            const int co = coT*64 + nf*8 + c0;
            size_t o0 = ((size_t)(b*COUT + co)*H + gy)*H + gx0;
            size_t o1 = o0 + (size_t)H*H;
            size_t o2 = ((size_t)(b*COUT + co)*H + gy)*H + gx8;
            size_t o3 = o2 + (size_t)H*H;
            float v0 = acc[mf][nf][0]*s0, v1 = acc[mf][nf][1]*s0;
            float v2 = acc[mf][nf][2]*s8, v3 = acc[mf][nf][3]*s8;
            if (RELU && CIN2 == 0) {
                v0 = fmaxf(v0, 0.f); v1 = fmaxf(v1, 0.f);
                v2 = fmaxf(v2, 0.f); v3 = fmaxf(v3, 0.f);
            }
            if (ADD_OUT) { v0 += outf[o0]; v1 += outf[o1]; v2 += outf[o2]; v3 += outf[o3]; }
            size_t pb = ((size_t)(b*(COUT/2) + (co >> 1)))*HW + (size_t)gy*H;
            if (ADD_HP) {
                float2 h0 = unpackhalf2(addhp[pb + gx0]);
                float2 h8 = unpackhalf2(addhp[pb + gx8]);
                v0 += h0.x; v1 += h0.y; v2 += h8.x; v3 += h8.y;
            }
            if (OUTF32) { outf[o0] = v0; outf[o1] = v1; outf[o2] = v2; outf[o3] = v3; }
            if (OUTPK) {
                outhp[pb + gx0] = packhalf2(v0, v1);
                outhp[pb + gx8] = packhalf2(v2, v3);
            }
        }
    }
}

// ===========================================================================
// Attention glue kernels (hp inputs)
// ===========================================================================
__global__ void chanpool_kernel(const uint32_t* __restrict__ r2hp, float* __restrict__ pool)
{
    int p = blockIdx.x * 256 + threadIdx.x;
    int b = blockIdx.y;
    const uint32_t* base = r2hp + (((size_t)b*256) << 14) + p;
    float mx = -3.4e38f, s = 0.f;
    #pragma unroll 8
    for (int c = 0; c < 256; ++c) {
        float2 f = unpackhalf2(base[(size_t)c << 14]);
        mx = fmaxf(mx, fmaxf(f.x, f.y));
        s += f.x + f.y;
    }
    pool[(((size_t)(b*2    )) << 14) + p] = mx;
    pool[(((size_t)(b*2 + 1)) << 14) + p] = s * (1.f/512.f);
}

__global__ void salconv_kernel(const float* __restrict__ pool,
                               const float* __restrict__ wsal,
                               float* __restrict__ sal)
{
    int p = blockIdx.x * 256 + threadIdx.x;
    int b = blockIdx.y;
    int y = p >> 7, x = p & 127;
    float a = 0.f;
    #pragma unroll
    for (int c = 0; c < 2; ++c) {
        const float* pp = pool + (((size_t)(b*2 + c)) << 14);
        #pragma unroll
        for (int ky = 0; ky < 5; ++ky) {
            int iy = y + ky - 2;
            if (iy < 0 || iy >= 128) continue;
            #pragma unroll
            for (int kx = 0; kx < 5; ++kx) {
                int ix = x + kx - 2;
                if (ix < 0 || ix >= 128) continue;
                a += wsal[c*25 + ky*5 + kx] * pp[(iy << 7) + ix];
            }
        }
    }
    sal[(((size_t)b) << 14) + p] = 1.f / (1.f + expf(-a));
}

__global__ void wmean_kernel(const uint32_t* __restrict__ r2hp,
                             const float* __restrict__ sal,
                             float* __restrict__ m)
{
    int cp = blockIdx.x, b = blockIdx.y;
    const uint32_t* r = r2hp + (((size_t)(b*256 + cp)) << 14);
    const float* s = sal + (((size_t)b) << 14);
    float s0 = 0.f, s1 = 0.f;
    for (int i = threadIdx.x; i < 4096; i += 256) {
        uint4 rv = *(const uint4*)(r + i*4);
        float4 sv = *(const float4*)(s + i*4);
        float2 f0 = unpackhalf2(rv.x), f1 = unpackhalf2(rv.y);
        float2 f2 = unpackhalf2(rv.z), f3 = unpackhalf2(rv.w);
        s0 += f0.x*sv.x + f1.x*sv.y + f2.x*sv.z + f3.x*sv.w;
        s1 += f0.y*sv.x + f1.y*sv.y + f2.y*sv.z + f3.y*sv.w;
    }
    #pragma unroll
    for (int o = 16; o > 0; o >>= 1) {
        s0 += __shfl_xor_sync(0xffffffffu, s0, o);
        s1 += __shfl_xor_sync(0xffffffffu, s1, o);
    }
    __shared__ float red[8][2];
    if ((threadIdx.x & 31) == 0) {
        red[threadIdx.x >> 5][0] = s0;
        red[threadIdx.x >> 5][1] = s1;
    }
    __syncthreads();
    if (threadIdx.x == 0) {
        float t0 = 0.f, t1 = 0.f;
        #pragma unroll
        for (int i = 0; i < 8; ++i) { t0 += red[i][0]; t1 += red[i][1]; }
        m[b*512 + 2*cp    ] = t0 * (1.f/16384.f);
        m[b*512 + 2*cp + 1] = t1 * (1.f/16384.f);
    }
}

__global__ void calmlp_kernel(const float* __restrict__ m,
                              const float* __restrict__ wca1,
                              const float* __restrict__ wca2,
                              float* __restrict__ cal)
{
    int b = blockIdx.x;
    __shared__ float sm[512];
    __shared__ float sy1[32];
    for (int i = threadIdx.x; i < 512; i += 256) sm[i] = m[b*512 + i];
    __syncthreads();
    if (threadIdx.x < 32) {
        float a = 0.f;
        for (int c = 0; c < 512; ++c) a += wca1[threadIdx.x*512 + c] * sm[c];
        sy1[threadIdx.x] = fmaxf(a, 0.f);
    }
    __syncthreads();
    for (int c = threadIdx.x; c < 512; c += 256) {
        float a = 0.f;
        #pragma unroll
        for (int j = 0; j < 32; ++j) a += wca2[c*32 + j] * sy1[j];
        cal[b*512 + c] = 1.f / (1.f + expf(-a));
    }
}

// ===========================================================================
// K9: IBWT (hp in from conv8) -> hi-pair packed output
// ===========================================================================
__global__ void ibwt_kernel(const uint32_t* __restrict__ rhp, uint32_t* __restrict__ ohp)
{
    int idx = blockIdx.x * 256 + threadIdx.x;
    int j  = idx & 127;
    int i  = (idx >> 7) & 127;
    int cp = (idx >> 14) & 31;
    int b  = idx >> 19;
    int p  = (i << 7) + j;
    size_t base = ((size_t)(b*256 + cp) << 14) + p;
    const size_t gsP = (size_t)32 << 14;
    float pe[8], qe[8];
    #pragma unroll
    for (int s = 0; s < 8; ++s) {
        float2 f = unpackhalf2(rhp[base + s*gsP]);
        pe[s] = f.x*0.5f; qe[s] = f.y*0.5f;
    }
    float a00p = pe[0]-pe[1]-pe[2]+pe[3]+pe[4]-pe[5]+pe[6]-pe[7];
    float a10p = pe[0]-pe[1]+pe[2]-pe[3]-pe[4]+pe[5]-pe[6]+pe[7];
    float a01p = pe[0]+pe[1]-pe[2]-pe[3]-pe[4]-pe[5]+pe[6]+pe[7];
    float a11p = pe[0]+pe[1]+pe[2]+pe[3]+pe[4]+pe[5]+pe[6]+pe[7];
    float a00q = qe[0]-qe[1]-qe[2]+qe[3]+qe[4]-qe[5]+qe[6]-qe[7];
    float a10q = qe[0]-qe[1]+qe[2]-qe[3]-qe[4]+qe[5]-qe[6]+qe[7];
    float a01q = qe[0]+qe[1]-qe[2]-qe[3]-qe[4]-qe[5]+qe[6]+qe[7];
    float a11q = qe[0]+qe[1]+qe[2]+qe[3]+qe[4]+qe[5]+qe[6]+qe[7];
    size_t off = ((size_t)(b*32 + cp) << 16) + ((size_t)(2*i))*256 + 2*j;
    ohp[off      ] = packhalf2(a00p, a00q);
    ohp[off + 1  ] = packhalf2(a01p, a01q);
    ohp[off + 256] = packhalf2(a10p, a10q);
    ohp[off + 257] = packhalf2(a11p, a11q);
}

// ===========================================================================
// Launch
// ===========================================================================
extern "C" void kernel_launch(void* const* d_in, const int* in_sizes, int n_in,
                              void* d_out, int out_size)
{
    const float* x       = (const float*)d_in[0];
    const float* w_body1 = (const float*)d_in[1];
    const float* w_body2 = (const float*)d_in[2];
    const float* w_sal   = (const float*)d_in[3];
    const float* w_ca1   = (const float*)d_in[4];
    const float* w_ca2   = (const float*)d_in[5];
    const float* w_1x1   = (const float*)d_in[6];
    const float* w_3x3   = (const float*)d_in[7];
    const float* w_final = (const float*)d_in[8];
    float* out = (float*)d_out;

    float *pool, *sal, *m, *cal;
    uint32_t *w8_hp, *bwt_hp, *x_hp, *r1_hp, *r2_hp, *wv_hp;
    uint32_t *wi1, *wi2, *wi3, *wif, *wic;
    cudaGetSymbolAddress((void**)&w8_hp,  g_w8_hp);
    cudaGetSymbolAddress((void**)&bwt_hp, g_bwt_hp);
    cudaGetSymbolAddress((void**)&x_hp,   g_x_hp);
    cudaGetSymbolAddress((void**)&r1_hp,  g_r1_hp);
    cudaGetSymbolAddress((void**)&r2_hp,  g_r2_hp);
    cudaGetSymbolAddress((void**)&wv_hp,  g_wv_hp);
    cudaGetSymbolAddress((void**)&pool,   g_pool);
    cudaGetSymbolAddress((void**)&sal,    g_sal);
    cudaGetSymbolAddress((void**)&m,      g_m);
    cudaGetSymbolAddress((void**)&cal,    g_cal);
    cudaGetSymbolAddress((void**)&wi1,    g_wi1);
    cudaGetSymbolAddress((void**)&wi2,    g_wi2);
    cudaGetSymbolAddress((void**)&wi3,    g_wi3);
    cudaGetSymbolAddress((void**)&wif,    g_wif);
    cudaGetSymbolAddress((void**)&wic,    g_wic);

    constexpr int SM3    = 2*(18*18*32) + 3*(9*2048);      // 76032
    constexpr int SM1K32 = 2*(2*16*16*32) + 3*(2*2048);    // 45056
    cudaFuncSetAttribute(
        (const void*)mmaconv_kernel<512,64,128,3,16, true,false,false,false,false,false,true,0>,
        cudaFuncAttributeMaxDynamicSharedMemorySize, SM3);
    cudaFuncSetAttribute(
        (const void*)mmaconv_kernel<64,512,128,3,16, false,false,false,false,false,false,true,0>,
        cudaFuncAttributeMaxDynamicSharedMemorySize, SM3);
    cudaFuncSetAttribute(
        (const void*)mmaconv_kernel<512,512,128,1,32, false,false,true,true,true,false,true,0>,
        cudaFuncAttributeMaxDynamicSharedMemorySize, SM1K32);
    cudaFuncSetAttribute(
        (const void*)mmaconv_kernel<64,64,256,3,16, true,false,false,false,false,true,false,64>,
        cudaFuncAttributeMaxDynamicSharedMemorySize, SM3);

    // 0) all static weight images in one launch
    packall_img<<<(315392 + 255)/256, 256>>>(w_body1, w_body2, w_3x3, w_final,
                                             wi1, wi2, wi3, wif);

    // 1) BWT (hi-pair) + x repack
    bwt_kernel<<<8192, 256>>>(x, bwt_hp, x_hp);
    // 2) body1 3x3 (512 -> 64) + relu -> r1 hi-pair
    mmaconv_kernel<512,64,128,3,16, true,false,false,false,false,false,true,0>
        <<<dim3(8,8,4), 256, SM3>>>(bwt_hp, wi1, nullptr, nullptr, nullptr, nullptr,
                                    nullptr, r1_hp);
    // 3) body2 3x3 (64 -> 512) -> r2 hi-pair
    mmaconv_kernel<64,512,128,3,16, false,false,false,false,false,false,true,0>
        <<<dim3(8,8,32), 256, SM3>>>(r1_hp, wi2, nullptr, nullptr, nullptr, nullptr,
                                     nullptr, r2_hp);
    // 4) channel pooling (hp)
    chanpool_kernel<<<dim3(64,4), 256>>>(r2_hp, pool);
    // 5) 5x5 conv + sigmoid -> sal
    salconv_kernel<<<dim3(64,4), 256>>>(pool, w_sal, sal);
    // 6) weighted channel means (hp, pairs)
    wmean_kernel<<<dim3(256,4), 256>>>(r2_hp, sal, m);
    // 7) channel attention MLP
    calmlp_kernel<<<4, 256>>>(m, w_ca1, w_ca2, cal);
    // 7b) 1x1 weights with cal folded (per batch), swizzled image
    packwcal_img<<<(4*8*32*512)/256, 256>>>(w_1x1, cal, wic);
    // 8) 1x1 conv (512->512), KCH=32: sal epilogue, += x_bwt hp -> w8 hp
    mmaconv_kernel<512,512,128,1,32, false,false,true,true,true,false,true,0>
        <<<dim3(8,8,32), 256, SM1K32>>>(r2_hp, wic, sal, bwt_hp, nullptr, nullptr,
                                        nullptr, w8_hp);
    // 9) IBWT (hp in) -> hi-pair wave
    ibwt_kernel<<<8192, 256>>>(w8_hp, wv_hp);
    // 10+11 fused) out = relu(conv3x3(wave)) + conv1x1(x)
    mmaconv_kernel<64,64,256,3,16, true,false,false,false,false,true,false,64>
        <<<dim3(16,16,4), 256, SM3>>>(wv_hp, wi3, nullptr, nullptr, x_hp, wif,
                                      out, nullptr);
}

// round 14
// speedup vs baseline: 4.8005x; 1.0678x over previous
#include <cuda_runtime.h>
#include <cuda_fp16.h>
#include <math.h>
#include <stdint.h>

// ===========================================================================
// mma.sync m16n8k16 row.col fp16*fp16 -> f32 + ldmatrix + cp.async helpers
// ===========================================================================
__device__ __forceinline__ void mma_f16(float* c, const uint32_t* a, const uint32_t* b)
{
    asm volatile(
        "mma.sync.aligned.m16n8k16.row.col.f32.f16.f16.f32 "
        "{%0,%1,%2,%3}, {%4,%5,%6,%7}, {%8,%9}, {%0,%1,%2,%3};"
        : "+f"(c[0]), "+f"(c[1]), "+f"(c[2]), "+f"(c[3])
        : "r"(a[0]), "r"(a[1]), "r"(a[2]), "r"(a[3]), "r"(b[0]), "r"(b[1]));
}
__device__ __forceinline__ void ldsm_x4(uint32_t* r, uint32_t addr)
{
    asm volatile(
        "ldmatrix.sync.aligned.m8n8.x4.shared.b16 {%0,%1,%2,%3}, [%4];"
        : "=r"(r[0]), "=r"(r[1]), "=r"(r[2]), "=r"(r[3]) : "r"(addr));
}
__device__ __forceinline__ void cp16(uint32_t dst, const void* src)
{
    asm volatile("cp.async.cg.shared.global [%0], [%1], 16;" :: "r"(dst), "l"(src));
}
#define CP_COMMIT asm volatile("cp.async.commit_group;" ::: "memory")
#define CP_WAIT1  asm volatile("cp.async.wait_group 1;" ::: "memory")

__device__ __forceinline__ uint32_t packhalf2(float c0, float c1)
{
    return ((uint32_t)__half_as_ushort(__float2half_rn(c1)) << 16)
         | __half_as_ushort(__float2half_rn(c0));
}
__device__ __forceinline__ float2 unpackhalf2(uint32_t v)
{
    __half2 h = *(__half2*)&v;
    return __half22float2(h);
}

// ===========================================================================
// Scratch buffers (activations in fp16 hi-pair format [b][ch/2][px])
// ===========================================================================
__device__ uint32_t g_w8_hp [(size_t)4*256*128*128];
__device__ uint32_t g_bwt_hp[(size_t)4*256*128*128];
__device__ uint32_t g_x_hp  [(size_t)4*32*256*256];
__device__ uint32_t g_r1_hp [(size_t)4*32*128*128];
__device__ uint32_t g_r2_hp [(size_t)4*256*128*128];
__device__ uint32_t g_wv_hp [(size_t)4*32*256*256];
__device__ float    g_pool  [(size_t)4*2*128*128];
__device__ float    g_sal   [(size_t)4*128*128];
__device__ float    g_m     [4*512];
__device__ float    g_cal   [4*512];
// weight images: exact smem layout, [coT][cc16][tap*512 + co*8 + swz(pos)]
__device__ uint32_t g_wi1[32*9*512];
__device__ uint32_t g_wi2[8*4*9*512];
__device__ uint32_t g_wi3[4*9*512];
__device__ uint32_t g_wif[4*512];
__device__ uint32_t g_wic[(size_t)4*8*32*512];

// ===========================================================================
// Weight prep: f32 [CO][CI][KS2] -> swizzled smem-image u32 (fp16 ci-pairs)
// ===========================================================================
__device__ __forceinline__ void packone(const float* __restrict__ w,
                                        uint32_t* __restrict__ wp,
                                        int CO, int CI, int KS2, int i)
{
    int chunkU = KS2*512;
    int perCoT = (CI/16)*chunkU;
    int coT = i / perCoT;
    int rem = i - coT*perCoT;
    int cc  = rem / chunkU;
    int u   = rem - cc*chunkU;
    int tap = u >> 9;
    int r   = u & 511;
    int co  = r >> 3, pos = r & 7;
    int xb  = (co>>2)&1;
    int cip = ((((pos>>2)^xb)<<2) | (pos&3));
    int ci  = cc*16 + 2*cip;
    int cog = coT*64 + co;
    wp[i] = packhalf2(w[((size_t)cog*CI + ci)*KS2 + tap],
                      w[((size_t)cog*CI + ci+1)*KS2 + tap]);
}
__global__ void packall_img(const float* __restrict__ w1, const float* __restrict__ w2,
                            const float* __restrict__ w3, const float* __restrict__ wf,
                            uint32_t* __restrict__ o1, uint32_t* __restrict__ o2,
                            uint32_t* __restrict__ o3, uint32_t* __restrict__ of)
{
    int i = blockIdx.x*256 + threadIdx.x;
    if (i < 147456)            packone(w1, o1, 64, 512, 9, i);
    else if (i < 294912)       packone(w2, o2, 512, 64, 9, i - 147456);
    else if (i < 313344)       packone(w3, o3, 64, 64, 9, i - 294912);
    else if (i < 315392)       packone(wf, of, 64, 64, 1, i - 313344);
}
__global__ void packwcal_img(const float* __restrict__ w, const float* __restrict__ cal,
                             uint32_t* __restrict__ wp)
{
    int i = blockIdx.x*256 + threadIdx.x;   // 4*131072
    int b = i >> 17;
    int rem = i & 131071;
    int coT = rem >> 14;
    int rem2 = rem & 16383;
    int cc  = rem2 >> 9;
    int u   = rem2 & 511;
    int co  = u >> 3, pos = u & 7;
    int xb  = (co>>2)&1;
    int cip = ((((pos>>2)^xb)<<2) | (pos&3));
    int ci  = cc*16 + 2*cip;
    int cog = coT*64 + co;
    wp[i] = packhalf2(w[cog*512 + ci]   * cal[b*512 + ci],
                      w[cog*512 + ci+1] * cal[b*512 + ci+1]);
}

// ===========================================================================
// K1: BWT  x -> bwt hi-pair, plus x repacked to hi-pair (for residual)
// ===========================================================================
__global__ void bwt_kernel(const float* __restrict__ x,
                           uint32_t* __restrict__ ohp, uint32_t* __restrict__ xhp)
{
    int idx = blockIdx.x * 256 + threadIdx.x;   // 4*32*128*128
    int j  = idx & 127;
    int i  = (idx >> 7) & 127;
    int cp = (idx >> 14) & 31;
    int b  = idx >> 19;
    const float* xp0 = x + ((size_t)(b*64 + 2*cp)*256 + 2*i)*256 + 2*j;
    const float* xp1 = xp0 + 65536;
    float2 r0 = *(const float2*)xp0, r1 = *(const float2*)(xp0 + 256);
    float2 s0 = *(const float2*)xp1, s1 = *(const float2*)(xp1 + 256);
    size_t xb = ((size_t)(b*32 + cp) << 16) + (size_t)(2*i)*256 + 2*j;
    xhp[xb      ] = packhalf2(r0.x, s0.x);
    xhp[xb + 1  ] = packhalf2(r0.y, s0.y);
    xhp[xb + 256] = packhalf2(r1.x, s1.x);
    xhp[xb + 257] = packhalf2(r1.y, s1.y);
    float a1 = r0.x*0.5f, a3 = r0.y*0.5f, a2 = r1.x*0.5f, a4 = r1.y*0.5f;
    float b1 = s0.x*0.5f, b3 = s0.y*0.5f, b2 = s1.x*0.5f, b4 = s1.y*0.5f;
    int p = (i << 7) + j;
    size_t obP = ((size_t)(b*256 + cp) << 14) + p;
    const size_t gsP = (size_t)32 << 14;
#define BWT_EMIT(k, s1_, s2_, s3_, s4_) \
    ohp[obP + k*gsP] = packhalf2(s1_ a1 s2_ a2 s3_ a3 s4_ a4, \
                                 s1_ b1 s2_ b2 s3_ b3 s4_ b4);
    BWT_EMIT(0, +, +, +, +)
    BWT_EMIT(1, -, -, +, +)
    BWT_EMIT(2, -, +, -, +)
    BWT_EMIT(3, +, -, -, +)
    BWT_EMIT(4, +, +, -, -)
    BWT_EMIT(5, -, +, +, -)
    BWT_EMIT(6, +, -, +, -)
    BWT_EMIT(7, -, -, -, -)
#undef BWT_EMIT
}

// ===========================================================================
// Implicit-GEMM conv, single-term fp16 mma.sync, pipelined, 1 sync/chunk.
// __launch_bounds__(256, 2): cap regs at 128 so 2 CTAs/SM are resident.
// ===========================================================================
template<int CIN, int COUT, int H, int KS, int KCH,
         bool RELU, bool ADD_OUT, bool ADD_HP, bool SAL, bool WPERB,
         bool OUTF32, bool OUTPK, int CIN2>
__global__ __launch_bounds__(256, 2)
void mmaconv_kernel(const uint32_t* __restrict__ in_hp,
                    const uint32_t* __restrict__ wimg,
                    const float* __restrict__ sal,
                    const uint32_t* __restrict__ addhp,
                    const uint32_t* __restrict__ in2_hp,
                    const uint32_t* __restrict__ wimg2,
                    float* outf, uint32_t* __restrict__ outhp)
{
    constexpr int KS2  = KS*KS;
    constexpr int PAD  = KS/2;
    constexpr int HC   = 16 + KS - 1;
    constexpr int HEL  = HC*HC;
    constexpr int NSUB = KCH/16;
    constexpr int APL  = HEL*32;
    constexpr int ASTG = NSUB*APL;
    constexpr int WCH  = NSUB*KS2*2048;
    constexpr int NC   = CIN/KCH;
    constexpr int ACNT = (KCH/2)*HEL;
    constexpr int NA   = (ACNT + 255)/256;
    constexpr int NG   = NSUB*KS2*128;
    constexpr int HW   = H*H;

    extern __shared__ __align__(16) char smem[];
    const uint32_t smemBase = (uint32_t)__cvta_generic_to_shared(smem);
    const uint32_t wSmem    = smemBase + 2*ASTG;

    const int t    = threadIdx.x;
    const int lane = t & 31, wid = t >> 5;
    const int g    = lane >> 2;
    const int c0   = (lane & 3) * 2;
    const int bx0  = blockIdx.x * 16;
    const int by0  = blockIdx.y * 16;
    const int z    = blockIdx.z;
    const int coT  = z % (COUT/64);
    const int b    = z / (COUT/64);

    const int ltile = lane >> 3, lrow = lane & 7;
    const int lt_lo = ltile & 1;
    const int lt_h  = ltile >> 1;

    uint32_t boff[4];
    #pragma unroll
    for (int nfp = 0; nfp < 4; ++nfp) {
        int cr = nfp*16 + lt_lo*8 + lrow;
        boff[nfp] = (uint32_t)(cr*32 + ((lt_h ^ ((cr>>2)&1)) << 4));
    }

    const size_t bciHW = (size_t)(b*(CIN/2))*HW;
    constexpr int NC16 = CIN/16;
    const uint32_t* wChunk0 = wimg
        + (WPERB ? (size_t)b*(COUT/64)*NC16*KS2*512 : 0)
        + (size_t)coT*NC16*KS2*512;

    float acc[2][8][4];
    #pragma unroll
    for (int mf = 0; mf < 2; ++mf)
        #pragma unroll
        for (int nf = 0; nf < 8; ++nf)
            #pragma unroll
            for (int q = 0; q < 4; ++q) acc[mf][nf][q] = 0.f;

    uint32_t av[NA];

    auto loadA = [&](const uint32_t* src, size_t bbase, int cc) {
        #pragma unroll
        for (int k = 0; k < NA; ++k) {
            int idx = t + k*256;
            uint32_t v = 0u;
            if (ACNT % 256 == 0 || idx < ACNT) {
                int cip = idx / HEL;
                int pix = idx - cip*HEL;
                int py  = pix / HC, px = pix - py*HC;
                int gy  = by0 + py - PAD, gx = bx0 + px - PAD;
                if (gy >= 0 && gy < H && gx >= 0 && gx < H)
                    v = src[bbase + (size_t)(cc*(KCH/2) + cip)*HW + gy*H + gx];
            }
            av[k] = v;
        }
    };
    auto stsA = [&](int s) {
        uint32_t* AH = (uint32_t*)(smem + s*ASTG);
        #pragma unroll
        for (int k = 0; k < NA; ++k) {
            int idx = t + k*256;
            if (ACNT % 256 == 0 || idx < ACNT) {
                int cip = idx / HEL;
                int pix = idx - cip*HEL;
                int sub = cip >> 3, c8 = cip & 7;
                int u = sub*(HEL*8) + pix*8
                      + ((((c8>>2) ^ ((pix>>2)&1)) << 2) | (c8 & 3));
                AH[u] = av[k];
            }
        }
    };
    auto cpW = [&](int cc) {
        const uint32_t* src = wChunk0 + (size_t)cc*NSUB*KS2*512;
        uint32_t dst = wSmem + (cc % 3)*WCH;
        #pragma unroll
        for (int k = t; k < NG; k += 256)
            cp16(dst + k*16, src + k*4);
    };
    auto computeTap = [&](uint32_t aHi, uint32_t wTap, int dy, int dx) {
        uint32_t bh[8][2];
        #pragma unroll
        for (int nfp = 0; nfp < 4; ++nfp) {
            uint32_t tmp[4];
            ldsm_x4(tmp, wTap + boff[nfp]);
            bh[2*nfp][0] = tmp[0]; bh[2*nfp+1][0] = tmp[1];
            bh[2*nfp][1] = tmp[2]; bh[2*nfp+1][1] = tmp[3];
        }
        #pragma unroll
        for (int mf = 0; mf < 2; ++mf) {
            const int pyb = (wid << 1) + mf + dy;
            const int pix = pyb*HC + dx + lt_lo*8 + lrow;
            uint32_t aoff = (uint32_t)(pix*32 + ((lt_h ^ ((pix>>2)&1)) << 4));
            uint32_t ah[4];
            ldsm_x4(ah, aHi + aoff);
            #pragma unroll
            for (int nf = 0; nf < 8; ++nf)
                mma_f16(acc[mf][nf], ah, bh[nf]);
        }
    };
    auto compute = [&](int sa, int sw) {
        #pragma unroll
        for (int s = 0; s < NSUB; ++s) {
            const uint32_t aHi = smemBase + sa*ASTG + s*APL;
            const uint32_t wB  = wSmem + sw*WCH + s*KS2*2048;
            #pragma unroll
            for (int tap = 0; tap < KS2; ++tap)
                computeTap(aHi, wB + (uint32_t)(tap*2048), tap/KS, tap - (tap/KS)*KS);
        }
    };

    // ---- pipelined chunk loop: ONE sync per chunk ----
    loadA(in_hp, bciHW, 0);
    cpW(0); CP_COMMIT;
    cpW(1); CP_COMMIT;
    stsA(0);
    loadA(in_hp, bciHW, 1);
    CP_WAIT1;
    __syncthreads();
    #pragma unroll 1
    for (int cc = 0; cc < NC; ++cc) {
        compute(cc & 1, cc % 3);
        if (cc + 1 < NC) {
            stsA((cc + 1) & 1);
            if (cc + 2 < NC) { loadA(in_hp, bciHW, cc + 2); cpW(cc + 2); }
            CP_COMMIT;
            CP_WAIT1;
            __syncthreads();
        }
    }

    // ---- fused phase 2: relu + 1x1 conv of in2 accumulated on top ----
    if constexpr (CIN2 > 0) {
        #pragma unroll
        for (int mf = 0; mf < 2; ++mf)
            #pragma unroll
            for (int nf = 0; nf < 8; ++nf)
                #pragma unroll
                for (int q = 0; q < 4; ++q)
                    acc[mf][nf][q] = fmaxf(acc[mf][nf][q], 0.f);
        const size_t bci2 = (size_t)(b*(CIN2/2))*HW;
        #pragma unroll 1
        for (int cc = 0; cc < CIN2/16; ++cc) {
            loadA(in2_hp, bci2, cc);
            __syncthreads();
            stsA(0);
            for (int k = t; k < 512; k += 256)
                ((uint32_t*)(smem + 2*ASTG))[k] = wimg2[cc*512 + k];
            __syncthreads();
            computeTap(smemBase, wSmem, PAD, PAD);
        }
    }

    // ---- epilogue ----
    #pragma unroll
    for (int mf = 0; mf < 2; ++mf) {
        const int gy  = by0 + (wid << 1) + mf;
        const int gx0 = bx0 + g;
        const int gx8 = gx0 + 8;
        float s0 = 1.f, s8 = 1.f;
        if (SAL) {
            s0 = sal[((size_t)b*H + gy)*H + gx0];
            s8 = sal[((size_t)b*H + gy)*H + gx8];
        }
        #pragma unroll
        for (int nf = 0; nf < 8; ++nf) {
            const int co = coT*64 + nf*8 + c0;
            size_t o0 = ((size_t)(b*COUT + co)*H + gy)*H + gx0;
            size_t o1 = o0 + (size_t)H*H;
            size_t o2 = ((size_t)(b*COUT + co)*H + gy)*H + gx8;
            size_t o3 = o2 + (size_t)H*H;
            float v0 = acc[mf][nf][0]*s0, v1 = acc[mf][nf][1]*s0;
            float v2 = acc[mf][nf][2]*s8, v3 = acc[mf][nf][3]*s8;
            if (RELU && CIN2 == 0) {
                v0 = fmaxf(v0, 0.f); v1 = fmaxf(v1, 0.f);
                v2 = fmaxf(v2, 0.f); v3 = fmaxf(v3, 0.f);
            }
            if (ADD_OUT) { v0 += outf[o0]; v1 += outf[o1]; v2 += outf[o2]; v3 += outf[o3]; }
            size_t pb = ((size_t)(b*(COUT/2) + (co >> 1)))*HW + (size_t)gy*H;
            if (ADD_HP) {
                float2 h0 = unpackhalf2(addhp[pb + gx0]);
                float2 h8 = unpackhalf2(addhp[pb + gx8]);
                v0 += h0.x; v1 += h0.y; v2 += h8.x; v3 += h8.y;
            }
            if (OUTF32) { outf[o0] = v0; outf[o1] = v1; outf[o2] = v2; outf[o3] = v3; }
            if (OUTPK) {
                outhp[pb + gx0] = packhalf2(v0, v1);
                outhp[pb + gx8] = packhalf2(v2, v3);
            }
        }
    }
}

// ===========================================================================
// Attention glue kernels (hp inputs)
// ===========================================================================
__global__ void chanpool_kernel(const uint32_t* __restrict__ r2hp, float* __restrict__ pool)
{
    int p = blockIdx.x * 256 + threadIdx.x;
    int b = blockIdx.y;
    const uint32_t* base = r2hp + (((size_t)b*256) << 14) + p;
    float mx = -3.4e38f, s = 0.f;
    #pragma unroll 8
    for (int c = 0; c < 256; ++c) {
        float2 f = unpackhalf2(base[(size_t)c << 14]);
        mx = fmaxf(mx, fmaxf(f.x, f.y));
        s += f.x + f.y;
    }
    pool[(((size_t)(b*2    )) << 14) + p] = mx;
    pool[(((size_t)(b*2 + 1)) << 14) + p] = s * (1.f/512.f);
}

__global__ void salconv_kernel(const float* __restrict__ pool,
                               const float* __restrict__ wsal,
                               float* __restrict__ sal)
{
    int p = blockIdx.x * 256 + threadIdx.x;
    int b = blockIdx.y;
    int y = p >> 7, x = p & 127;
    float a = 0.f;
    #pragma unroll
    for (int c = 0; c < 2; ++c) {
        const float* pp = pool + (((size_t)(b*2 + c)) << 14);
        #pragma unroll
        for (int ky = 0; ky < 5; ++ky) {
            int iy = y + ky - 2;
            if (iy < 0 || iy >= 128) continue;
            #pragma unroll
            for (int kx = 0; kx < 5; ++kx) {
                int ix = x + kx - 2;
                if (ix < 0 || ix >= 128) continue;
                a += wsal[c*25 + ky*5 + kx] * pp[(iy << 7) + ix];
            }
        }
    }
    sal[(((size_t)b) << 14) + p] = 1.f / (1.f + expf(-a));
}

__global__ void wmean_kernel(const uint32_t* __restrict__ r2hp,
                             const float* __restrict__ sal,
                             float* __restrict__ m)
{
    int cp = blockIdx.x, b = blockIdx.y;
    const uint32_t* r = r2hp + (((size_t)(b*256 + cp)) << 14);
    const float* s = sal + (((size_t)b) << 14);
    float s0 = 0.f, s1 = 0.f;
    for (int i = threadIdx.x; i < 4096; i += 256) {
        uint4 rv = *(const uint4*)(r + i*4);
        float4 sv = *(const float4*)(s + i*4);
        float2 f0 = unpackhalf2(rv.x), f1 = unpackhalf2(rv.y);
        float2 f2 = unpackhalf2(rv.z), f3 = unpackhalf2(rv.w);
        s0 += f0.x*sv.x + f1.x*sv.y + f2.x*sv.z + f3.x*sv.w;
        s1 += f0.y*sv.x + f1.y*sv.y + f2.y*sv.z + f3.y*sv.w;
    }
    #pragma unroll
    for (int o = 16; o > 0; o >>= 1) {
        s0 += __shfl_xor_sync(0xffffffffu, s0, o);
        s1 += __shfl_xor_sync(0xffffffffu, s1, o);
    }
    __shared__ float red[8][2];
    if ((threadIdx.x & 31) == 0) {
        red[threadIdx.x >> 5][0] = s0;
        red[threadIdx.x >> 5][1] = s1;
    }
    __syncthreads();
    if (threadIdx.x == 0) {
        float t0 = 0.f, t1 = 0.f;
        #pragma unroll
        for (int i = 0; i < 8; ++i) { t0 += red[i][0]; t1 += red[i][1]; }
        m[b*512 + 2*cp    ] = t0 * (1.f/16384.f);
        m[b*512 + 2*cp + 1] = t1 * (1.f/16384.f);
    }
}

__global__ void calmlp_kernel(const float* __restrict__ m,
                              const float* __restrict__ wca1,
                              const float* __restrict__ wca2,
                              float* __restrict__ cal)
{
    int b = blockIdx.x;
    __shared__ float sm[512];
    __shared__ float sy1[32];
    for (int i = threadIdx.x; i < 512; i += 256) sm[i] = m[b*512 + i];
    __syncthreads();
    if (threadIdx.x < 32) {
        float a = 0.f;
        for (int c = 0; c < 512; ++c) a += wca1[threadIdx.x*512 + c] * sm[c];
        sy1[threadIdx.x] = fmaxf(a, 0.f);
    }
    __syncthreads();
    for (int c = threadIdx.x; c < 512; c += 256) {
        float a = 0.f;
        #pragma unroll
        for (int j = 0; j < 32; ++j) a += wca2[c*32 + j] * sy1[j];
        cal[b*512 + c] = 1.f / (1.f + expf(-a));
    }
}

// ===========================================================================
// K9: IBWT (hp in from conv8) -> hi-pair packed output
// ===========================================================================
__global__ void ibwt_kernel(const uint32_t* __restrict__ rhp, uint32_t* __restrict__ ohp)
{
    int idx = blockIdx.x * 256 + threadIdx.x;
    int j  = idx & 127;
    int i  = (idx >> 7) & 127;
    int cp = (idx >> 14) & 31;
    int b  = idx >> 19;
    int p  = (i << 7) + j;
    size_t base = ((size_t)(b*256 + cp) << 14) + p;
    const size_t gsP = (size_t)32 << 14;
    float pe[8], qe[8];
    #pragma unroll
    for (int s = 0; s < 8; ++s) {
        float2 f = unpackhalf2(rhp[base + s*gsP]);
        pe[s] = f.x*0.5f; qe[s] = f.y*0.5f;
    }
    float a00p = pe[0]-pe[1]-pe[2]+pe[3]+pe[4]-pe[5]+pe[6]-pe[7];
    float a10p = pe[0]-pe[1]+pe[2]-pe[3]-pe[4]+pe[5]-pe[6]+pe[7];
    float a01p = pe[0]+pe[1]-pe[2]-pe[3]-pe[4]-pe[5]+pe[6]+pe[7];
    float a11p = pe[0]+pe[1]+pe[2]+pe[3]+pe[4]+pe[5]+pe[6]+pe[7];
    float a00q = qe[0]-qe[1]-qe[2]+qe[3]+qe[4]-qe[5]+qe[6]-qe[7];
    float a10q = qe[0]-qe[1]+qe[2]-qe[3]-qe[4]+qe[5]-qe[6]+qe[7];
    float a01q = qe[0]+qe[1]-qe[2]-qe[3]-qe[4]-qe[5]+qe[6]+qe[7];
    float a11q = qe[0]+qe[1]+qe[2]+qe[3]+qe[4]+qe[5]+qe[6]+qe[7];
    size_t off = ((size_t)(b*32 + cp) << 16) + ((size_t)(2*i))*256 + 2*j;
    ohp[off      ] = packhalf2(a00p, a00q);
    ohp[off + 1  ] = packhalf2(a01p, a01q);
    ohp[off + 256] = packhalf2(a10p, a10q);
    ohp[off + 257] = packhalf2(a11p, a11q);
}

// ===========================================================================
// Launch
// ===========================================================================
extern "C" void kernel_launch(void* const* d_in, const int* in_sizes, int n_in,
                              void* d_out, int out_size)
{
    const float* x       = (const float*)d_in[0];
    const float* w_body1 = (const float*)d_in[1];
    const float* w_body2 = (const float*)d_in[2];
    const float* w_sal   = (const float*)d_in[3];
    const float* w_ca1   = (const float*)d_in[4];
    const float* w_ca2   = (const float*)d_in[5];
    const float* w_1x1   = (const float*)d_in[6];
    const float* w_3x3   = (const float*)d_in[7];
    const float* w_final = (const float*)d_in[8];
    float* out = (float*)d_out;

    float *pool, *sal, *m, *cal;
    uint32_t *w8_hp, *bwt_hp, *x_hp, *r1_hp, *r2_hp, *wv_hp;
    uint32_t *wi1, *wi2, *wi3, *wif, *wic;
    cudaGetSymbolAddress((void**)&w8_hp,  g_w8_hp);
    cudaGetSymbolAddress((void**)&bwt_hp, g_bwt_hp);
    cudaGetSymbolAddress((void**)&x_hp,   g_x_hp);
    cudaGetSymbolAddress((void**)&r1_hp,  g_r1_hp);
    cudaGetSymbolAddress((void**)&r2_hp,  g_r2_hp);
    cudaGetSymbolAddress((void**)&wv_hp,  g_wv_hp);
    cudaGetSymbolAddress((void**)&pool,   g_pool);
    cudaGetSymbolAddress((void**)&sal,    g_sal);
    cudaGetSymbolAddress((void**)&m,      g_m);
    cudaGetSymbolAddress((void**)&cal,    g_cal);
    cudaGetSymbolAddress((void**)&wi1,    g_wi1);
    cudaGetSymbolAddress((void**)&wi2,    g_wi2);
    cudaGetSymbolAddress((void**)&wi3,    g_wi3);
    cudaGetSymbolAddress((void**)&wif,    g_wif);
    cudaGetSymbolAddress((void**)&wic,    g_wic);

    constexpr int SM3    = 2*(18*18*32) + 3*(9*2048);      // 76032
    constexpr int SM1K32 = 2*(2*16*16*32) + 3*(2*2048);    // 45056
    cudaFuncSetAttribute(
        (const void*)mmaconv_kernel<512,64,128,3,16, true,false,false,false,false,false,true,0>,
        cudaFuncAttributeMaxDynamicSharedMemorySize, SM3);
    cudaFuncSetAttribute(
        (const void*)mmaconv_kernel<64,512,128,3,16, false,false,false,false,false,false,true,0>,
        cudaFuncAttributeMaxDynamicSharedMemorySize, SM3);
    cudaFuncSetAttribute(
        (const void*)mmaconv_kernel<512,512,128,1,32, false,false,true,true,true,false,true,0>,
        cudaFuncAttributeMaxDynamicSharedMemorySize, SM1K32);
    cudaFuncSetAttribute(
        (const void*)mmaconv_kernel<64,64,256,3,16, true,false,false,false,false,true,false,64>,
        cudaFuncAttributeMaxDynamicSharedMemorySize, SM3);

    // 0) all static weight images in one launch
    packall_img<<<(315392 + 255)/256, 256>>>(w_body1, w_body2, w_3x3, w_final,
                                             wi1, wi2, wi3, wif);

    // 1) BWT (hi-pair) + x repack
    bwt_kernel<<<8192, 256>>>(x, bwt_hp, x_hp);
    // 2) body1 3x3 (512 -> 64) + relu -> r1 hi-pair
    mmaconv_kernel<512,64,128,3,16, true,false,false,false,false,false,true,0>
        <<<dim3(8,8,4), 256, SM3>>>(bwt_hp, wi1, nullptr, nullptr, nullptr, nullptr,
                                    nullptr, r1_hp);
    // 3) body2 3x3 (64 -> 512) -> r2 hi-pair
    mmaconv_kernel<64,512,128,3,16, false,false,false,false,false,false,true,0>
        <<<dim3(8,8,32), 256, SM3>>>(r1_hp, wi2, nullptr, nullptr, nullptr, nullptr,
                                     nullptr, r2_hp);
    // 4) channel pooling (hp)
    chanpool_kernel<<<dim3(64,4), 256>>>(r2_hp, pool);
    // 5) 5x5 conv + sigmoid -> sal
    salconv_kernel<<<dim3(64,4), 256>>>(pool, w_sal, sal);
    // 6) weighted channel means (hp, pairs)
    wmean_kernel<<<dim3(256,4), 256>>>(r2_hp, sal, m);
    // 7) channel attention MLP
    calmlp_kernel<<<4, 256>>>(m, w_ca1, w_ca2, cal);
    // 7b) 1x1 weights with cal folded (per batch), swizzled image
    packwcal_img<<<(4*8*32*512)/256, 256>>>(w_1x1, cal, wic);
    // 8) 1x1 conv (512->512), KCH=32: sal epilogue, += x_bwt hp -> w8 hp
    mmaconv_kernel<512,512,128,1,32, false,false,true,true,true,false,true,0>
        <<<dim3(8,8,32), 256, SM1K32>>>(r2_hp, wic, sal, bwt_hp, nullptr, nullptr,
                                        nullptr, w8_hp);
    // 9) IBWT (hp in) -> hi-pair wave
    ibwt_kernel<<<8192, 256>>>(w8_hp, wv_hp);
    // 10+11 fused) out = relu(conv3x3(wave)) + conv1x1(x)
    mmaconv_kernel<64,64,256,3,16, true,false,false,false,false,true,false,64>
        <<<dim3(16,16,4), 256, SM3>>>(wv_hp, wi3, nullptr, nullptr, x_hp, wif,
                                      out, nullptr);
}